// round 2
// baseline (speedup 1.0000x reference)
#include <cuda_runtime.h>
#include <math.h>

#define BB 4
#define TT 2048
#define DIMD 1024
#define HH 16
#define DHD 64
#define NQKV (3 * DIMD)
#define ATT_SCALE 0.03125f  /* 1024^-0.5 */

// Scratch (device globals; no allocation allowed)
__device__ float g_q[BB * HH * TT * DHD];   // [b,h,t,d]
__device__ float g_k[BB * HH * TT * DHD];
__device__ float g_v[BB * HH * TT * DHD];
__device__ float g_ao[BB * TT * DIMD];      // [b,t,(h d)]

// ---------------------------------------------------------------------------
// GEMM 1: qkv[m, o] = sum_c x[m, c] * w_qkv[o, c]
// M = B*T = 8192, N = 3072, K = 1024. Epilogue scatters to g_q/g_k/g_v.
// Tile 64x64x16, 256 threads, 4x4 per thread.
// ---------------------------------------------------------------------------
__global__ __launch_bounds__(256) void qkv_gemm(const float* __restrict__ x,
                                                const float* __restrict__ w) {
    __shared__ float As[64][16];    // [row][k] natural: conflict-free stores, broadcast reads
    __shared__ float Bs[16][68];    // [k][col] transposed + pad; float4-aligned rows (272B)

    const int tid = threadIdx.x;
    const int tx = tid & 15;
    const int ty = tid >> 4;
    const int m0 = blockIdx.y * 64;
    const int n0 = blockIdx.x * 64;

    float acc[4][4];
#pragma unroll
    for (int i = 0; i < 4; i++)
#pragma unroll
        for (int j = 0; j < 4; j++) acc[i][j] = 0.0f;

    for (int k0 = 0; k0 < DIMD; k0 += 16) {
#pragma unroll
        for (int i = 0; i < 4; i++) {
            int idx = tid + i * 256;
            int r = idx >> 4;
            int c = idx & 15;
            As[r][c] = x[(m0 + r) * DIMD + k0 + c];
            Bs[c][r] = w[(n0 + r) * DIMD + k0 + c];
        }
        __syncthreads();
#pragma unroll
        for (int kk = 0; kk < 16; kk++) {
            float a0 = As[ty * 4 + 0][kk];
            float a1 = As[ty * 4 + 1][kk];
            float a2 = As[ty * 4 + 2][kk];
            float a3 = As[ty * 4 + 3][kk];
            float4 b4 = *(const float4*)&Bs[kk][tx * 4];
            acc[0][0] = fmaf(a0, b4.x, acc[0][0]);
            acc[0][1] = fmaf(a0, b4.y, acc[0][1]);
            acc[0][2] = fmaf(a0, b4.z, acc[0][2]);
            acc[0][3] = fmaf(a0, b4.w, acc[0][3]);
            acc[1][0] = fmaf(a1, b4.x, acc[1][0]);
            acc[1][1] = fmaf(a1, b4.y, acc[1][1]);
            acc[1][2] = fmaf(a1, b4.z, acc[1][2]);
            acc[1][3] = fmaf(a1, b4.w, acc[1][3]);
            acc[2][0] = fmaf(a2, b4.x, acc[2][0]);
            acc[2][1] = fmaf(a2, b4.y, acc[2][1]);
            acc[2][2] = fmaf(a2, b4.z, acc[2][2]);
            acc[2][3] = fmaf(a2, b4.w, acc[2][3]);
            acc[3][0] = fmaf(a3, b4.x, acc[3][0]);
            acc[3][1] = fmaf(a3, b4.y, acc[3][1]);
            acc[3][2] = fmaf(a3, b4.z, acc[3][2]);
            acc[3][3] = fmaf(a3, b4.w, acc[3][3]);
        }
        __syncthreads();
    }

    // Epilogue: o = d*48 + k*16 + h  ->  {q,k,v}[b,h,t,d]
#pragma unroll
    for (int i = 0; i < 4; i++) {
        int m = m0 + ty * 4 + i;
        int b = m >> 11;          // / T
        int t = m & (TT - 1);
#pragma unroll
        for (int j = 0; j < 4; j++) {
            int o = n0 + tx * 4 + j;
            int d = o / 48;
            int rem = o - d * 48;
            int kq = rem >> 4;
            int h = rem & 15;
            float* dst = (kq == 0) ? g_q : (kq == 1) ? g_k : g_v;
            dst[(((b * HH + h) * TT) + t) * DHD + d] = acc[i][j];
        }
    }
}

// ---------------------------------------------------------------------------
// Attention: one thread per query row. 128 rows/CTA, stream 64-key tiles.
// Online softmax with rescale-on-new-max.
// ---------------------------------------------------------------------------
__global__ __launch_bounds__(128) void attn_kernel() {
    __shared__ float4 Ks4[1024];   // 64 keys x 64 d  (16 KB)
    __shared__ float4 Vs4[1024];   // 16 KB

    const int tid = threadIdx.x;
    const int bh = blockIdx.x >> 4;      // [0, 64)
    const int rb = blockIdx.x & 15;
    const int b = bh >> 4;
    const int h = bh & 15;

    const float4* Qg = (const float4*)(g_q + (size_t)bh * TT * DHD);
    const float4* Kg = (const float4*)(g_k + (size_t)bh * TT * DHD);
    const float4* Vg = (const float4*)(g_v + (size_t)bh * TT * DHD);

    const int row = rb * 128 + tid;

    float4 q[16];
#pragma unroll
    for (int i = 0; i < 16; i++) q[i] = Qg[row * 16 + i];

    float4 o[16];
#pragma unroll
    for (int i = 0; i < 16; i++) o[i] = make_float4(0.f, 0.f, 0.f, 0.f);

    float mrow = -INFINITY;
    float lrow = 0.0f;

    for (int kt = 0; kt < TT / 64; kt++) {
        __syncthreads();
#pragma unroll
        for (int i = 0; i < 8; i++) {
            int idx = tid + i * 128;
            Ks4[idx] = Kg[kt * 1024 + idx];
            Vs4[idx] = Vg[kt * 1024 + idx];
        }
        __syncthreads();

        for (int j = 0; j < 64; j++) {
            const float4* kr = Ks4 + j * 16;
            float sx = 0.f, sy = 0.f, sz = 0.f, sw = 0.f;
#pragma unroll
            for (int i = 0; i < 16; i++) {
                float4 kv = kr[i];
                sx = fmaf(q[i].x, kv.x, sx);
                sy = fmaf(q[i].y, kv.y, sy);
                sz = fmaf(q[i].z, kv.z, sz);
                sw = fmaf(q[i].w, kv.w, sw);
            }
            float s = ((sx + sy) + (sz + sw)) * ATT_SCALE;

            if (s > mrow) {
                float corr = __expf(mrow - s);
                lrow *= corr;
#pragma unroll
                for (int i = 0; i < 16; i++) {
                    o[i].x *= corr; o[i].y *= corr;
                    o[i].z *= corr; o[i].w *= corr;
                }
                mrow = s;
            }
            float p = __expf(s - mrow);
            lrow += p;

            const float4* vr = Vs4 + j * 16;
#pragma unroll
            for (int i = 0; i < 16; i++) {
                float4 vv = vr[i];
                o[i].x = fmaf(p, vv.x, o[i].x);
                o[i].y = fmaf(p, vv.y, o[i].y);
                o[i].z = fmaf(p, vv.z, o[i].z);
                o[i].w = fmaf(p, vv.w, o[i].w);
            }
        }
    }

    float inv = 1.0f / lrow;
    float4* dst = (float4*)(g_ao + (size_t)(b * TT + row) * DIMD + h * DHD);
#pragma unroll
    for (int i = 0; i < 16; i++) {
        float4 ov;
        ov.x = o[i].x * inv; ov.y = o[i].y * inv;
        ov.z = o[i].z * inv; ov.w = o[i].w * inv;
        dst[i] = ov;
    }
}

// ---------------------------------------------------------------------------
// GEMM 2: y[m, o] = sum_c ao[m, c] * w_out[o, c] + b_out[o]
// M = 8192, N = 1024, K = 1024.
// ---------------------------------------------------------------------------
__global__ __launch_bounds__(256) void out_gemm(const float* __restrict__ w,
                                                const float* __restrict__ bias,
                                                float* __restrict__ y) {
    __shared__ float As[64][16];
    __shared__ float Bs[16][68];

    const int tid = threadIdx.x;
    const int tx = tid & 15;
    const int ty = tid >> 4;
    const int m0 = blockIdx.y * 64;
    const int n0 = blockIdx.x * 64;

    float acc[4][4];
#pragma unroll
    for (int i = 0; i < 4; i++)
#pragma unroll
        for (int j = 0; j < 4; j++) acc[i][j] = 0.0f;

    for (int k0 = 0; k0 < DIMD; k0 += 16) {
#pragma unroll
        for (int i = 0; i < 4; i++) {
            int idx = tid + i * 256;
            int r = idx >> 4;
            int c = idx & 15;
            As[r][c] = g_ao[(m0 + r) * DIMD + k0 + c];
            Bs[c][r] = w[(n0 + r) * DIMD + k0 + c];
        }
        __syncthreads();
#pragma unroll
        for (int kk = 0; kk < 16; kk++) {
            float a0 = As[ty * 4 + 0][kk];
            float a1 = As[ty * 4 + 1][kk];
            float a2 = As[ty * 4 + 2][kk];
            float a3 = As[ty * 4 + 3][kk];
            float4 b4 = *(const float4*)&Bs[kk][tx * 4];
            acc[0][0] = fmaf(a0, b4.x, acc[0][0]);
            acc[0][1] = fmaf(a0, b4.y, acc[0][1]);
            acc[0][2] = fmaf(a0, b4.z, acc[0][2]);
            acc[0][3] = fmaf(a0, b4.w, acc[0][3]);
            acc[1][0] = fmaf(a1, b4.x, acc[1][0]);
            acc[1][1] = fmaf(a1, b4.y, acc[1][1]);
            acc[1][2] = fmaf(a1, b4.z, acc[1][2]);
            acc[1][3] = fmaf(a1, b4.w, acc[1][3]);
            acc[2][0] = fmaf(a2, b4.x, acc[2][0]);
            acc[2][1] = fmaf(a2, b4.y, acc[2][1]);
            acc[2][2] = fmaf(a2, b4.z, acc[2][2]);
            acc[2][3] = fmaf(a2, b4.w, acc[2][3]);
            acc[3][0] = fmaf(a3, b4.x, acc[3][0]);
            acc[3][1] = fmaf(a3, b4.y, acc[3][1]);
            acc[3][2] = fmaf(a3, b4.z, acc[3][2]);
            acc[3][3] = fmaf(a3, b4.w, acc[3][3]);
        }
        __syncthreads();
    }

#pragma unroll
    for (int i = 0; i < 4; i++) {
        int m = m0 + ty * 4 + i;
#pragma unroll
        for (int j = 0; j < 4; j++) {
            int oc = n0 + tx * 4 + j;
            y[m * DIMD + oc] = acc[i][j] + bias[oc];
        }
    }
}

// ---------------------------------------------------------------------------
extern "C" void kernel_launch(void* const* d_in, const int* in_sizes, int n_in,
                              void* d_out, int out_size) {
    const float* x     = (const float*)d_in[0];
    const float* w_qkv = (const float*)d_in[1];
    const float* w_out = (const float*)d_in[2];
    const float* b_out = (const float*)d_in[3];
    float* y = (float*)d_out;

    dim3 g1(NQKV / 64, (BB * TT) / 64);      // 48 x 128
    qkv_gemm<<<g1, 256>>>(x, w_qkv);

    attn_kernel<<<BB * HH * (TT / 128), 128>>>();   // 1024 blocks

    dim3 g2(DIMD / 64, (BB * TT) / 64);      // 16 x 128
    out_gemm<<<g2, 256>>>(w_out, b_out, y);
}

// round 4
// speedup vs baseline: 1.3881x; 1.3881x over previous
#include <cuda_runtime.h>
#include <cuda_bf16.h>
#include <math.h>
#include <stdint.h>

#define BB 4
#define TT 2048
#define DIMD 1024
#define HH 16
#define DHD 64
#define NQKV 3072
#define ATT_SCALE 0.03125f  /* 1024^-0.5 */
#define KDIM 1024
#define ROWPAD 40   /* 32 bf16 data + 8 pad; 80B row stride -> conflict-free ldmatrix */

// ---------------------------------------------------------------------------
// Device-global scratch (no allocation allowed)
// ---------------------------------------------------------------------------
__device__ float g_q[BB * HH * TT * DHD];   // [b,h,t,d]
__device__ float g_k[BB * HH * TT * DHD];
__device__ float g_v[BB * HH * TT * DHD];
__device__ float g_ao[BB * TT * DIMD];      // [b,t,(h d)]

__device__ __nv_bfloat16 g_xh[BB * TT * DIMD];
__device__ __nv_bfloat16 g_xl[BB * TT * DIMD];
__device__ __nv_bfloat16 g_wqh[NQKV * DIMD];
__device__ __nv_bfloat16 g_wql[NQKV * DIMD];
__device__ __nv_bfloat16 g_woh[DIMD * DIMD];
__device__ __nv_bfloat16 g_wol[DIMD * DIMD];
__device__ __nv_bfloat16 g_aoh[BB * TT * DIMD];
__device__ __nv_bfloat16 g_aol[BB * TT * DIMD];

// ---------------------------------------------------------------------------
// Standard-PTX tensor-core helpers (valid at compute_103 non-'a' target)
// ---------------------------------------------------------------------------
__device__ __forceinline__ uint32_t smem_u32(const void* p) {
    uint32_t a;
    asm("{ .reg .u64 t; cvta.to.shared.u64 t, %1; cvt.u32.u64 %0, t; }" : "=r"(a) : "l"(p));
    return a;
}

__device__ __forceinline__ void ldm_x4(uint32_t* r, uint32_t addr) {
    asm volatile("ldmatrix.sync.aligned.m8n8.x4.shared.b16 {%0,%1,%2,%3}, [%4];"
                 : "=r"(r[0]), "=r"(r[1]), "=r"(r[2]), "=r"(r[3]) : "r"(addr));
}

__device__ __forceinline__ void ldm_x2(uint32_t* r, uint32_t addr) {
    asm volatile("ldmatrix.sync.aligned.m8n8.x2.shared.b16 {%0,%1}, [%2];"
                 : "=r"(r[0]), "=r"(r[1]) : "r"(addr));
}

__device__ __forceinline__ void mma16816(float* d, const uint32_t* a, const uint32_t* b) {
    asm volatile(
        "mma.sync.aligned.m16n8k16.row.col.f32.bf16.bf16.f32 "
        "{%0,%1,%2,%3}, {%4,%5,%6,%7}, {%8,%9}, {%0,%1,%2,%3};"
        : "+f"(d[0]), "+f"(d[1]), "+f"(d[2]), "+f"(d[3])
        : "r"(a[0]), "r"(a[1]), "r"(a[2]), "r"(a[3]), "r"(b[0]), "r"(b[1]));
}

// ---------------------------------------------------------------------------
// fp32 -> (bf16 hi, bf16 lo) split pre-pass
// ---------------------------------------------------------------------------
__global__ __launch_bounds__(256) void split_kernel(const float* __restrict__ s,
                                                    __nv_bfloat16* __restrict__ h,
                                                    __nv_bfloat16* __restrict__ l,
                                                    int n4) {
    int i = blockIdx.x * blockDim.x + threadIdx.x;
    if (i >= n4) return;
    float4 v = ((const float4*)s)[i];
    __nv_bfloat16 h0 = __float2bfloat16(v.x);
    __nv_bfloat16 h1 = __float2bfloat16(v.y);
    __nv_bfloat16 h2 = __float2bfloat16(v.z);
    __nv_bfloat16 h3 = __float2bfloat16(v.w);
    __nv_bfloat16 l0 = __float2bfloat16(v.x - __bfloat162float(h0));
    __nv_bfloat16 l1 = __float2bfloat16(v.y - __bfloat162float(h1));
    __nv_bfloat16 l2 = __float2bfloat16(v.z - __bfloat162float(h2));
    __nv_bfloat16 l3 = __float2bfloat16(v.w - __bfloat162float(h3));
    uint2 hp, lp;
    hp.x = ((uint32_t)__bfloat16_as_ushort(h1) << 16) | __bfloat16_as_ushort(h0);
    hp.y = ((uint32_t)__bfloat16_as_ushort(h3) << 16) | __bfloat16_as_ushort(h2);
    lp.x = ((uint32_t)__bfloat16_as_ushort(l1) << 16) | __bfloat16_as_ushort(l0);
    lp.y = ((uint32_t)__bfloat16_as_ushort(l3) << 16) | __bfloat16_as_ushort(l2);
    ((uint2*)h)[i] = hp;
    ((uint2*)l)[i] = lp;
}

// ---------------------------------------------------------------------------
// HMMA bf16x3 GEMM: D[128x128] tile = A[128xK] * B[128xK]^T, fp32 accum.
// 256 threads = 8 warps (2 M x 4 N), warp tile 64x32, K-chunks of 32.
// EPI 0: scatter into g_q/g_k/g_v.  EPI 1: +bias -> out.
// ---------------------------------------------------------------------------
__device__ __forceinline__ void load_chunk(__nv_bfloat16 (*S)[ROWPAD],
                                           const __nv_bfloat16* src, int tid) {
#pragma unroll
    for (int i = 0; i < 2; i++) {
        int idx = tid + i * 256;       // 0..511 : 128 rows x 4 16B-segments
        int row = idx >> 2;
        int seg = idx & 3;
        *(uint4*)&S[row][seg * 8] = *(const uint4*)(src + (size_t)row * KDIM + seg * 8);
    }
}

template <int EPI>
__global__ __launch_bounds__(256, 2) void mma_gemm(const __nv_bfloat16* __restrict__ Ahp,
                                                   const __nv_bfloat16* __restrict__ Alp,
                                                   const __nv_bfloat16* __restrict__ Bhp,
                                                   const __nv_bfloat16* __restrict__ Blp,
                                                   const float* __restrict__ bias,
                                                   float* __restrict__ out) {
    __shared__ __nv_bfloat16 Ah[128][ROWPAD];
    __shared__ __nv_bfloat16 Al[128][ROWPAD];
    __shared__ __nv_bfloat16 Bh[128][ROWPAD];
    __shared__ __nv_bfloat16 Bl[128][ROWPAD];

    const int tid = threadIdx.x;
    const int wid = tid >> 5;
    const int lane = tid & 31;
    const int warp_m = wid & 1;        // 2 warps over M
    const int warp_n = wid >> 1;       // 4 warps over N
    const int m0 = blockIdx.y * 128;
    const int n0 = blockIdx.x * 128;

    const uint32_t aAh = smem_u32(Ah);
    const uint32_t aAl = smem_u32(Al);
    const uint32_t aBh = smem_u32(Bh);
    const uint32_t aBl = smem_u32(Bl);

    // ldmatrix lane->address components
    const int a_row_base = warp_m * 64 + (lane & 15);   // + mi*16
    const int a_colsel = (lane >> 4) * 8;               // + kk*16
    const int b_row_base = warp_n * 32 + (lane & 7);    // + ni*8
    const int b_colsel = ((lane >> 3) & 1) * 8;         // + kk*16

    float acc[4][4][4];
#pragma unroll
    for (int mi = 0; mi < 4; mi++)
#pragma unroll
        for (int ni = 0; ni < 4; ni++)
#pragma unroll
            for (int e = 0; e < 4; e++) acc[mi][ni][e] = 0.0f;

    const __nv_bfloat16* srcAh = Ahp + (size_t)m0 * KDIM;
    const __nv_bfloat16* srcAl = Alp + (size_t)m0 * KDIM;
    const __nv_bfloat16* srcBh = Bhp + (size_t)n0 * KDIM;
    const __nv_bfloat16* srcBl = Blp + (size_t)n0 * KDIM;

    for (int k0 = 0; k0 < KDIM; k0 += 32) {
        __syncthreads();
        load_chunk(Ah, srcAh + k0, tid);
        load_chunk(Al, srcAl + k0, tid);
        load_chunk(Bh, srcBh + k0, tid);
        load_chunk(Bl, srcBl + k0, tid);
        __syncthreads();

#pragma unroll
        for (int kk = 0; kk < 2; kk++) {
            const int acol = kk * 16 + a_colsel;
            const int bcol = kk * 16 + b_colsel;

            uint32_t fa[4][4];
            uint32_t fb[4][2];

            // pass 1: Ah * Bh
#pragma unroll
            for (int mi = 0; mi < 4; mi++)
                ldm_x4(fa[mi], aAh + ((a_row_base + mi * 16) * ROWPAD + acol) * 2);
#pragma unroll
            for (int ni = 0; ni < 4; ni++)
                ldm_x2(fb[ni], aBh + ((b_row_base + ni * 8) * ROWPAD + bcol) * 2);
#pragma unroll
            for (int mi = 0; mi < 4; mi++)
#pragma unroll
                for (int ni = 0; ni < 4; ni++)
                    mma16816(acc[mi][ni], fa[mi], fb[ni]);

            // pass 2: Ah * Bl (reuse fa)
            uint32_t fbl[4][2];
#pragma unroll
            for (int ni = 0; ni < 4; ni++)
                ldm_x2(fbl[ni], aBl + ((b_row_base + ni * 8) * ROWPAD + bcol) * 2);
#pragma unroll
            for (int mi = 0; mi < 4; mi++)
#pragma unroll
                for (int ni = 0; ni < 4; ni++)
                    mma16816(acc[mi][ni], fa[mi], fbl[ni]);

            // pass 3: Al * Bh (reuse fb)
#pragma unroll
            for (int mi = 0; mi < 4; mi++)
                ldm_x4(fa[mi], aAl + ((a_row_base + mi * 16) * ROWPAD + acol) * 2);
#pragma unroll
            for (int mi = 0; mi < 4; mi++)
#pragma unroll
                for (int ni = 0; ni < 4; ni++)
                    mma16816(acc[mi][ni], fa[mi], fb[ni]);
        }
    }

    // Epilogue. Thread owns rows (lane>>2, +8), cols ((lane&3)*2, +1) per tile.
    const int r0 = lane >> 2;
    const int c0 = (lane & 3) * 2;
#pragma unroll
    for (int mi = 0; mi < 4; mi++) {
#pragma unroll
        for (int half = 0; half < 2; half++) {
            const int m = m0 + warp_m * 64 + mi * 16 + r0 + half * 8;
            if (EPI == 0) {
                const int b = m >> 11;
                const int t = m & (TT - 1);
                const size_t mbase = ((size_t)b * HH) * TT;
#pragma unroll
                for (int ni = 0; ni < 4; ni++) {
#pragma unroll
                    for (int e = 0; e < 2; e++) {
                        int o = n0 + warp_n * 32 + ni * 8 + c0 + e;
                        float v = acc[mi][ni][half * 2 + e];
                        int d = o / 48;
                        int rem = o - d * 48;
                        int kq = rem >> 4;
                        int h = rem & 15;
                        float* dst = (kq == 0) ? g_q : (kq == 1) ? g_k : g_v;
                        dst[((mbase + (size_t)h * TT) + t) * DHD + d] = v;
                    }
                }
            } else {
#pragma unroll
                for (int ni = 0; ni < 4; ni++) {
#pragma unroll
                    for (int e = 0; e < 2; e++) {
                        int o = n0 + warp_n * 32 + ni * 8 + c0 + e;
                        out[(size_t)m * DIMD + o] = acc[mi][ni][half * 2 + e] + bias[o];
                    }
                }
            }
        }
    }
}

// ---------------------------------------------------------------------------
// Attention: unchanged (known-correct FFMA flash attention)
// ---------------------------------------------------------------------------
__global__ __launch_bounds__(128) void attn_kernel() {
    __shared__ float4 Ks4[1024];
    __shared__ float4 Vs4[1024];

    const int tid = threadIdx.x;
    const int bh = blockIdx.x >> 4;
    const int rb = blockIdx.x & 15;
    const int b = bh >> 4;
    const int h = bh & 15;

    const float4* Qg = (const float4*)(g_q + (size_t)bh * TT * DHD);
    const float4* Kg = (const float4*)(g_k + (size_t)bh * TT * DHD);
    const float4* Vg = (const float4*)(g_v + (size_t)bh * TT * DHD);

    const int row = rb * 128 + tid;

    float4 q[16];
#pragma unroll
    for (int i = 0; i < 16; i++) q[i] = Qg[row * 16 + i];

    float4 o[16];
#pragma unroll
    for (int i = 0; i < 16; i++) o[i] = make_float4(0.f, 0.f, 0.f, 0.f);

    float mrow = -INFINITY;
    float lrow = 0.0f;

    for (int kt = 0; kt < TT / 64; kt++) {
        __syncthreads();
#pragma unroll
        for (int i = 0; i < 8; i++) {
            int idx = tid + i * 128;
            Ks4[idx] = Kg[kt * 1024 + idx];
            Vs4[idx] = Vg[kt * 1024 + idx];
        }
        __syncthreads();

        for (int j = 0; j < 64; j++) {
            const float4* kr = Ks4 + j * 16;
            float sx = 0.f, sy = 0.f, sz = 0.f, sw = 0.f;
#pragma unroll
            for (int i = 0; i < 16; i++) {
                float4 kv = kr[i];
                sx = fmaf(q[i].x, kv.x, sx);
                sy = fmaf(q[i].y, kv.y, sy);
                sz = fmaf(q[i].z, kv.z, sz);
                sw = fmaf(q[i].w, kv.w, sw);
            }
            float s = ((sx + sy) + (sz + sw)) * ATT_SCALE;

            if (s > mrow) {
                float corr = __expf(mrow - s);
                lrow *= corr;
#pragma unroll
                for (int i = 0; i < 16; i++) {
                    o[i].x *= corr; o[i].y *= corr;
                    o[i].z *= corr; o[i].w *= corr;
                }
                mrow = s;
            }
            float p = __expf(s - mrow);
            lrow += p;

            const float4* vr = Vs4 + j * 16;
#pragma unroll
            for (int i = 0; i < 16; i++) {
                float4 vv = vr[i];
                o[i].x = fmaf(p, vv.x, o[i].x);
                o[i].y = fmaf(p, vv.y, o[i].y);
                o[i].z = fmaf(p, vv.z, o[i].z);
                o[i].w = fmaf(p, vv.w, o[i].w);
            }
        }
    }

    float inv = 1.0f / lrow;
    float4* dst = (float4*)(g_ao + (size_t)(b * TT + row) * DIMD + h * DHD);
#pragma unroll
    for (int i = 0; i < 16; i++) {
        float4 ov;
        ov.x = o[i].x * inv; ov.y = o[i].y * inv;
        ov.z = o[i].z * inv; ov.w = o[i].w * inv;
        dst[i] = ov;
    }
}

// ---------------------------------------------------------------------------
extern "C" void kernel_launch(void* const* d_in, const int* in_sizes, int n_in,
                              void* d_out, int out_size) {
    const float* x     = (const float*)d_in[0];
    const float* w_qkv = (const float*)d_in[1];
    const float* w_out = (const float*)d_in[2];
    const float* b_out = (const float*)d_in[3];
    float* y = (float*)d_out;

    void *p_xh, *p_xl, *p_wqh, *p_wql, *p_woh, *p_wol, *p_aoh, *p_aol, *p_ao;
    cudaGetSymbolAddress(&p_xh, g_xh);
    cudaGetSymbolAddress(&p_xl, g_xl);
    cudaGetSymbolAddress(&p_wqh, g_wqh);
    cudaGetSymbolAddress(&p_wql, g_wql);
    cudaGetSymbolAddress(&p_woh, g_woh);
    cudaGetSymbolAddress(&p_wol, g_wol);
    cudaGetSymbolAddress(&p_aoh, g_aoh);
    cudaGetSymbolAddress(&p_aol, g_aol);
    cudaGetSymbolAddress(&p_ao, g_ao);

    // Split pre-passes (fp32 -> bf16 hi/lo)
    {
        int n4 = (BB * TT * DIMD) / 4;
        split_kernel<<<(n4 + 255) / 256, 256>>>(x, (__nv_bfloat16*)p_xh, (__nv_bfloat16*)p_xl, n4);
    }
    {
        int n4 = (NQKV * DIMD) / 4;
        split_kernel<<<(n4 + 255) / 256, 256>>>(w_qkv, (__nv_bfloat16*)p_wqh, (__nv_bfloat16*)p_wql, n4);
    }
    {
        int n4 = (DIMD * DIMD) / 4;
        split_kernel<<<(n4 + 255) / 256, 256>>>(w_out, (__nv_bfloat16*)p_woh, (__nv_bfloat16*)p_wol, n4);
    }

    // QKV projection: M=8192, N=3072
    {
        dim3 g(NQKV / 128, (BB * TT) / 128);   // 24 x 64
        mma_gemm<0><<<g, 256>>>((__nv_bfloat16*)p_xh, (__nv_bfloat16*)p_xl,
                                (__nv_bfloat16*)p_wqh, (__nv_bfloat16*)p_wql,
                                nullptr, nullptr);
    }

    attn_kernel<<<BB * HH * (TT / 128), 128>>>();

    {
        int n4 = (BB * TT * DIMD) / 4;
        split_kernel<<<(n4 + 255) / 256, 256>>>((const float*)p_ao,
                                                (__nv_bfloat16*)p_aoh, (__nv_bfloat16*)p_aol, n4);
    }

    // Output projection: M=8192, N=1024 (+bias)
    {
        dim3 g(DIMD / 128, (BB * TT) / 128);   // 8 x 64
        mma_gemm<1><<<g, 256>>>((__nv_bfloat16*)p_aoh, (__nv_bfloat16*)p_aol,
                                (__nv_bfloat16*)p_woh, (__nv_bfloat16*)p_wol,
                                b_out, y);
    }
}

// round 5
// speedup vs baseline: 1.9901x; 1.4337x over previous
#include <cuda_runtime.h>
#include <cuda_bf16.h>
#include <math.h>
#include <stdint.h>

#define BB 4
#define TT 2048
#define DIMD 1024
#define HH 16
#define DHD 64
#define NQKV 3072
#define KDIM 1024
#define ROWPAD 40   /* gemm smem pad */
#define APAD 72     /* attention smem row pad (bf16 elems): 144B rows, conflict-free ldmatrix */
#define EXP_C 0.045084439f  /* (1/32) * log2(e) */

// ---------------------------------------------------------------------------
// Device-global scratch (no allocation allowed)
// ---------------------------------------------------------------------------
__device__ float g_q[BB * HH * TT * DHD];   // [b,h,t,d]
__device__ float g_k[BB * HH * TT * DHD];
__device__ float g_v[BB * HH * TT * DHD];
__device__ float g_ao[BB * TT * DIMD];      // [b,t,(h d)]

__device__ __nv_bfloat16 g_xh[BB * TT * DIMD];
__device__ __nv_bfloat16 g_xl[BB * TT * DIMD];
__device__ __nv_bfloat16 g_wqh[NQKV * DIMD];
__device__ __nv_bfloat16 g_wql[NQKV * DIMD];
__device__ __nv_bfloat16 g_woh[DIMD * DIMD];
__device__ __nv_bfloat16 g_wol[DIMD * DIMD];
__device__ __nv_bfloat16 g_aoh[BB * TT * DIMD];
__device__ __nv_bfloat16 g_aol[BB * TT * DIMD];

// ---------------------------------------------------------------------------
// Standard-PTX tensor-core helpers (valid at compute_103 non-'a' target)
// ---------------------------------------------------------------------------
__device__ __forceinline__ uint32_t smem_u32(const void* p) {
    uint32_t a;
    asm("{ .reg .u64 t; cvta.to.shared.u64 t, %1; cvt.u32.u64 %0, t; }" : "=r"(a) : "l"(p));
    return a;
}

__device__ __forceinline__ void ldm_x4(uint32_t* r, uint32_t addr) {
    asm volatile("ldmatrix.sync.aligned.m8n8.x4.shared.b16 {%0,%1,%2,%3}, [%4];"
                 : "=r"(r[0]), "=r"(r[1]), "=r"(r[2]), "=r"(r[3]) : "r"(addr));
}

__device__ __forceinline__ void ldm_x2(uint32_t* r, uint32_t addr) {
    asm volatile("ldmatrix.sync.aligned.m8n8.x2.shared.b16 {%0,%1}, [%2];"
                 : "=r"(r[0]), "=r"(r[1]) : "r"(addr));
}

__device__ __forceinline__ void ldm_x2_trans(uint32_t* r, uint32_t addr) {
    asm volatile("ldmatrix.sync.aligned.m8n8.x2.trans.shared.b16 {%0,%1}, [%2];"
                 : "=r"(r[0]), "=r"(r[1]) : "r"(addr));
}

__device__ __forceinline__ void mma16816(float* d, const uint32_t* a, const uint32_t* b) {
    asm volatile(
        "mma.sync.aligned.m16n8k16.row.col.f32.bf16.bf16.f32 "
        "{%0,%1,%2,%3}, {%4,%5,%6,%7}, {%8,%9}, {%0,%1,%2,%3};"
        : "+f"(d[0]), "+f"(d[1]), "+f"(d[2]), "+f"(d[3])
        : "r"(a[0]), "r"(a[1]), "r"(a[2]), "r"(a[3]), "r"(b[0]), "r"(b[1]));
}

__device__ __forceinline__ uint32_t pack_bf16x2(float lo, float hi) {
    uint32_t r;
    asm("cvt.rn.satfinite.bf16x2.f32 %0, %1, %2;" : "=r"(r) : "f"(hi), "f"(lo));
    return r;
}

__device__ __forceinline__ float fexp2(float x) {
    float r;
    asm("ex2.approx.ftz.f32 %0, %1;" : "=f"(r) : "f"(x));
    return r;
}

// Split a float4 into bf16 hi / lo pairs, store 8B each.
__device__ __forceinline__ void split_store(__nv_bfloat16* ph, __nv_bfloat16* pl, float4 v) {
    uint32_t h0 = pack_bf16x2(v.x, v.y);
    uint32_t h1 = pack_bf16x2(v.z, v.w);
    float fx = __uint_as_float(h0 << 16);
    float fy = __uint_as_float(h0 & 0xffff0000u);
    float fz = __uint_as_float(h1 << 16);
    float fw = __uint_as_float(h1 & 0xffff0000u);
    uint32_t l0 = pack_bf16x2(v.x - fx, v.y - fy);
    uint32_t l1 = pack_bf16x2(v.z - fz, v.w - fw);
    ((uint32_t*)ph)[0] = h0; ((uint32_t*)ph)[1] = h1;
    ((uint32_t*)pl)[0] = l0; ((uint32_t*)pl)[1] = l1;
}

// ---------------------------------------------------------------------------
// fp32 -> (bf16 hi, bf16 lo) split pre-pass
// ---------------------------------------------------------------------------
__global__ __launch_bounds__(256) void split_kernel(const float* __restrict__ s,
                                                    __nv_bfloat16* __restrict__ h,
                                                    __nv_bfloat16* __restrict__ l,
                                                    int n4) {
    int i = blockIdx.x * blockDim.x + threadIdx.x;
    if (i >= n4) return;
    float4 v = ((const float4*)s)[i];
    uint2 hp, lp;
    hp.x = pack_bf16x2(v.x, v.y);
    hp.y = pack_bf16x2(v.z, v.w);
    lp.x = pack_bf16x2(v.x - __uint_as_float(hp.x << 16),
                       v.y - __uint_as_float(hp.x & 0xffff0000u));
    lp.y = pack_bf16x2(v.z - __uint_as_float(hp.y << 16),
                       v.w - __uint_as_float(hp.y & 0xffff0000u));
    ((uint2*)h)[i] = hp;
    ((uint2*)l)[i] = lp;
}

// ---------------------------------------------------------------------------
// HMMA bf16x3 GEMM (unchanged from R3 — validated)
// ---------------------------------------------------------------------------
__device__ __forceinline__ void load_chunk(__nv_bfloat16 (*S)[ROWPAD],
                                           const __nv_bfloat16* src, int tid) {
#pragma unroll
    for (int i = 0; i < 2; i++) {
        int idx = tid + i * 256;
        int row = idx >> 2;
        int seg = idx & 3;
        *(uint4*)&S[row][seg * 8] = *(const uint4*)(src + (size_t)row * KDIM + seg * 8);
    }
}

template <int EPI>
__global__ __launch_bounds__(256, 2) void mma_gemm(const __nv_bfloat16* __restrict__ Ahp,
                                                   const __nv_bfloat16* __restrict__ Alp,
                                                   const __nv_bfloat16* __restrict__ Bhp,
                                                   const __nv_bfloat16* __restrict__ Blp,
                                                   const float* __restrict__ bias,
                                                   float* __restrict__ out) {
    __shared__ __nv_bfloat16 Ah[128][ROWPAD];
    __shared__ __nv_bfloat16 Al[128][ROWPAD];
    __shared__ __nv_bfloat16 Bh[128][ROWPAD];
    __shared__ __nv_bfloat16 Bl[128][ROWPAD];

    const int tid = threadIdx.x;
    const int wid = tid >> 5;
    const int lane = tid & 31;
    const int warp_m = wid & 1;
    const int warp_n = wid >> 1;
    const int m0 = blockIdx.y * 128;
    const int n0 = blockIdx.x * 128;

    const uint32_t aAh = smem_u32(Ah);
    const uint32_t aAl = smem_u32(Al);
    const uint32_t aBh = smem_u32(Bh);
    const uint32_t aBl = smem_u32(Bl);

    const int a_row_base = warp_m * 64 + (lane & 15);
    const int a_colsel = (lane >> 4) * 8;
    const int b_row_base = warp_n * 32 + (lane & 7);
    const int b_colsel = ((lane >> 3) & 1) * 8;

    float acc[4][4][4];
#pragma unroll
    for (int mi = 0; mi < 4; mi++)
#pragma unroll
        for (int ni = 0; ni < 4; ni++)
#pragma unroll
            for (int e = 0; e < 4; e++) acc[mi][ni][e] = 0.0f;

    const __nv_bfloat16* srcAh = Ahp + (size_t)m0 * KDIM;
    const __nv_bfloat16* srcAl = Alp + (size_t)m0 * KDIM;
    const __nv_bfloat16* srcBh = Bhp + (size_t)n0 * KDIM;
    const __nv_bfloat16* srcBl = Blp + (size_t)n0 * KDIM;

    for (int k0 = 0; k0 < KDIM; k0 += 32) {
        __syncthreads();
        load_chunk(Ah, srcAh + k0, tid);
        load_chunk(Al, srcAl + k0, tid);
        load_chunk(Bh, srcBh + k0, tid);
        load_chunk(Bl, srcBl + k0, tid);
        __syncthreads();

#pragma unroll
        for (int kk = 0; kk < 2; kk++) {
            const int acol = kk * 16 + a_colsel;
            const int bcol = kk * 16 + b_colsel;

            uint32_t fa[4][4];
            uint32_t fb[4][2];

#pragma unroll
            for (int mi = 0; mi < 4; mi++)
                ldm_x4(fa[mi], aAh + ((a_row_base + mi * 16) * ROWPAD + acol) * 2);
#pragma unroll
            for (int ni = 0; ni < 4; ni++)
                ldm_x2(fb[ni], aBh + ((b_row_base + ni * 8) * ROWPAD + bcol) * 2);
#pragma unroll
            for (int mi = 0; mi < 4; mi++)
#pragma unroll
                for (int ni = 0; ni < 4; ni++)
                    mma16816(acc[mi][ni], fa[mi], fb[ni]);

            uint32_t fbl[4][2];
#pragma unroll
            for (int ni = 0; ni < 4; ni++)
                ldm_x2(fbl[ni], aBl + ((b_row_base + ni * 8) * ROWPAD + bcol) * 2);
#pragma unroll
            for (int mi = 0; mi < 4; mi++)
#pragma unroll
                for (int ni = 0; ni < 4; ni++)
                    mma16816(acc[mi][ni], fa[mi], fbl[ni]);

#pragma unroll
            for (int mi = 0; mi < 4; mi++)
                ldm_x4(fa[mi], aAl + ((a_row_base + mi * 16) * ROWPAD + acol) * 2);
#pragma unroll
            for (int mi = 0; mi < 4; mi++)
#pragma unroll
                for (int ni = 0; ni < 4; ni++)
                    mma16816(acc[mi][ni], fa[mi], fb[ni]);
        }
    }

    const int r0 = lane >> 2;
    const int c0 = (lane & 3) * 2;
#pragma unroll
    for (int mi = 0; mi < 4; mi++) {
#pragma unroll
        for (int half = 0; half < 2; half++) {
            const int m = m0 + warp_m * 64 + mi * 16 + r0 + half * 8;
            if (EPI == 0) {
                const int b = m >> 11;
                const int t = m & (TT - 1);
                const size_t mbase = ((size_t)b * HH) * TT;
#pragma unroll
                for (int ni = 0; ni < 4; ni++) {
#pragma unroll
                    for (int e = 0; e < 2; e++) {
                        int o = n0 + warp_n * 32 + ni * 8 + c0 + e;
                        float v = acc[mi][ni][half * 2 + e];
                        int d = o / 48;
                        int rem = o - d * 48;
                        int kq = rem >> 4;
                        int h = rem & 15;
                        float* dst = (kq == 0) ? g_q : (kq == 1) ? g_k : g_v;
                        dst[((mbase + (size_t)h * TT) + t) * DHD + d] = v;
                    }
                }
            } else {
#pragma unroll
                for (int ni = 0; ni < 4; ni++) {
#pragma unroll
                    for (int e = 0; e < 2; e++) {
                        int o = n0 + warp_n * 32 + ni * 8 + c0 + e;
                        out[(size_t)m * DIMD + o] = acc[mi][ni][half * 2 + e] + bias[o];
                    }
                }
            }
        }
    }
}

// ---------------------------------------------------------------------------
// HMMA flash attention. 256 threads = 8 warps, 16 q-rows per warp.
// smem: flat [256][APAD] bf16. Q phase: Qh rows 0-127, Ql 128-255.
// Chunk phase: Kh 0-63, Kl 64-127, Vh 128-191, Vl 192-255.
// ---------------------------------------------------------------------------
__global__ __launch_bounds__(256) void attn_mma_kernel() {
    __shared__ __nv_bfloat16 sm[256 * APAD];

    const int tid = threadIdx.x;
    const int w = tid >> 5;
    const int lane = tid & 31;
    const int bh = blockIdx.x >> 4;
    const int rb = blockIdx.x & 15;
    const int b = bh >> 4;
    const int h = bh & 15;
    const int row0 = rb * 128;

    const float* Qg = g_q + (size_t)bh * TT * DHD;
    const float* Kg = g_k + (size_t)bh * TT * DHD;
    const float* Vg = g_v + (size_t)bh * TT * DHD;

    const uint32_t aSm = smem_u32(sm);

    // ---- Q: load fp32, split to bf16 h/l in smem ----
#pragma unroll
    for (int i = 0; i < 8; i++) {
        int idx = tid + i * 256;          // 2048 float4 = 128 rows x 16 segs
        int r = idx >> 4;
        int d0 = (idx & 15) * 4;
        float4 v = *(const float4*)(Qg + (size_t)(row0 + r) * DHD + d0);
        split_store(&sm[r * APAD + d0], &sm[(128 + r) * APAD + d0], v);
    }
    __syncthreads();

    // ---- Q fragments (register resident for whole kernel) ----
    uint32_t qh[4][4], ql[4][4];
    {
        const uint32_t qrow = w * 16 + (lane & 15);
        const uint32_t qcol = (lane >> 4) * 8;
#pragma unroll
        for (int ks = 0; ks < 4; ks++) {
            ldm_x4(qh[ks], aSm + (qrow * APAD + ks * 16 + qcol) * 2);
            ldm_x4(ql[ks], aSm + ((qrow + 128) * APAD + ks * 16 + qcol) * 2);
        }
    }
    __syncthreads();

    float accO[8][4];
#pragma unroll
    for (int nt = 0; nt < 8; nt++)
#pragma unroll
        for (int e = 0; e < 4; e++) accO[nt][e] = 0.0f;

    float M0 = -1e30f, M1 = -1e30f;
    float L0 = 0.0f, L1 = 0.0f;

    for (int kt = 0; kt < TT / 64; kt++) {
        // ---- load K,V chunk (fp32 -> bf16 h/l split in smem) ----
        const float* Kc = Kg + (size_t)kt * 64 * DHD;
        const float* Vc = Vg + (size_t)kt * 64 * DHD;
#pragma unroll
        for (int i = 0; i < 4; i++) {
            int idx = tid + i * 256;      // 1024 float4 = 64 rows x 16 segs
            int r = idx >> 4;
            int d0 = (idx & 15) * 4;
            float4 kv = *(const float4*)(Kc + (size_t)r * DHD + d0);
            split_store(&sm[r * APAD + d0], &sm[(64 + r) * APAD + d0], kv);
            float4 vv = *(const float4*)(Vc + (size_t)r * DHD + d0);
            split_store(&sm[(128 + r) * APAD + d0], &sm[(192 + r) * APAD + d0], vv);
        }
        __syncthreads();

        // ---- S = Q K^T (3-pass bf16x3) ----
        float accS[8][4];
#pragma unroll
        for (int nt = 0; nt < 8; nt++)
#pragma unroll
            for (int e = 0; e < 4; e++) accS[nt][e] = 0.0f;

        {
            const uint32_t kcolsel = ((lane >> 3) & 1) * 8;
            const uint32_t krowl = (lane & 7);
#pragma unroll
            for (int nt = 0; nt < 8; nt++) {
                const uint32_t krow = nt * 8 + krowl;
#pragma unroll
                for (int ks = 0; ks < 4; ks++) {
                    uint32_t kh[2], kl[2];
                    const uint32_t off = (krow * APAD + ks * 16 + kcolsel) * 2;
                    ldm_x2(kh, aSm + off);
                    ldm_x2(kl, aSm + 64 * APAD * 2 + off);
                    mma16816(accS[nt], qh[ks], kh);
                    mma16816(accS[nt], qh[ks], kl);
                    mma16816(accS[nt], ql[ks], kh);
                }
            }
        }

        // ---- online softmax on fragments ----
        float vm0 = accS[0][0], vm1 = accS[0][2];
#pragma unroll
        for (int nt = 0; nt < 8; nt++) {
            vm0 = fmaxf(vm0, fmaxf(accS[nt][0], accS[nt][1]));
            vm1 = fmaxf(vm1, fmaxf(accS[nt][2], accS[nt][3]));
        }
        vm0 = fmaxf(vm0, __shfl_xor_sync(0xffffffffu, vm0, 1));
        vm0 = fmaxf(vm0, __shfl_xor_sync(0xffffffffu, vm0, 2));
        vm1 = fmaxf(vm1, __shfl_xor_sync(0xffffffffu, vm1, 1));
        vm1 = fmaxf(vm1, __shfl_xor_sync(0xffffffffu, vm1, 2));

        const float Mn0 = fmaxf(M0, vm0);
        const float Mn1 = fmaxf(M1, vm1);
        const float corr0 = fexp2((M0 - Mn0) * EXP_C);
        const float corr1 = fexp2((M1 - Mn1) * EXP_C);
        M0 = Mn0; M1 = Mn1;
        const float mc0 = M0 * EXP_C;
        const float mc1 = M1 * EXP_C;

        float sp0 = 0.0f, sp1 = 0.0f;
#pragma unroll
        for (int nt = 0; nt < 8; nt++) {
            accS[nt][0] = fexp2(fmaf(accS[nt][0], EXP_C, -mc0));
            accS[nt][1] = fexp2(fmaf(accS[nt][1], EXP_C, -mc0));
            accS[nt][2] = fexp2(fmaf(accS[nt][2], EXP_C, -mc1));
            accS[nt][3] = fexp2(fmaf(accS[nt][3], EXP_C, -mc1));
            sp0 += accS[nt][0] + accS[nt][1];
            sp1 += accS[nt][2] + accS[nt][3];
        }
        sp0 += __shfl_xor_sync(0xffffffffu, sp0, 1);
        sp0 += __shfl_xor_sync(0xffffffffu, sp0, 2);
        sp1 += __shfl_xor_sync(0xffffffffu, sp1, 1);
        sp1 += __shfl_xor_sync(0xffffffffu, sp1, 2);
        L0 = L0 * corr0 + sp0;
        L1 = L1 * corr1 + sp1;

#pragma unroll
        for (int nt = 0; nt < 8; nt++) {
            accO[nt][0] *= corr0; accO[nt][1] *= corr0;
            accO[nt][2] *= corr1; accO[nt][3] *= corr1;
        }

        // ---- O += P V (3-pass: Ph*Vh + Ph*Vl + Pl*Vh) ----
        {
            const uint32_t vrowl = 128 + (lane & 7) + ((lane >> 3) & 1) * 8;
#pragma unroll
            for (int kc = 0; kc < 4; kc++) {
                uint32_t ph[4], pl[4];
#pragma unroll
                for (int half = 0; half < 2; half++) {
                    const int nt = 2 * kc + half;
                    uint32_t h0 = pack_bf16x2(accS[nt][0], accS[nt][1]);
                    uint32_t h1 = pack_bf16x2(accS[nt][2], accS[nt][3]);
                    ph[half * 2 + 0] = h0;   // wait: mapping below
                    ph[half * 2 + 1] = h1;
                    float f0 = __uint_as_float(h0 << 16);
                    float f1 = __uint_as_float(h0 & 0xffff0000u);
                    float f2 = __uint_as_float(h1 << 16);
                    float f3 = __uint_as_float(h1 & 0xffff0000u);
                    pl[half * 2 + 0] = pack_bf16x2(accS[nt][0] - f0, accS[nt][1] - f1);
                    pl[half * 2 + 1] = pack_bf16x2(accS[nt][2] - f2, accS[nt][3] - f3);
                }
                const uint32_t vrow = vrowl + kc * 16;
#pragma unroll
                for (int nt = 0; nt < 8; nt++) {
                    uint32_t vh[2], vl[2];
                    ldm_x2_trans(vh, aSm + (vrow * APAD + nt * 8) * 2);
                    ldm_x2_trans(vl, aSm + ((vrow + 64) * APAD + nt * 8) * 2);
                    mma16816(accO[nt], ph, vh);
                    mma16816(accO[nt], ph, vl);
                    mma16816(accO[nt], pl, vh);
                }
            }
        }
        __syncthreads();
    }

    // ---- epilogue: normalize, write g_ao[b, t, h*64+d] ----
    const float i0 = 1.0f / L0;
    const float i1 = 1.0f / L1;
    const int r = lane >> 2;
    const int c = (lane & 3) * 2;
    const int row = row0 + w * 16 + r;
    float* dst0 = g_ao + ((size_t)b * TT + row) * DIMD + h * DHD;
    float* dst1 = dst0 + 8 * DIMD;
#pragma unroll
    for (int nt = 0; nt < 8; nt++) {
        float2 v0 = make_float2(accO[nt][0] * i0, accO[nt][1] * i0);
        float2 v1 = make_float2(accO[nt][2] * i1, accO[nt][3] * i1);
        *(float2*)(dst0 + nt * 8 + c) = v0;
        *(float2*)(dst1 + nt * 8 + c) = v1;
    }
}

// ---------------------------------------------------------------------------
extern "C" void kernel_launch(void* const* d_in, const int* in_sizes, int n_in,
                              void* d_out, int out_size) {
    const float* x     = (const float*)d_in[0];
    const float* w_qkv = (const float*)d_in[1];
    const float* w_out = (const float*)d_in[2];
    const float* b_out = (const float*)d_in[3];
    float* y = (float*)d_out;

    void *p_xh, *p_xl, *p_wqh, *p_wql, *p_woh, *p_wol, *p_aoh, *p_aol, *p_ao;
    cudaGetSymbolAddress(&p_xh, g_xh);
    cudaGetSymbolAddress(&p_xl, g_xl);
    cudaGetSymbolAddress(&p_wqh, g_wqh);
    cudaGetSymbolAddress(&p_wql, g_wql);
    cudaGetSymbolAddress(&p_woh, g_woh);
    cudaGetSymbolAddress(&p_wol, g_wol);
    cudaGetSymbolAddress(&p_aoh, g_aoh);
    cudaGetSymbolAddress(&p_aol, g_aol);
    cudaGetSymbolAddress(&p_ao, g_ao);

    {
        int n4 = (BB * TT * DIMD) / 4;
        split_kernel<<<(n4 + 255) / 256, 256>>>(x, (__nv_bfloat16*)p_xh, (__nv_bfloat16*)p_xl, n4);
    }
    {
        int n4 = (NQKV * DIMD) / 4;
        split_kernel<<<(n4 + 255) / 256, 256>>>(w_qkv, (__nv_bfloat16*)p_wqh, (__nv_bfloat16*)p_wql, n4);
    }
    {
        int n4 = (DIMD * DIMD) / 4;
        split_kernel<<<(n4 + 255) / 256, 256>>>(w_out, (__nv_bfloat16*)p_woh, (__nv_bfloat16*)p_wol, n4);
    }

    // QKV projection: M=8192, N=3072
    {
        dim3 g(NQKV / 128, (BB * TT) / 128);
        mma_gemm<0><<<g, 256>>>((__nv_bfloat16*)p_xh, (__nv_bfloat16*)p_xl,
                                (__nv_bfloat16*)p_wqh, (__nv_bfloat16*)p_wql,
                                nullptr, nullptr);
    }

    // Attention (HMMA flash)
    attn_mma_kernel<<<BB * HH * (TT / 128), 256>>>();

    {
        int n4 = (BB * TT * DIMD) / 4;
        split_kernel<<<(n4 + 255) / 256, 256>>>((const float*)p_ao,
                                                (__nv_bfloat16*)p_aoh, (__nv_bfloat16*)p_aol, n4);
    }

    // Output projection: M=8192, N=1024 (+bias)
    {
        dim3 g(DIMD / 128, (BB * TT) / 128);
        mma_gemm<1><<<g, 256>>>((__nv_bfloat16*)p_aoh, (__nv_bfloat16*)p_aol,
                                (__nv_bfloat16*)p_woh, (__nv_bfloat16*)p_wol,
                                b_out, y);
    }
}

// round 6
// speedup vs baseline: 2.5748x; 1.2938x over previous
#include <cuda_runtime.h>
#include <cuda_bf16.h>
#include <math.h>
#include <stdint.h>

#define BB 4
#define TT 2048
#define DIMD 1024
#define HH 16
#define DHD 64
#define NQKV 3072
#define KDIM 1024
#define ROWPAD 40   /* gemm smem row pad (bf16): 80B rows (16B-mult), conflict-free ldmatrix */
#define APAD 72     /* attention smem row pad (bf16): 144B rows (16B-mult), conflict-free */
#define EXP_C 0.045084439f  /* (1/32) * log2(e) */

// ---------------------------------------------------------------------------
// Device-global scratch (no allocation allowed)
// ---------------------------------------------------------------------------
__device__ __nv_bfloat16 g_qh[BB * HH * TT * DHD];   // [b,h,t,d] split hi/lo
__device__ __nv_bfloat16 g_ql[BB * HH * TT * DHD];
__device__ __nv_bfloat16 g_kh[BB * HH * TT * DHD];
__device__ __nv_bfloat16 g_kl[BB * HH * TT * DHD];
__device__ __nv_bfloat16 g_vh[BB * HH * TT * DHD];
__device__ __nv_bfloat16 g_vl[BB * HH * TT * DHD];

__device__ __nv_bfloat16 g_xh[BB * TT * DIMD];
__device__ __nv_bfloat16 g_xl[BB * TT * DIMD];
__device__ __nv_bfloat16 g_wqh[NQKV * DIMD];
__device__ __nv_bfloat16 g_wql[NQKV * DIMD];
__device__ __nv_bfloat16 g_woh[DIMD * DIMD];
__device__ __nv_bfloat16 g_wol[DIMD * DIMD];
__device__ __nv_bfloat16 g_aoh[BB * TT * DIMD];      // attention out split
__device__ __nv_bfloat16 g_aol[BB * TT * DIMD];

// ---------------------------------------------------------------------------
// Standard-PTX helpers (valid at compute_103 non-'a' target)
// ---------------------------------------------------------------------------
__device__ __forceinline__ uint32_t smem_u32(const void* p) {
    uint32_t a;
    asm("{ .reg .u64 t; cvta.to.shared.u64 t, %1; cvt.u32.u64 %0, t; }" : "=r"(a) : "l"(p));
    return a;
}

__device__ __forceinline__ void cp16(uint32_t dst, const void* src) {
    asm volatile("cp.async.cg.shared.global [%0], [%1], 16;" :: "r"(dst), "l"(src));
}
#define CP_COMMIT() asm volatile("cp.async.commit_group;" ::: "memory")
#define CP_WAIT1()  asm volatile("cp.async.wait_group 1;" ::: "memory")
#define CP_WAIT0()  asm volatile("cp.async.wait_group 0;" ::: "memory")

__device__ __forceinline__ void ldm_x4(uint32_t* r, uint32_t addr) {
    asm volatile("ldmatrix.sync.aligned.m8n8.x4.shared.b16 {%0,%1,%2,%3}, [%4];"
                 : "=r"(r[0]), "=r"(r[1]), "=r"(r[2]), "=r"(r[3]) : "r"(addr));
}
__device__ __forceinline__ void ldm_x2(uint32_t* r, uint32_t addr) {
    asm volatile("ldmatrix.sync.aligned.m8n8.x2.shared.b16 {%0,%1}, [%2];"
                 : "=r"(r[0]), "=r"(r[1]) : "r"(addr));
}
__device__ __forceinline__ void ldm_x2_trans(uint32_t* r, uint32_t addr) {
    asm volatile("ldmatrix.sync.aligned.m8n8.x2.trans.shared.b16 {%0,%1}, [%2];"
                 : "=r"(r[0]), "=r"(r[1]) : "r"(addr));
}
__device__ __forceinline__ void mma16816(float* d, const uint32_t* a, const uint32_t* b) {
    asm volatile(
        "mma.sync.aligned.m16n8k16.row.col.f32.bf16.bf16.f32 "
        "{%0,%1,%2,%3}, {%4,%5,%6,%7}, {%8,%9}, {%0,%1,%2,%3};"
        : "+f"(d[0]), "+f"(d[1]), "+f"(d[2]), "+f"(d[3])
        : "r"(a[0]), "r"(a[1]), "r"(a[2]), "r"(a[3]), "r"(b[0]), "r"(b[1]));
}
__device__ __forceinline__ uint32_t pack_bf16x2(float lo, float hi) {
    uint32_t r;
    asm("cvt.rn.satfinite.bf16x2.f32 %0, %1, %2;" : "=r"(r) : "f"(hi), "f"(lo));
    return r;
}
__device__ __forceinline__ float fexp2(float x) {
    float r;
    asm("ex2.approx.ftz.f32 %0, %1;" : "=f"(r) : "f"(x));
    return r;
}

// ---------------------------------------------------------------------------
// fp32 -> (bf16 hi, bf16 lo) split pre-pass (inputs only)
// ---------------------------------------------------------------------------
__global__ __launch_bounds__(256) void split_kernel(const float* __restrict__ s,
                                                    __nv_bfloat16* __restrict__ h,
                                                    __nv_bfloat16* __restrict__ l,
                                                    int n4) {
    int i = blockIdx.x * blockDim.x + threadIdx.x;
    if (i >= n4) return;
    float4 v = ((const float4*)s)[i];
    uint2 hp, lp;
    hp.x = pack_bf16x2(v.x, v.y);
    hp.y = pack_bf16x2(v.z, v.w);
    lp.x = pack_bf16x2(v.x - __uint_as_float(hp.x << 16),
                       v.y - __uint_as_float(hp.x & 0xffff0000u));
    lp.y = pack_bf16x2(v.z - __uint_as_float(hp.y << 16),
                       v.w - __uint_as_float(hp.y & 0xffff0000u));
    ((uint2*)h)[i] = hp;
    ((uint2*)l)[i] = lp;
}

// ---------------------------------------------------------------------------
// HMMA bf16x3 GEMM, cp.async double-buffered.
// D[128x128] = A[128xK] * B[128xK]^T, K-chunks of 32, 2 stages.
// EPI 0: split-scatter into g_{q,k,v}{h,l}.  EPI 1: +bias -> out fp32.
// Dynamic smem: 2 stages * 4 arrays * 128*ROWPAD bf16 = 81,920 B.
// ---------------------------------------------------------------------------
#define GAS (128 * ROWPAD)   /* elems per array */

template <int EPI>
__global__ __launch_bounds__(256, 2) void mma_gemm(const __nv_bfloat16* __restrict__ Ahp,
                                                   const __nv_bfloat16* __restrict__ Alp,
                                                   const __nv_bfloat16* __restrict__ Bhp,
                                                   const __nv_bfloat16* __restrict__ Blp,
                                                   const float* __restrict__ bias,
                                                   float* __restrict__ out) {
    extern __shared__ __nv_bfloat16 dsm[];
    const uint32_t aD = smem_u32(dsm);

    const int tid = threadIdx.x;
    const int wid = tid >> 5;
    const int lane = tid & 31;
    const int warp_m = wid & 1;
    const int warp_n = wid >> 1;
    const int m0 = blockIdx.y * 128;
    const int n0 = blockIdx.x * 128;

    const __nv_bfloat16* srcs[4] = {
        Ahp + (size_t)m0 * KDIM, Alp + (size_t)m0 * KDIM,
        Bhp + (size_t)n0 * KDIM, Blp + (size_t)n0 * KDIM};

    const int ld_row = tid >> 2;          // 0..63 (x2 iterations -> 128)
    const int ld_seg = tid & 3;

    const int a_row_base = warp_m * 64 + (lane & 15);
    const int a_colsel = (lane >> 4) * 8;
    const int b_row_base = warp_n * 32 + (lane & 7);
    const int b_colsel = ((lane >> 3) & 1) * 8;

    float acc[4][4][4];
#pragma unroll
    for (int mi = 0; mi < 4; mi++)
#pragma unroll
        for (int ni = 0; ni < 4; ni++)
#pragma unroll
            for (int e = 0; e < 4; e++) acc[mi][ni][e] = 0.0f;

    auto issue = [&](int c, int s) {
        const int k0 = c * 32;
        const uint32_t sb = aD + (uint32_t)s * (4 * GAS * 2);
#pragma unroll
        for (int a = 0; a < 4; a++) {
#pragma unroll
            for (int i = 0; i < 2; i++) {
                int row = ld_row + i * 64;
                cp16(sb + (uint32_t)(a * GAS + row * ROWPAD + ld_seg * 8) * 2,
                     srcs[a] + (size_t)row * KDIM + k0 + ld_seg * 8);
            }
        }
        CP_COMMIT();
    };

    issue(0, 0);

    for (int c = 0; c < 32; c++) {
        if (c + 1 < 32) { issue(c + 1, (c + 1) & 1); CP_WAIT1(); }
        else           { CP_WAIT0(); }
        __syncthreads();

        const uint32_t sb = aD + (uint32_t)(c & 1) * (4 * GAS * 2);
        const uint32_t aAh = sb;
        const uint32_t aAl = sb + GAS * 2;
        const uint32_t aBh = sb + 2 * GAS * 2;
        const uint32_t aBl = sb + 3 * GAS * 2;

#pragma unroll
        for (int kk = 0; kk < 2; kk++) {
            const int acol = kk * 16 + a_colsel;
            const int bcol = kk * 16 + b_colsel;

            uint32_t fa[4][4];
            uint32_t fb[4][2];

#pragma unroll
            for (int mi = 0; mi < 4; mi++)
                ldm_x4(fa[mi], aAh + ((a_row_base + mi * 16) * ROWPAD + acol) * 2);
#pragma unroll
            for (int ni = 0; ni < 4; ni++)
                ldm_x2(fb[ni], aBh + ((b_row_base + ni * 8) * ROWPAD + bcol) * 2);
#pragma unroll
            for (int mi = 0; mi < 4; mi++)
#pragma unroll
                for (int ni = 0; ni < 4; ni++)
                    mma16816(acc[mi][ni], fa[mi], fb[ni]);

            uint32_t fbl[4][2];
#pragma unroll
            for (int ni = 0; ni < 4; ni++)
                ldm_x2(fbl[ni], aBl + ((b_row_base + ni * 8) * ROWPAD + bcol) * 2);
#pragma unroll
            for (int mi = 0; mi < 4; mi++)
#pragma unroll
                for (int ni = 0; ni < 4; ni++)
                    mma16816(acc[mi][ni], fa[mi], fbl[ni]);

#pragma unroll
            for (int mi = 0; mi < 4; mi++)
                ldm_x4(fa[mi], aAl + ((a_row_base + mi * 16) * ROWPAD + acol) * 2);
#pragma unroll
            for (int mi = 0; mi < 4; mi++)
#pragma unroll
                for (int ni = 0; ni < 4; ni++)
                    mma16816(acc[mi][ni], fa[mi], fb[ni]);
        }
        __syncthreads();
    }

    const int r0 = lane >> 2;
    const int c0 = (lane & 3) * 2;
#pragma unroll
    for (int mi = 0; mi < 4; mi++) {
#pragma unroll
        for (int half = 0; half < 2; half++) {
            const int m = m0 + warp_m * 64 + mi * 16 + r0 + half * 8;
            if (EPI == 0) {
                const int b = m >> 11;
                const int t = m & (TT - 1);
                const size_t mbase = ((size_t)b * HH) * TT;
#pragma unroll
                for (int ni = 0; ni < 4; ni++) {
#pragma unroll
                    for (int e = 0; e < 2; e++) {
                        int o = n0 + warp_n * 32 + ni * 8 + c0 + e;
                        float v = acc[mi][ni][half * 2 + e];
                        int d = o / 48;
                        int rem = o - d * 48;
                        int kq = rem >> 4;
                        int h = rem & 15;
                        __nv_bfloat16* dh = (kq == 0) ? g_qh : (kq == 1) ? g_kh : g_vh;
                        __nv_bfloat16* dl = (kq == 0) ? g_ql : (kq == 1) ? g_kl : g_vl;
                        size_t idx = ((mbase + (size_t)h * TT) + t) * DHD + d;
                        __nv_bfloat16 hi = __float2bfloat16(v);
                        dh[idx] = hi;
                        dl[idx] = __float2bfloat16(v - __bfloat162float(hi));
                    }
                }
            } else {
#pragma unroll
                for (int ni = 0; ni < 4; ni++) {
#pragma unroll
                    for (int e = 0; e < 2; e++) {
                        int o = n0 + warp_n * 32 + ni * 8 + c0 + e;
                        out[(size_t)m * DIMD + o] = acc[mi][ni][half * 2 + e] + bias[o];
                    }
                }
            }
        }
    }
}

// ---------------------------------------------------------------------------
// HMMA flash attention, cp.async double-buffered, pre-split bf16 inputs.
// 256 threads = 8 warps x 16 q-rows. 64-key chunks.
// Dynamic smem: 2 stages * 4 arrays (Kh,Kl,Vh,Vl) * 64*APAD bf16 = 73,728 B.
// Q hi/lo staged transiently in stage-0 region before the pipeline starts.
// ---------------------------------------------------------------------------
#define ARR (64 * APAD)      /* elems per chunk array */

__global__ __launch_bounds__(256) void attn_mma_kernel() {
    extern __shared__ __nv_bfloat16 dsm[];
    const uint32_t aD = smem_u32(dsm);

    const int tid = threadIdx.x;
    const int w = tid >> 5;
    const int lane = tid & 31;
    const int bh = blockIdx.x >> 4;
    const int rb = blockIdx.x & 15;
    const int b = bh >> 4;
    const int h = bh & 15;
    const int row0 = rb * 128;

    const __nv_bfloat16* Qh = g_qh + (size_t)bh * TT * DHD;
    const __nv_bfloat16* Ql = g_ql + (size_t)bh * TT * DHD;
    const __nv_bfloat16* Kh = g_kh + (size_t)bh * TT * DHD;
    const __nv_bfloat16* Kl = g_kl + (size_t)bh * TT * DHD;
    const __nv_bfloat16* Vh = g_vh + (size_t)bh * TT * DHD;
    const __nv_bfloat16* Vl = g_vl + (size_t)bh * TT * DHD;

    // ---- stage Q hi/lo into smem (rows 0-127 hi, 128-255 lo), build fragments ----
    {
        const int r = tid >> 1;            // 0..127
        const int seg = tid & 1;           // 2 segs of 32B? -> use 4x16B per row: redo
    }
    // 128 rows x 64 bf16 = 8 segs of 16B per row, x2 arrays = 2048 segs, 8/thread
#pragma unroll
    for (int i = 0; i < 4; i++) {
        int idx = tid + i * 256;           // 0..1023 : rows 0..127, segs 0..7
        int r = idx >> 3;
        int sg = idx & 7;
        *(uint4*)&dsm[r * APAD + sg * 8] =
            *(const uint4*)(Qh + (size_t)(row0 + r) * DHD + sg * 8);
        *(uint4*)&dsm[(128 + r) * APAD + sg * 8] =
            *(const uint4*)(Ql + (size_t)(row0 + r) * DHD + sg * 8);
    }
    __syncthreads();

    uint32_t qh[4][4], ql[4][4];
    {
        const uint32_t qrow = w * 16 + (lane & 15);
        const uint32_t qcol = (lane >> 4) * 8;
#pragma unroll
        for (int ks = 0; ks < 4; ks++) {
            ldm_x4(qh[ks], aD + (qrow * APAD + ks * 16 + qcol) * 2);
            ldm_x4(ql[ks], aD + ((qrow + 128) * APAD + ks * 16 + qcol) * 2);
        }
    }
    __syncthreads();   // all fragment reads done before cp.async overwrites

    const int ld_row = tid >> 2;           // 0..63
    const int ld_seg = tid & 3;            // 4 segs (x2 iter -> 8)

    auto issue = [&](int kt, int s) {
        const size_t goff = (size_t)kt * 64 * DHD;
        const uint32_t sb = aD + (uint32_t)s * (4 * ARR * 2);
        const __nv_bfloat16* srcs[4] = {Kh + goff, Kl + goff, Vh + goff, Vl + goff};
#pragma unroll
        for (int a = 0; a < 4; a++) {
#pragma unroll
            for (int i = 0; i < 2; i++) {
                int sg = ld_seg + i * 4;
                cp16(sb + (uint32_t)(a * ARR + ld_row * APAD + sg * 8) * 2,
                     srcs[a] + (size_t)ld_row * DHD + sg * 8);
            }
        }
        CP_COMMIT();
    };

    float accO[8][4];
#pragma unroll
    for (int nt = 0; nt < 8; nt++)
#pragma unroll
        for (int e = 0; e < 4; e++) accO[nt][e] = 0.0f;

    float M0 = -1e30f, M1 = -1e30f;
    float L0 = 0.0f, L1 = 0.0f;

    issue(0, 0);

    for (int kt = 0; kt < TT / 64; kt++) {
        if (kt + 1 < TT / 64) { issue(kt + 1, (kt + 1) & 1); CP_WAIT1(); }
        else                  { CP_WAIT0(); }
        __syncthreads();

        const uint32_t sb = aD + (uint32_t)(kt & 1) * (4 * ARR * 2);
        const uint32_t aKh = sb;
        const uint32_t aKl = sb + ARR * 2;
        const uint32_t aVh = sb + 2 * ARR * 2;
        const uint32_t aVl = sb + 3 * ARR * 2;

        // ---- S = Q K^T (3-pass bf16x3) ----
        float accS[8][4];
#pragma unroll
        for (int nt = 0; nt < 8; nt++)
#pragma unroll
            for (int e = 0; e < 4; e++) accS[nt][e] = 0.0f;

        {
            const uint32_t kcolsel = ((lane >> 3) & 1) * 8;
            const uint32_t krowl = (lane & 7);
#pragma unroll
            for (int nt = 0; nt < 8; nt++) {
                const uint32_t krow = nt * 8 + krowl;
#pragma unroll
                for (int ks = 0; ks < 4; ks++) {
                    uint32_t kfh[2], kfl[2];
                    const uint32_t off = (krow * APAD + ks * 16 + kcolsel) * 2;
                    ldm_x2(kfh, aKh + off);
                    ldm_x2(kfl, aKl + off);
                    mma16816(accS[nt], qh[ks], kfh);
                    mma16816(accS[nt], qh[ks], kfl);
                    mma16816(accS[nt], ql[ks], kfh);
                }
            }
        }

        // ---- online softmax ----
        float vm0 = accS[0][0], vm1 = accS[0][2];
#pragma unroll
        for (int nt = 0; nt < 8; nt++) {
            vm0 = fmaxf(vm0, fmaxf(accS[nt][0], accS[nt][1]));
            vm1 = fmaxf(vm1, fmaxf(accS[nt][2], accS[nt][3]));
        }
        vm0 = fmaxf(vm0, __shfl_xor_sync(0xffffffffu, vm0, 1));
        vm0 = fmaxf(vm0, __shfl_xor_sync(0xffffffffu, vm0, 2));
        vm1 = fmaxf(vm1, __shfl_xor_sync(0xffffffffu, vm1, 1));
        vm1 = fmaxf(vm1, __shfl_xor_sync(0xffffffffu, vm1, 2));

        const float Mn0 = fmaxf(M0, vm0);
        const float Mn1 = fmaxf(M1, vm1);
        const float corr0 = fexp2((M0 - Mn0) * EXP_C);
        const float corr1 = fexp2((M1 - Mn1) * EXP_C);
        M0 = Mn0; M1 = Mn1;
        const float mc0 = M0 * EXP_C;
        const float mc1 = M1 * EXP_C;

        float sp0 = 0.0f, sp1 = 0.0f;
#pragma unroll
        for (int nt = 0; nt < 8; nt++) {
            accS[nt][0] = fexp2(fmaf(accS[nt][0], EXP_C, -mc0));
            accS[nt][1] = fexp2(fmaf(accS[nt][1], EXP_C, -mc0));
            accS[nt][2] = fexp2(fmaf(accS[nt][2], EXP_C, -mc1));
            accS[nt][3] = fexp2(fmaf(accS[nt][3], EXP_C, -mc1));
            sp0 += accS[nt][0] + accS[nt][1];
            sp1 += accS[nt][2] + accS[nt][3];
        }
        sp0 += __shfl_xor_sync(0xffffffffu, sp0, 1);
        sp0 += __shfl_xor_sync(0xffffffffu, sp0, 2);
        sp1 += __shfl_xor_sync(0xffffffffu, sp1, 1);
        sp1 += __shfl_xor_sync(0xffffffffu, sp1, 2);
        L0 = L0 * corr0 + sp0;
        L1 = L1 * corr1 + sp1;

#pragma unroll
        for (int nt = 0; nt < 8; nt++) {
            accO[nt][0] *= corr0; accO[nt][1] *= corr0;
            accO[nt][2] *= corr1; accO[nt][3] *= corr1;
        }

        // ---- O += P V (3-pass) ----
        {
            const uint32_t vrowl = (lane & 7) + ((lane >> 3) & 1) * 8;
#pragma unroll
            for (int kc = 0; kc < 4; kc++) {
                uint32_t ph[4], pl[4];
#pragma unroll
                for (int half = 0; half < 2; half++) {
                    const int nt = 2 * kc + half;
                    uint32_t h0 = pack_bf16x2(accS[nt][0], accS[nt][1]);
                    uint32_t h1 = pack_bf16x2(accS[nt][2], accS[nt][3]);
                    ph[half * 2 + 0] = h0;
                    ph[half * 2 + 1] = h1;
                    float f0 = __uint_as_float(h0 << 16);
                    float f1 = __uint_as_float(h0 & 0xffff0000u);
                    float f2 = __uint_as_float(h1 << 16);
                    float f3 = __uint_as_float(h1 & 0xffff0000u);
                    pl[half * 2 + 0] = pack_bf16x2(accS[nt][0] - f0, accS[nt][1] - f1);
                    pl[half * 2 + 1] = pack_bf16x2(accS[nt][2] - f2, accS[nt][3] - f3);
                }
                const uint32_t vrow = vrowl + kc * 16;
#pragma unroll
                for (int nt = 0; nt < 8; nt++) {
                    uint32_t vfh[2], vfl[2];
                    ldm_x2_trans(vfh, aVh + (vrow * APAD + nt * 8) * 2);
                    ldm_x2_trans(vfl, aVl + (vrow * APAD + nt * 8) * 2);
                    mma16816(accO[nt], ph, vfh);
                    mma16816(accO[nt], ph, vfl);
                    mma16816(accO[nt], pl, vfh);
                }
            }
        }
        __syncthreads();
    }

    // ---- epilogue: normalize, split to bf16 hi/lo, write g_aoh/g_aol ----
    const float i0 = 1.0f / L0;
    const float i1 = 1.0f / L1;
    const int r = lane >> 2;
    const int c = (lane & 3) * 2;
    const int row = row0 + w * 16 + r;
    const size_t base0 = ((size_t)b * TT + row) * DIMD + h * DHD + c;
    const size_t base1 = base0 + 8 * DIMD;
#pragma unroll
    for (int nt = 0; nt < 8; nt++) {
        float a0 = accO[nt][0] * i0, a1 = accO[nt][1] * i0;
        float b0 = accO[nt][2] * i1, b1 = accO[nt][3] * i1;
        uint32_t h0 = pack_bf16x2(a0, a1);
        uint32_t h1 = pack_bf16x2(b0, b1);
        uint32_t l0 = pack_bf16x2(a0 - __uint_as_float(h0 << 16),
                                  a1 - __uint_as_float(h0 & 0xffff0000u));
        uint32_t l1 = pack_bf16x2(b0 - __uint_as_float(h1 << 16),
                                  b1 - __uint_as_float(h1 & 0xffff0000u));
        *(uint32_t*)(g_aoh + base0 + nt * 8) = h0;
        *(uint32_t*)(g_aol + base0 + nt * 8) = l0;
        *(uint32_t*)(g_aoh + base1 + nt * 8) = h1;
        *(uint32_t*)(g_aol + base1 + nt * 8) = l1;
    }
}

// ---------------------------------------------------------------------------
extern "C" void kernel_launch(void* const* d_in, const int* in_sizes, int n_in,
                              void* d_out, int out_size) {
    const float* x     = (const float*)d_in[0];
    const float* w_qkv = (const float*)d_in[1];
    const float* w_out = (const float*)d_in[2];
    const float* b_out = (const float*)d_in[3];
    float* y = (float*)d_out;

    void *p_xh, *p_xl, *p_wqh, *p_wql, *p_woh, *p_wol, *p_aoh, *p_aol;
    cudaGetSymbolAddress(&p_xh, g_xh);
    cudaGetSymbolAddress(&p_xl, g_xl);
    cudaGetSymbolAddress(&p_wqh, g_wqh);
    cudaGetSymbolAddress(&p_wql, g_wql);
    cudaGetSymbolAddress(&p_woh, g_woh);
    cudaGetSymbolAddress(&p_wol, g_wol);
    cudaGetSymbolAddress(&p_aoh, g_aoh);
    cudaGetSymbolAddress(&p_aol, g_aol);

    const int GEMM_SMEM = 2 * 4 * GAS * 2;   // 81,920 B
    const int ATTN_SMEM = 2 * 4 * ARR * 2;   // 73,728 B
    cudaFuncSetAttribute(mma_gemm<0>, cudaFuncAttributeMaxDynamicSharedMemorySize, GEMM_SMEM);
    cudaFuncSetAttribute(mma_gemm<1>, cudaFuncAttributeMaxDynamicSharedMemorySize, GEMM_SMEM);
    cudaFuncSetAttribute(attn_mma_kernel, cudaFuncAttributeMaxDynamicSharedMemorySize, ATTN_SMEM);

    {
        int n4 = (BB * TT * DIMD) / 4;
        split_kernel<<<(n4 + 255) / 256, 256>>>(x, (__nv_bfloat16*)p_xh, (__nv_bfloat16*)p_xl, n4);
    }
    {
        int n4 = (NQKV * DIMD) / 4;
        split_kernel<<<(n4 + 255) / 256, 256>>>(w_qkv, (__nv_bfloat16*)p_wqh, (__nv_bfloat16*)p_wql, n4);
    }
    {
        int n4 = (DIMD * DIMD) / 4;
        split_kernel<<<(n4 + 255) / 256, 256>>>(w_out, (__nv_bfloat16*)p_woh, (__nv_bfloat16*)p_wol, n4);
    }

    // QKV projection: M=8192, N=3072 (epilogue splits into g_{q,k,v}{h,l})
    {
        dim3 g(NQKV / 128, (BB * TT) / 128);
        mma_gemm<0><<<g, 256, GEMM_SMEM>>>((__nv_bfloat16*)p_xh, (__nv_bfloat16*)p_xl,
                                           (__nv_bfloat16*)p_wqh, (__nv_bfloat16*)p_wql,
                                           nullptr, nullptr);
    }

    // Attention (HMMA flash, double-buffered)
    attn_mma_kernel<<<BB * HH * (TT / 128), 256, ATTN_SMEM>>>();

    // Output projection: M=8192, N=1024 (+bias)
    {
        dim3 g(DIMD / 128, (BB * TT) / 128);
        mma_gemm<1><<<g, 256, GEMM_SMEM>>>((__nv_bfloat16*)p_aoh, (__nv_bfloat16*)p_aol,
                                           (__nv_bfloat16*)p_woh, (__nv_bfloat16*)p_wol,
                                           b_out, y);
    }
}

// round 7
// speedup vs baseline: 2.7145x; 1.0543x over previous
#include <cuda_runtime.h>
#include <cuda_bf16.h>
#include <math.h>
#include <stdint.h>

#define BB 4
#define TT 2048
#define DIMD 1024
#define HH 16
#define DHD 64
#define NQKV 3072
#define KDIM 1024
#define ROWPAD 40   /* gemm smem row pad (bf16) */
#define APAD 72     /* attention smem row pad (bf16) */
#define EXP_C 0.045084439f  /* (1/32) * log2(e) */

// ---------------------------------------------------------------------------
// Device-global scratch
// ---------------------------------------------------------------------------
__device__ __nv_bfloat16 g_qh[BB * HH * TT * DHD];
__device__ __nv_bfloat16 g_ql[BB * HH * TT * DHD];
__device__ __nv_bfloat16 g_kh[BB * HH * TT * DHD];
__device__ __nv_bfloat16 g_kl[BB * HH * TT * DHD];
__device__ __nv_bfloat16 g_vh[BB * HH * TT * DHD];
__device__ __nv_bfloat16 g_vl[BB * HH * TT * DHD];

__device__ __nv_bfloat16 g_xh[BB * TT * DIMD];
__device__ __nv_bfloat16 g_xl[BB * TT * DIMD];
__device__ __nv_bfloat16 g_wqh[NQKV * DIMD];
__device__ __nv_bfloat16 g_wql[NQKV * DIMD];
__device__ __nv_bfloat16 g_woh[DIMD * DIMD];
__device__ __nv_bfloat16 g_wol[DIMD * DIMD];
__device__ __nv_bfloat16 g_aoh[BB * TT * DIMD];
__device__ __nv_bfloat16 g_aol[BB * TT * DIMD];

// ---------------------------------------------------------------------------
// Standard-PTX helpers (compute_103-safe)
// ---------------------------------------------------------------------------
__device__ __forceinline__ uint32_t smem_u32(const void* p) {
    uint32_t a;
    asm("{ .reg .u64 t; cvta.to.shared.u64 t, %1; cvt.u32.u64 %0, t; }" : "=r"(a) : "l"(p));
    return a;
}
__device__ __forceinline__ void cp16(uint32_t dst, const void* src) {
    asm volatile("cp.async.cg.shared.global [%0], [%1], 16;" :: "r"(dst), "l"(src));
}
#define CP_COMMIT() asm volatile("cp.async.commit_group;" ::: "memory")
#define CP_WAIT1()  asm volatile("cp.async.wait_group 1;" ::: "memory")
#define CP_WAIT0()  asm volatile("cp.async.wait_group 0;" ::: "memory")

__device__ __forceinline__ void ldm_x4(uint32_t* r, uint32_t addr) {
    asm volatile("ldmatrix.sync.aligned.m8n8.x4.shared.b16 {%0,%1,%2,%3}, [%4];"
                 : "=r"(r[0]), "=r"(r[1]), "=r"(r[2]), "=r"(r[3]) : "r"(addr));
}
__device__ __forceinline__ void ldm_x4_trans(uint32_t* r, uint32_t addr) {
    asm volatile("ldmatrix.sync.aligned.m8n8.x4.trans.shared.b16 {%0,%1,%2,%3}, [%4];"
                 : "=r"(r[0]), "=r"(r[1]), "=r"(r[2]), "=r"(r[3]) : "r"(addr));
}
__device__ __forceinline__ void mma16816(float* d, const uint32_t* a, const uint32_t* b) {
    asm volatile(
        "mma.sync.aligned.m16n8k16.row.col.f32.bf16.bf16.f32 "
        "{%0,%1,%2,%3}, {%4,%5,%6,%7}, {%8,%9}, {%0,%1,%2,%3};"
        : "+f"(d[0]), "+f"(d[1]), "+f"(d[2]), "+f"(d[3])
        : "r"(a[0]), "r"(a[1]), "r"(a[2]), "r"(a[3]), "r"(b[0]), "r"(b[1]));
}
__device__ __forceinline__ uint32_t pack_bf16x2(float lo, float hi) {
    uint32_t r;
    asm("cvt.rn.satfinite.bf16x2.f32 %0, %1, %2;" : "=r"(r) : "f"(hi), "f"(lo));
    return r;
}
__device__ __forceinline__ float fexp2(float x) {
    float r;
    asm("ex2.approx.ftz.f32 %0, %1;" : "=f"(r) : "f"(x));
    return r;
}

// ---------------------------------------------------------------------------
// fp32 -> (bf16 hi, bf16 lo) split pre-pass
// ---------------------------------------------------------------------------
__global__ __launch_bounds__(256) void split_kernel(const float* __restrict__ s,
                                                    __nv_bfloat16* __restrict__ h,
                                                    __nv_bfloat16* __restrict__ l,
                                                    int n4) {
    int i = blockIdx.x * blockDim.x + threadIdx.x;
    if (i >= n4) return;
    float4 v = ((const float4*)s)[i];
    uint2 hp, lp;
    hp.x = pack_bf16x2(v.x, v.y);
    hp.y = pack_bf16x2(v.z, v.w);
    lp.x = pack_bf16x2(v.x - __uint_as_float(hp.x << 16),
                       v.y - __uint_as_float(hp.x & 0xffff0000u));
    lp.y = pack_bf16x2(v.z - __uint_as_float(hp.y << 16),
                       v.w - __uint_as_float(hp.y & 0xffff0000u));
    ((uint2*)h)[i] = hp;
    ((uint2*)l)[i] = lp;
}

// ---------------------------------------------------------------------------
// HMMA bf16x3 GEMM, cp.async double-buffered, x4-paired B fragments.
// ---------------------------------------------------------------------------
#define GAS (128 * ROWPAD)

template <int EPI>
__global__ __launch_bounds__(256, 2) void mma_gemm(const __nv_bfloat16* __restrict__ Ahp,
                                                   const __nv_bfloat16* __restrict__ Alp,
                                                   const __nv_bfloat16* __restrict__ Bhp,
                                                   const __nv_bfloat16* __restrict__ Blp,
                                                   const float* __restrict__ bias,
                                                   float* __restrict__ out) {
    extern __shared__ __nv_bfloat16 dsm[];
    const uint32_t aD = smem_u32(dsm);

    const int tid = threadIdx.x;
    const int wid = tid >> 5;
    const int lane = tid & 31;
    const int warp_m = wid & 1;
    const int warp_n = wid >> 1;
    const int m0 = blockIdx.y * 128;
    const int n0 = blockIdx.x * 128;

    const __nv_bfloat16* srcs[4] = {
        Ahp + (size_t)m0 * KDIM, Alp + (size_t)m0 * KDIM,
        Bhp + (size_t)n0 * KDIM, Blp + (size_t)n0 * KDIM};

    const int ld_row = tid >> 2;
    const int ld_seg = tid & 3;

    // A fragment addressing (x4 per 16-row tile)
    const int a_row_base = warp_m * 64 + (lane & 15);
    const int a_colsel = (lane >> 4) * 8;
    // B fragment addressing: x4 pairs two 8-col n-tiles
    //   row = warp_n*32 + ni2*16 + ((lane>>4)&1)*8 + (lane&7)
    //   col = kk*16 + ((lane>>3)&1)*8
    const int b_row_base = warp_n * 32 + ((lane >> 4) & 1) * 8 + (lane & 7);
    const int b_colsel = ((lane >> 3) & 1) * 8;

    float acc[4][4][4];
#pragma unroll
    for (int mi = 0; mi < 4; mi++)
#pragma unroll
        for (int ni = 0; ni < 4; ni++)
#pragma unroll
            for (int e = 0; e < 4; e++) acc[mi][ni][e] = 0.0f;

    auto issue = [&](int c, int s) {
        const int k0 = c * 32;
        const uint32_t sb = aD + (uint32_t)s * (4 * GAS * 2);
#pragma unroll
        for (int a = 0; a < 4; a++) {
#pragma unroll
            for (int i = 0; i < 2; i++) {
                int row = ld_row + i * 64;
                cp16(sb + (uint32_t)(a * GAS + row * ROWPAD + ld_seg * 8) * 2,
                     srcs[a] + (size_t)row * KDIM + k0 + ld_seg * 8);
            }
        }
        CP_COMMIT();
    };

    issue(0, 0);

    for (int c = 0; c < 32; c++) {
        if (c + 1 < 32) { issue(c + 1, (c + 1) & 1); CP_WAIT1(); }
        else           { CP_WAIT0(); }
        __syncthreads();

        const uint32_t sb = aD + (uint32_t)(c & 1) * (4 * GAS * 2);
        const uint32_t aAh = sb;
        const uint32_t aAl = sb + GAS * 2;
        const uint32_t aBh = sb + 2 * GAS * 2;
        const uint32_t aBl = sb + 3 * GAS * 2;

#pragma unroll
        for (int kk = 0; kk < 2; kk++) {
            const int acol = kk * 16 + a_colsel;
            const int bcol = kk * 16 + b_colsel;

            uint32_t fa[4][4];
            uint32_t fbh[4][2];   // [ni][khalf], filled pairwise by x4
            uint32_t fbl[4][2];

            // front-load all hi fragments + lo-B
#pragma unroll
            for (int mi = 0; mi < 4; mi++)
                ldm_x4(fa[mi], aAh + ((a_row_base + mi * 16) * ROWPAD + acol) * 2);
#pragma unroll
            for (int ni2 = 0; ni2 < 2; ni2++) {
                const uint32_t boff = ((b_row_base + ni2 * 16) * ROWPAD + bcol) * 2;
                ldm_x4(&fbh[ni2 * 2][0], aBh + boff);
                ldm_x4(&fbl[ni2 * 2][0], aBl + boff);
            }

            // pass 1: Ah*Bh ; pass 2: Ah*Bl (interleaved per mi for ILP)
#pragma unroll
            for (int mi = 0; mi < 4; mi++) {
#pragma unroll
                for (int ni = 0; ni < 4; ni++) mma16816(acc[mi][ni], fa[mi], fbh[ni]);
#pragma unroll
                for (int ni = 0; ni < 4; ni++) mma16816(acc[mi][ni], fa[mi], fbl[ni]);
            }
            // pass 3: Al*Bh
#pragma unroll
            for (int mi = 0; mi < 4; mi++) {
                ldm_x4(fa[mi], aAl + ((a_row_base + mi * 16) * ROWPAD + acol) * 2);
#pragma unroll
                for (int ni = 0; ni < 4; ni++) mma16816(acc[mi][ni], fa[mi], fbh[ni]);
            }
        }
        __syncthreads();
    }

    const int r0 = lane >> 2;
    const int c0 = (lane & 3) * 2;
#pragma unroll
    for (int mi = 0; mi < 4; mi++) {
#pragma unroll
        for (int half = 0; half < 2; half++) {
            const int m = m0 + warp_m * 64 + mi * 16 + r0 + half * 8;
            if (EPI == 0) {
                const int b = m >> 11;
                const int t = m & (TT - 1);
                const size_t mbase = ((size_t)b * HH) * TT;
#pragma unroll
                for (int ni = 0; ni < 4; ni++) {
#pragma unroll
                    for (int e = 0; e < 2; e++) {
                        int o = n0 + (wid >> 1) * 32 + ni * 8 + c0 + e;
                        float v = acc[mi][ni][half * 2 + e];
                        int d = o / 48;
                        int rem = o - d * 48;
                        int kq = rem >> 4;
                        int h = rem & 15;
                        __nv_bfloat16* dh = (kq == 0) ? g_qh : (kq == 1) ? g_kh : g_vh;
                        __nv_bfloat16* dl = (kq == 0) ? g_ql : (kq == 1) ? g_kl : g_vl;
                        size_t idx = ((mbase + (size_t)h * TT) + t) * DHD + d;
                        __nv_bfloat16 hi = __float2bfloat16(v);
                        dh[idx] = hi;
                        dl[idx] = __float2bfloat16(v - __bfloat162float(hi));
                    }
                }
            } else {
#pragma unroll
                for (int ni = 0; ni < 4; ni++) {
#pragma unroll
                    for (int e = 0; e < 2; e++) {
                        int o = n0 + (wid >> 1) * 32 + ni * 8 + c0 + e;
                        out[(size_t)m * DIMD + o] = acc[mi][ni][half * 2 + e] + bias[o];
                    }
                }
            }
        }
    }
}

// ---------------------------------------------------------------------------
// HMMA flash attention, x4-paired K and V fragments.
// ---------------------------------------------------------------------------
#define ARR (64 * APAD)

__global__ __launch_bounds__(256, 2) void attn_mma_kernel() {
    extern __shared__ __nv_bfloat16 dsm[];
    const uint32_t aD = smem_u32(dsm);

    const int tid = threadIdx.x;
    const int w = tid >> 5;
    const int lane = tid & 31;
    const int bh = blockIdx.x >> 4;
    const int rb = blockIdx.x & 15;
    const int b = bh >> 4;
    const int h = bh & 15;
    const int row0 = rb * 128;

    const __nv_bfloat16* Qh = g_qh + (size_t)bh * TT * DHD;
    const __nv_bfloat16* Ql = g_ql + (size_t)bh * TT * DHD;
    const __nv_bfloat16* Kh = g_kh + (size_t)bh * TT * DHD;
    const __nv_bfloat16* Kl = g_kl + (size_t)bh * TT * DHD;
    const __nv_bfloat16* Vh = g_vh + (size_t)bh * TT * DHD;
    const __nv_bfloat16* Vl = g_vl + (size_t)bh * TT * DHD;

    // ---- stage Q hi/lo into smem, build register fragments ----
#pragma unroll
    for (int i = 0; i < 4; i++) {
        int idx = tid + i * 256;
        int r = idx >> 3;
        int sg = idx & 7;
        *(uint4*)&dsm[r * APAD + sg * 8] =
            *(const uint4*)(Qh + (size_t)(row0 + r) * DHD + sg * 8);
        *(uint4*)&dsm[(128 + r) * APAD + sg * 8] =
            *(const uint4*)(Ql + (size_t)(row0 + r) * DHD + sg * 8);
    }
    __syncthreads();

    uint32_t qh[4][4], ql[4][4];
    {
        const uint32_t qrow = w * 16 + (lane & 15);
        const uint32_t qcol = (lane >> 4) * 8;
#pragma unroll
        for (int ks = 0; ks < 4; ks++) {
            ldm_x4(qh[ks], aD + (qrow * APAD + ks * 16 + qcol) * 2);
            ldm_x4(ql[ks], aD + ((qrow + 128) * APAD + ks * 16 + qcol) * 2);
        }
    }
    __syncthreads();

    const int ld_row = tid >> 2;
    const int ld_seg = tid & 3;

    auto issue = [&](int kt, int s) {
        const size_t goff = (size_t)kt * 64 * DHD;
        const uint32_t sb = aD + (uint32_t)s * (4 * ARR * 2);
        const __nv_bfloat16* srcs[4] = {Kh + goff, Kl + goff, Vh + goff, Vl + goff};
#pragma unroll
        for (int a = 0; a < 4; a++) {
#pragma unroll
            for (int i = 0; i < 2; i++) {
                int sg = ld_seg + i * 4;
                cp16(sb + (uint32_t)(a * ARR + ld_row * APAD + sg * 8) * 2,
                     srcs[a] + (size_t)ld_row * DHD + sg * 8);
            }
        }
        CP_COMMIT();
    };

    float accO[8][4];
#pragma unroll
    for (int nt = 0; nt < 8; nt++)
#pragma unroll
        for (int e = 0; e < 4; e++) accO[nt][e] = 0.0f;

    float M0 = -1e30f, M1 = -1e30f;
    float L0 = 0.0f, L1 = 0.0f;

    issue(0, 0);

    // K-fragment x4 pairing: row = nt2*16 + ((lane>>4)&1)*8 + (lane&7),
    //                        col = ks*16 + ((lane>>3)&1)*8
    const uint32_t k_rowl = ((lane >> 4) & 1) * 8 + (lane & 7);
    const uint32_t k_coll = ((lane >> 3) & 1) * 8;
    // V-fragment x4.trans pairing: row = kc*16 + ((lane>>3)&1)*8 + (lane&7),
    //                              col = nt2*16 + ((lane>>4)&1)*8
    const uint32_t v_rowl = ((lane >> 3) & 1) * 8 + (lane & 7);
    const uint32_t v_coll = ((lane >> 4) & 1) * 8;

    for (int kt = 0; kt < TT / 64; kt++) {
        if (kt + 1 < TT / 64) { issue(kt + 1, (kt + 1) & 1); CP_WAIT1(); }
        else                  { CP_WAIT0(); }
        __syncthreads();

        const uint32_t sb = aD + (uint32_t)(kt & 1) * (4 * ARR * 2);
        const uint32_t aKh = sb;
        const uint32_t aKl = sb + ARR * 2;
        const uint32_t aVh = sb + 2 * ARR * 2;
        const uint32_t aVl = sb + 3 * ARR * 2;

        // ---- S = Q K^T (3-pass bf16x3, x4-paired K) ----
        float accS[8][4];
#pragma unroll
        for (int nt = 0; nt < 8; nt++)
#pragma unroll
            for (int e = 0; e < 4; e++) accS[nt][e] = 0.0f;

#pragma unroll
        for (int nt2 = 0; nt2 < 4; nt2++) {
            const uint32_t krow = nt2 * 16 + k_rowl;
#pragma unroll
            for (int ks = 0; ks < 4; ks++) {
                uint32_t kfh[4], kfl[4];
                const uint32_t off = (krow * APAD + ks * 16 + k_coll) * 2;
                ldm_x4(kfh, aKh + off);
                ldm_x4(kfl, aKl + off);
                mma16816(accS[2 * nt2 + 0], qh[ks], &kfh[0]);
                mma16816(accS[2 * nt2 + 1], qh[ks], &kfh[2]);
                mma16816(accS[2 * nt2 + 0], qh[ks], &kfl[0]);
                mma16816(accS[2 * nt2 + 1], qh[ks], &kfl[2]);
                mma16816(accS[2 * nt2 + 0], ql[ks], &kfh[0]);
                mma16816(accS[2 * nt2 + 1], ql[ks], &kfh[2]);
            }
        }

        // ---- online softmax ----
        float vm0 = accS[0][0], vm1 = accS[0][2];
#pragma unroll
        for (int nt = 0; nt < 8; nt++) {
            vm0 = fmaxf(vm0, fmaxf(accS[nt][0], accS[nt][1]));
            vm1 = fmaxf(vm1, fmaxf(accS[nt][2], accS[nt][3]));
        }
        vm0 = fmaxf(vm0, __shfl_xor_sync(0xffffffffu, vm0, 1));
        vm0 = fmaxf(vm0, __shfl_xor_sync(0xffffffffu, vm0, 2));
        vm1 = fmaxf(vm1, __shfl_xor_sync(0xffffffffu, vm1, 1));
        vm1 = fmaxf(vm1, __shfl_xor_sync(0xffffffffu, vm1, 2));

        const float Mn0 = fmaxf(M0, vm0);
        const float Mn1 = fmaxf(M1, vm1);
        const float corr0 = fexp2((M0 - Mn0) * EXP_C);
        const float corr1 = fexp2((M1 - Mn1) * EXP_C);
        M0 = Mn0; M1 = Mn1;
        const float mc0 = M0 * EXP_C;
        const float mc1 = M1 * EXP_C;

        float sp0 = 0.0f, sp1 = 0.0f;
#pragma unroll
        for (int nt = 0; nt < 8; nt++) {
            accS[nt][0] = fexp2(fmaf(accS[nt][0], EXP_C, -mc0));
            accS[nt][1] = fexp2(fmaf(accS[nt][1], EXP_C, -mc0));
            accS[nt][2] = fexp2(fmaf(accS[nt][2], EXP_C, -mc1));
            accS[nt][3] = fexp2(fmaf(accS[nt][3], EXP_C, -mc1));
            sp0 += accS[nt][0] + accS[nt][1];
            sp1 += accS[nt][2] + accS[nt][3];
        }
        sp0 += __shfl_xor_sync(0xffffffffu, sp0, 1);
        sp0 += __shfl_xor_sync(0xffffffffu, sp0, 2);
        sp1 += __shfl_xor_sync(0xffffffffu, sp1, 1);
        sp1 += __shfl_xor_sync(0xffffffffu, sp1, 2);
        L0 = L0 * corr0 + sp0;
        L1 = L1 * corr1 + sp1;

#pragma unroll
        for (int nt = 0; nt < 8; nt++) {
            accO[nt][0] *= corr0; accO[nt][1] *= corr0;
            accO[nt][2] *= corr1; accO[nt][3] *= corr1;
        }

        // ---- O += P V (3-pass, x4.trans-paired V) ----
#pragma unroll
        for (int kc = 0; kc < 4; kc++) {
            uint32_t ph[4], pl[4];
#pragma unroll
            for (int half = 0; half < 2; half++) {
                const int nt = 2 * kc + half;
                uint32_t h0 = pack_bf16x2(accS[nt][0], accS[nt][1]);
                uint32_t h1 = pack_bf16x2(accS[nt][2], accS[nt][3]);
                ph[half * 2 + 0] = h0;
                ph[half * 2 + 1] = h1;
                float f0 = __uint_as_float(h0 << 16);
                float f1 = __uint_as_float(h0 & 0xffff0000u);
                float f2 = __uint_as_float(h1 << 16);
                float f3 = __uint_as_float(h1 & 0xffff0000u);
                pl[half * 2 + 0] = pack_bf16x2(accS[nt][0] - f0, accS[nt][1] - f1);
                pl[half * 2 + 1] = pack_bf16x2(accS[nt][2] - f2, accS[nt][3] - f3);
            }
            const uint32_t vrow = kc * 16 + v_rowl;
#pragma unroll
            for (int nt2 = 0; nt2 < 4; nt2++) {
                uint32_t vfh[4], vfl[4];
                const uint32_t off = (vrow * APAD + nt2 * 16 + v_coll) * 2;
                ldm_x4_trans(vfh, aVh + off);
                ldm_x4_trans(vfl, aVl + off);
                mma16816(accO[2 * nt2 + 0], ph, &vfh[0]);
                mma16816(accO[2 * nt2 + 1], ph, &vfh[2]);
                mma16816(accO[2 * nt2 + 0], ph, &vfl[0]);
                mma16816(accO[2 * nt2 + 1], ph, &vfl[2]);
                mma16816(accO[2 * nt2 + 0], pl, &vfh[0]);
                mma16816(accO[2 * nt2 + 1], pl, &vfh[2]);
            }
        }
        __syncthreads();
    }

    // ---- epilogue: normalize, split to bf16 hi/lo ----
    const float i0 = 1.0f / L0;
    const float i1 = 1.0f / L1;
    const int r = lane >> 2;
    const int c = (lane & 3) * 2;
    const int row = row0 + w * 16 + r;
    const size_t base0 = ((size_t)b * TT + row) * DIMD + h * DHD + c;
    const size_t base1 = base0 + 8 * DIMD;
#pragma unroll
    for (int nt = 0; nt < 8; nt++) {
        float a0 = accO[nt][0] * i0, a1 = accO[nt][1] * i0;
        float b0 = accO[nt][2] * i1, b1 = accO[nt][3] * i1;
        uint32_t h0 = pack_bf16x2(a0, a1);
        uint32_t h1 = pack_bf16x2(b0, b1);
        uint32_t l0 = pack_bf16x2(a0 - __uint_as_float(h0 << 16),
                                  a1 - __uint_as_float(h0 & 0xffff0000u));
        uint32_t l1 = pack_bf16x2(b0 - __uint_as_float(h1 << 16),
                                  b1 - __uint_as_float(h1 & 0xffff0000u));
        *(uint32_t*)(g_aoh + base0 + nt * 8) = h0;
        *(uint32_t*)(g_aol + base0 + nt * 8) = l0;
        *(uint32_t*)(g_aoh + base1 + nt * 8) = h1;
        *(uint32_t*)(g_aol + base1 + nt * 8) = l1;
    }
}

// ---------------------------------------------------------------------------
extern "C" void kernel_launch(void* const* d_in, const int* in_sizes, int n_in,
                              void* d_out, int out_size) {
    const float* x     = (const float*)d_in[0];
    const float* w_qkv = (const float*)d_in[1];
    const float* w_out = (const float*)d_in[2];
    const float* b_out = (const float*)d_in[3];
    float* y = (float*)d_out;

    void *p_xh, *p_xl, *p_wqh, *p_wql, *p_woh, *p_wol, *p_aoh, *p_aol;
    cudaGetSymbolAddress(&p_xh, g_xh);
    cudaGetSymbolAddress(&p_xl, g_xl);
    cudaGetSymbolAddress(&p_wqh, g_wqh);
    cudaGetSymbolAddress(&p_wql, g_wql);
    cudaGetSymbolAddress(&p_woh, g_woh);
    cudaGetSymbolAddress(&p_wol, g_wol);
    cudaGetSymbolAddress(&p_aoh, g_aoh);
    cudaGetSymbolAddress(&p_aol, g_aol);

    const int GEMM_SMEM = 2 * 4 * GAS * 2;   // 81,920 B
    const int ATTN_SMEM = 2 * 4 * ARR * 2;   // 73,728 B
    cudaFuncSetAttribute(mma_gemm<0>, cudaFuncAttributeMaxDynamicSharedMemorySize, GEMM_SMEM);
    cudaFuncSetAttribute(mma_gemm<1>, cudaFuncAttributeMaxDynamicSharedMemorySize, GEMM_SMEM);
    cudaFuncSetAttribute(attn_mma_kernel, cudaFuncAttributeMaxDynamicSharedMemorySize, ATTN_SMEM);

    {
        int n4 = (BB * TT * DIMD) / 4;
        split_kernel<<<(n4 + 255) / 256, 256>>>(x, (__nv_bfloat16*)p_xh, (__nv_bfloat16*)p_xl, n4);
    }
    {
        int n4 = (NQKV * DIMD) / 4;
        split_kernel<<<(n4 + 255) / 256, 256>>>(w_qkv, (__nv_bfloat16*)p_wqh, (__nv_bfloat16*)p_wql, n4);
    }
    {
        int n4 = (DIMD * DIMD) / 4;
        split_kernel<<<(n4 + 255) / 256, 256>>>(w_out, (__nv_bfloat16*)p_woh, (__nv_bfloat16*)p_wol, n4);
    }

    {
        dim3 g(NQKV / 128, (BB * TT) / 128);
        mma_gemm<0><<<g, 256, GEMM_SMEM>>>((__nv_bfloat16*)p_xh, (__nv_bfloat16*)p_xl,
                                           (__nv_bfloat16*)p_wqh, (__nv_bfloat16*)p_wql,
                                           nullptr, nullptr);
    }

    attn_mma_kernel<<<BB * HH * (TT / 128), 256, ATTN_SMEM>>>();

    {
        dim3 g(DIMD / 128, (BB * TT) / 128);
        mma_gemm<1><<<g, 256, GEMM_SMEM>>>((__nv_bfloat16*)p_aoh, (__nv_bfloat16*)p_aol,
                                           (__nv_bfloat16*)p_woh, (__nv_bfloat16*)p_wol,
                                           b_out, y);
    }
}

// round 8
// speedup vs baseline: 2.7276x; 1.0048x over previous
#include <cuda_runtime.h>
#include <cuda_bf16.h>
#include <math.h>
#include <stdint.h>

#define BB 4
#define TT 2048
#define DIMD 1024
#define HH 16
#define DHD 64
#define NQKV 3072
#define KDIM 1024
#define ROWPAD 40   /* gemm smem row pad (bf16) */
#define APAD 72     /* attention smem row pad (bf16) */
#define EXP_C 0.045084439f  /* (1/32) * log2(e) */

// ---------------------------------------------------------------------------
// Device-global scratch
// ---------------------------------------------------------------------------
__device__ __nv_bfloat16 g_qh[BB * HH * TT * DHD];
__device__ __nv_bfloat16 g_ql[BB * HH * TT * DHD];
__device__ __nv_bfloat16 g_kh[BB * HH * TT * DHD];
__device__ __nv_bfloat16 g_kl[BB * HH * TT * DHD];
__device__ __nv_bfloat16 g_vh[BB * HH * TT * DHD];
__device__ __nv_bfloat16 g_vl[BB * HH * TT * DHD];

__device__ __nv_bfloat16 g_xh[BB * TT * DIMD];
__device__ __nv_bfloat16 g_xl[BB * TT * DIMD];
__device__ __nv_bfloat16 g_wqh[NQKV * DIMD];
__device__ __nv_bfloat16 g_wql[NQKV * DIMD];
__device__ __nv_bfloat16 g_woh[DIMD * DIMD];
__device__ __nv_bfloat16 g_wol[DIMD * DIMD];
__device__ __nv_bfloat16 g_aoh[BB * TT * DIMD];
__device__ __nv_bfloat16 g_aol[BB * TT * DIMD];

// ---------------------------------------------------------------------------
// Standard-PTX helpers (compute_103-safe)
// ---------------------------------------------------------------------------
__device__ __forceinline__ uint32_t smem_u32(const void* p) {
    uint32_t a;
    asm("{ .reg .u64 t; cvta.to.shared.u64 t, %1; cvt.u32.u64 %0, t; }" : "=r"(a) : "l"(p));
    return a;
}
__device__ __forceinline__ void cp16(uint32_t dst, const void* src) {
    asm volatile("cp.async.cg.shared.global [%0], [%1], 16;" :: "r"(dst), "l"(src));
}
#define CP_COMMIT() asm volatile("cp.async.commit_group;" ::: "memory")
#define CP_WAIT1()  asm volatile("cp.async.wait_group 1;" ::: "memory")
#define CP_WAIT0()  asm volatile("cp.async.wait_group 0;" ::: "memory")

__device__ __forceinline__ void ldm_x4(uint32_t* r, uint32_t addr) {
    asm volatile("ldmatrix.sync.aligned.m8n8.x4.shared.b16 {%0,%1,%2,%3}, [%4];"
                 : "=r"(r[0]), "=r"(r[1]), "=r"(r[2]), "=r"(r[3]) : "r"(addr));
}
__device__ __forceinline__ void ldm_x4_trans(uint32_t* r, uint32_t addr) {
    asm volatile("ldmatrix.sync.aligned.m8n8.x4.trans.shared.b16 {%0,%1,%2,%3}, [%4];"
                 : "=r"(r[0]), "=r"(r[1]), "=r"(r[2]), "=r"(r[3]) : "r"(addr));
}
__device__ __forceinline__ void mma16816(float* d, const uint32_t* a, const uint32_t* b) {
    asm volatile(
        "mma.sync.aligned.m16n8k16.row.col.f32.bf16.bf16.f32 "
        "{%0,%1,%2,%3}, {%4,%5,%6,%7}, {%8,%9}, {%0,%1,%2,%3};"
        : "+f"(d[0]), "+f"(d[1]), "+f"(d[2]), "+f"(d[3])
        : "r"(a[0]), "r"(a[1]), "r"(a[2]), "r"(a[3]), "r"(b[0]), "r"(b[1]));
}
__device__ __forceinline__ uint32_t pack_bf16x2(float lo, float hi) {
    uint32_t r;
    asm("cvt.rn.satfinite.bf16x2.f32 %0, %1, %2;" : "=r"(r) : "f"(hi), "f"(lo));
    return r;
}
__device__ __forceinline__ float fexp2(float x) {
    float r;
    asm("ex2.approx.ftz.f32 %0, %1;" : "=f"(r) : "f"(x));
    return r;
}

// ---------------------------------------------------------------------------
// fp32 -> (bf16 hi, bf16 lo) split pre-pass
// ---------------------------------------------------------------------------
__global__ __launch_bounds__(256) void split_kernel(const float* __restrict__ s,
                                                    __nv_bfloat16* __restrict__ h,
                                                    __nv_bfloat16* __restrict__ l,
                                                    int n4) {
    int i = blockIdx.x * blockDim.x + threadIdx.x;
    if (i >= n4) return;
    float4 v = ((const float4*)s)[i];
    uint2 hp, lp;
    hp.x = pack_bf16x2(v.x, v.y);
    hp.y = pack_bf16x2(v.z, v.w);
    lp.x = pack_bf16x2(v.x - __uint_as_float(hp.x << 16),
                       v.y - __uint_as_float(hp.x & 0xffff0000u));
    lp.y = pack_bf16x2(v.z - __uint_as_float(hp.y << 16),
                       v.w - __uint_as_float(hp.y & 0xffff0000u));
    ((uint2*)h)[i] = hp;
    ((uint2*)l)[i] = lp;
}

// ---------------------------------------------------------------------------
// HMMA bf16x3 GEMM, cp.async double-buffered, PASS-MAJOR MMA order.
// ---------------------------------------------------------------------------
#define GAS (128 * ROWPAD)

template <int EPI>
__global__ __launch_bounds__(256, 2) void mma_gemm(const __nv_bfloat16* __restrict__ Ahp,
                                                   const __nv_bfloat16* __restrict__ Alp,
                                                   const __nv_bfloat16* __restrict__ Bhp,
                                                   const __nv_bfloat16* __restrict__ Blp,
                                                   const float* __restrict__ bias,
                                                   float* __restrict__ out) {
    extern __shared__ __nv_bfloat16 dsm[];
    const uint32_t aD = smem_u32(dsm);

    const int tid = threadIdx.x;
    const int wid = tid >> 5;
    const int lane = tid & 31;
    const int warp_m = wid & 1;
    const int warp_n = wid >> 1;
    const int m0 = blockIdx.y * 128;
    const int n0 = blockIdx.x * 128;

    const __nv_bfloat16* srcs[4] = {
        Ahp + (size_t)m0 * KDIM, Alp + (size_t)m0 * KDIM,
        Bhp + (size_t)n0 * KDIM, Blp + (size_t)n0 * KDIM};

    const int ld_row = tid >> 2;
    const int ld_seg = tid & 3;

    const int a_row_base = warp_m * 64 + (lane & 15);
    const int a_colsel = (lane >> 4) * 8;
    const int b_row_base = warp_n * 32 + ((lane >> 4) & 1) * 8 + (lane & 7);
    const int b_colsel = ((lane >> 3) & 1) * 8;

    float acc[4][4][4];
#pragma unroll
    for (int mi = 0; mi < 4; mi++)
#pragma unroll
        for (int ni = 0; ni < 4; ni++)
#pragma unroll
            for (int e = 0; e < 4; e++) acc[mi][ni][e] = 0.0f;

    auto issue = [&](int c, int s) {
        const int k0 = c * 32;
        const uint32_t sb = aD + (uint32_t)s * (4 * GAS * 2);
#pragma unroll
        for (int a = 0; a < 4; a++) {
#pragma unroll
            for (int i = 0; i < 2; i++) {
                int row = ld_row + i * 64;
                cp16(sb + (uint32_t)(a * GAS + row * ROWPAD + ld_seg * 8) * 2,
                     srcs[a] + (size_t)row * KDIM + k0 + ld_seg * 8);
            }
        }
        CP_COMMIT();
    };

    issue(0, 0);

    for (int c = 0; c < 32; c++) {
        if (c + 1 < 32) { issue(c + 1, (c + 1) & 1); CP_WAIT1(); }
        else           { CP_WAIT0(); }
        __syncthreads();

        const uint32_t sb = aD + (uint32_t)(c & 1) * (4 * GAS * 2);
        const uint32_t aAh = sb;
        const uint32_t aAl = sb + GAS * 2;
        const uint32_t aBh = sb + 2 * GAS * 2;
        const uint32_t aBl = sb + 3 * GAS * 2;

#pragma unroll
        for (int kk = 0; kk < 2; kk++) {
            const int acol = kk * 16 + a_colsel;
            const int bcol = kk * 16 + b_colsel;

            uint32_t fa[4][4];
            uint32_t fbh[4][2];
            uint32_t fbl[4][2];

#pragma unroll
            for (int mi = 0; mi < 4; mi++)
                ldm_x4(fa[mi], aAh + ((a_row_base + mi * 16) * ROWPAD + acol) * 2);
#pragma unroll
            for (int ni2 = 0; ni2 < 2; ni2++) {
                const uint32_t boff = ((b_row_base + ni2 * 16) * ROWPAD + bcol) * 2;
                ldm_x4(&fbh[ni2 * 2][0], aBh + boff);
                ldm_x4(&fbl[ni2 * 2][0], aBl + boff);
            }

            // PASS-MAJOR: reuse distance = 16 MMAs per accumulator
#pragma unroll
            for (int mi = 0; mi < 4; mi++)
#pragma unroll
                for (int ni = 0; ni < 4; ni++) mma16816(acc[mi][ni], fa[mi], fbh[ni]);
#pragma unroll
            for (int mi = 0; mi < 4; mi++)
#pragma unroll
                for (int ni = 0; ni < 4; ni++) mma16816(acc[mi][ni], fa[mi], fbl[ni]);
#pragma unroll
            for (int mi = 0; mi < 4; mi++)
                ldm_x4(fa[mi], aAl + ((a_row_base + mi * 16) * ROWPAD + acol) * 2);
#pragma unroll
            for (int mi = 0; mi < 4; mi++)
#pragma unroll
                for (int ni = 0; ni < 4; ni++) mma16816(acc[mi][ni], fa[mi], fbh[ni]);
        }
        __syncthreads();
    }

    const int r0 = lane >> 2;
    const int c0 = (lane & 3) * 2;
#pragma unroll
    for (int mi = 0; mi < 4; mi++) {
#pragma unroll
        for (int half = 0; half < 2; half++) {
            const int m = m0 + warp_m * 64 + mi * 16 + r0 + half * 8;
            if (EPI == 0) {
                const int b = m >> 11;
                const int t = m & (TT - 1);
                const size_t mbase = ((size_t)b * HH) * TT;
#pragma unroll
                for (int ni = 0; ni < 4; ni++) {
#pragma unroll
                    for (int e = 0; e < 2; e++) {
                        int o = n0 + warp_n * 32 + ni * 8 + c0 + e;
                        float v = acc[mi][ni][half * 2 + e];
                        int d = o / 48;
                        int rem = o - d * 48;
                        int kq = rem >> 4;
                        int h = rem & 15;
                        __nv_bfloat16* dh = (kq == 0) ? g_qh : (kq == 1) ? g_kh : g_vh;
                        __nv_bfloat16* dl = (kq == 0) ? g_ql : (kq == 1) ? g_kl : g_vl;
                        size_t idx = ((mbase + (size_t)h * TT) + t) * DHD + d;
                        __nv_bfloat16 hi = __float2bfloat16(v);
                        dh[idx] = hi;
                        dl[idx] = __float2bfloat16(v - __bfloat162float(hi));
                    }
                }
            } else {
#pragma unroll
                for (int ni = 0; ni < 4; ni++) {
#pragma unroll
                    for (int e = 0; e < 2; e++) {
                        int o = n0 + warp_n * 32 + ni * 8 + c0 + e;
                        out[(size_t)m * DIMD + o] = acc[mi][ni][half * 2 + e] + bias[o];
                    }
                }
            }
        }
    }
}

// ---------------------------------------------------------------------------
// HMMA flash attention, nt2-PAIRED MMA scheduling (4 independent accs in flight)
// ---------------------------------------------------------------------------
#define ARR (64 * APAD)

__global__ __launch_bounds__(256, 2) void attn_mma_kernel() {
    extern __shared__ __nv_bfloat16 dsm[];
    const uint32_t aD = smem_u32(dsm);

    const int tid = threadIdx.x;
    const int w = tid >> 5;
    const int lane = tid & 31;
    const int bh = blockIdx.x >> 4;
    const int rb = blockIdx.x & 15;
    const int b = bh >> 4;
    const int h = bh & 15;
    const int row0 = rb * 128;

    const __nv_bfloat16* Qh = g_qh + (size_t)bh * TT * DHD;
    const __nv_bfloat16* Ql = g_ql + (size_t)bh * TT * DHD;
    const __nv_bfloat16* Kh = g_kh + (size_t)bh * TT * DHD;
    const __nv_bfloat16* Kl = g_kl + (size_t)bh * TT * DHD;
    const __nv_bfloat16* Vh = g_vh + (size_t)bh * TT * DHD;
    const __nv_bfloat16* Vl = g_vl + (size_t)bh * TT * DHD;

    // ---- stage Q hi/lo into smem, build register fragments ----
#pragma unroll
    for (int i = 0; i < 4; i++) {
        int idx = tid + i * 256;
        int r = idx >> 3;
        int sg = idx & 7;
        *(uint4*)&dsm[r * APAD + sg * 8] =
            *(const uint4*)(Qh + (size_t)(row0 + r) * DHD + sg * 8);
        *(uint4*)&dsm[(128 + r) * APAD + sg * 8] =
            *(const uint4*)(Ql + (size_t)(row0 + r) * DHD + sg * 8);
    }
    __syncthreads();

    uint32_t qh[4][4], ql[4][4];
    {
        const uint32_t qrow = w * 16 + (lane & 15);
        const uint32_t qcol = (lane >> 4) * 8;
#pragma unroll
        for (int ks = 0; ks < 4; ks++) {
            ldm_x4(qh[ks], aD + (qrow * APAD + ks * 16 + qcol) * 2);
            ldm_x4(ql[ks], aD + ((qrow + 128) * APAD + ks * 16 + qcol) * 2);
        }
    }
    __syncthreads();

    const int ld_row = tid >> 2;
    const int ld_seg = tid & 3;

    auto issue = [&](int kt, int s) {
        const size_t goff = (size_t)kt * 64 * DHD;
        const uint32_t sb = aD + (uint32_t)s * (4 * ARR * 2);
        const __nv_bfloat16* srcs[4] = {Kh + goff, Kl + goff, Vh + goff, Vl + goff};
#pragma unroll
        for (int a = 0; a < 4; a++) {
#pragma unroll
            for (int i = 0; i < 2; i++) {
                int sg = ld_seg + i * 4;
                cp16(sb + (uint32_t)(a * ARR + ld_row * APAD + sg * 8) * 2,
                     srcs[a] + (size_t)ld_row * DHD + sg * 8);
            }
        }
        CP_COMMIT();
    };

    float accO[8][4];
#pragma unroll
    for (int nt = 0; nt < 8; nt++)
#pragma unroll
        for (int e = 0; e < 4; e++) accO[nt][e] = 0.0f;

    float M0 = -1e30f, M1 = -1e30f;
    float L0 = 0.0f, L1 = 0.0f;

    issue(0, 0);

    const uint32_t k_rowl = ((lane >> 4) & 1) * 8 + (lane & 7);
    const uint32_t k_coll = ((lane >> 3) & 1) * 8;
    const uint32_t v_rowl = ((lane >> 3) & 1) * 8 + (lane & 7);
    const uint32_t v_coll = ((lane >> 4) & 1) * 8;

    for (int kt = 0; kt < TT / 64; kt++) {
        if (kt + 1 < TT / 64) { issue(kt + 1, (kt + 1) & 1); CP_WAIT1(); }
        else                  { CP_WAIT0(); }
        __syncthreads();

        const uint32_t sb = aD + (uint32_t)(kt & 1) * (4 * ARR * 2);
        const uint32_t aKh = sb;
        const uint32_t aKl = sb + ARR * 2;
        const uint32_t aVh = sb + 2 * ARR * 2;
        const uint32_t aVl = sb + 3 * ARR * 2;

        // ---- S = Q K^T: nt2-pairs, 12 MMAs over 4 independent accs per ks ----
        float accS[8][4];
#pragma unroll
        for (int nt = 0; nt < 8; nt++)
#pragma unroll
            for (int e = 0; e < 4; e++) accS[nt][e] = 0.0f;

#pragma unroll
        for (int np = 0; np < 2; np++) {
            float* a0 = accS[4 * np + 0];
            float* a1 = accS[4 * np + 1];
            float* a2 = accS[4 * np + 2];
            float* a3 = accS[4 * np + 3];
            const uint32_t krowA = (2 * np) * 16 + k_rowl;
            const uint32_t krowB = (2 * np + 1) * 16 + k_rowl;
#pragma unroll
            for (int ks = 0; ks < 4; ks++) {
                uint32_t kha[4], kla[4], khb[4], klb[4];
                const uint32_t offA = (krowA * APAD + ks * 16 + k_coll) * 2;
                const uint32_t offB = (krowB * APAD + ks * 16 + k_coll) * 2;
                ldm_x4(kha, aKh + offA);
                ldm_x4(khb, aKh + offB);
                ldm_x4(kla, aKl + offA);
                ldm_x4(klb, aKl + offB);
                mma16816(a0, qh[ks], &kha[0]);
                mma16816(a1, qh[ks], &kha[2]);
                mma16816(a2, qh[ks], &khb[0]);
                mma16816(a3, qh[ks], &khb[2]);
                mma16816(a0, qh[ks], &kla[0]);
                mma16816(a1, qh[ks], &kla[2]);
                mma16816(a2, qh[ks], &klb[0]);
                mma16816(a3, qh[ks], &klb[2]);
                mma16816(a0, ql[ks], &kha[0]);
                mma16816(a1, ql[ks], &kha[2]);
                mma16816(a2, ql[ks], &khb[0]);
                mma16816(a3, ql[ks], &khb[2]);
            }
        }

        // ---- online softmax ----
        float vm0 = accS[0][0], vm1 = accS[0][2];
#pragma unroll
        for (int nt = 0; nt < 8; nt++) {
            vm0 = fmaxf(vm0, fmaxf(accS[nt][0], accS[nt][1]));
            vm1 = fmaxf(vm1, fmaxf(accS[nt][2], accS[nt][3]));
        }
        vm0 = fmaxf(vm0, __shfl_xor_sync(0xffffffffu, vm0, 1));
        vm0 = fmaxf(vm0, __shfl_xor_sync(0xffffffffu, vm0, 2));
        vm1 = fmaxf(vm1, __shfl_xor_sync(0xffffffffu, vm1, 1));
        vm1 = fmaxf(vm1, __shfl_xor_sync(0xffffffffu, vm1, 2));

        const float Mn0 = fmaxf(M0, vm0);
        const float Mn1 = fmaxf(M1, vm1);
        const float corr0 = fexp2((M0 - Mn0) * EXP_C);
        const float corr1 = fexp2((M1 - Mn1) * EXP_C);
        M0 = Mn0; M1 = Mn1;
        const float mc0 = M0 * EXP_C;
        const float mc1 = M1 * EXP_C;

        float sp0 = 0.0f, sp1 = 0.0f;
#pragma unroll
        for (int nt = 0; nt < 8; nt++) {
            accS[nt][0] = fexp2(fmaf(accS[nt][0], EXP_C, -mc0));
            accS[nt][1] = fexp2(fmaf(accS[nt][1], EXP_C, -mc0));
            accS[nt][2] = fexp2(fmaf(accS[nt][2], EXP_C, -mc1));
            accS[nt][3] = fexp2(fmaf(accS[nt][3], EXP_C, -mc1));
            sp0 += accS[nt][0] + accS[nt][1];
            sp1 += accS[nt][2] + accS[nt][3];
        }
        sp0 += __shfl_xor_sync(0xffffffffu, sp0, 1);
        sp0 += __shfl_xor_sync(0xffffffffu, sp0, 2);
        sp1 += __shfl_xor_sync(0xffffffffu, sp1, 1);
        sp1 += __shfl_xor_sync(0xffffffffu, sp1, 2);
        L0 = L0 * corr0 + sp0;
        L1 = L1 * corr1 + sp1;

#pragma unroll
        for (int nt = 0; nt < 8; nt++) {
            accO[nt][0] *= corr0; accO[nt][1] *= corr0;
            accO[nt][2] *= corr1; accO[nt][3] *= corr1;
        }

        // ---- O += P V: nt2-pairs, 12 MMAs over 4 independent accs ----
#pragma unroll
        for (int kc = 0; kc < 4; kc++) {
            uint32_t ph[4], pl[4];
#pragma unroll
            for (int half = 0; half < 2; half++) {
                const int nt = 2 * kc + half;
                uint32_t h0 = pack_bf16x2(accS[nt][0], accS[nt][1]);
                uint32_t h1 = pack_bf16x2(accS[nt][2], accS[nt][3]);
                ph[half * 2 + 0] = h0;
                ph[half * 2 + 1] = h1;
                float f0 = __uint_as_float(h0 << 16);
                float f1 = __uint_as_float(h0 & 0xffff0000u);
                float f2 = __uint_as_float(h1 << 16);
                float f3 = __uint_as_float(h1 & 0xffff0000u);
                pl[half * 2 + 0] = pack_bf16x2(accS[nt][0] - f0, accS[nt][1] - f1);
                pl[half * 2 + 1] = pack_bf16x2(accS[nt][2] - f2, accS[nt][3] - f3);
            }
            const uint32_t vrow = kc * 16 + v_rowl;
#pragma unroll
            for (int np = 0; np < 2; np++) {
                float* o0 = accO[4 * np + 0];
                float* o1 = accO[4 * np + 1];
                float* o2 = accO[4 * np + 2];
                float* o3 = accO[4 * np + 3];
                uint32_t vha[4], vla[4], vhb[4], vlb[4];
                const uint32_t offA = (vrow * APAD + (2 * np) * 16 + v_coll) * 2;
                const uint32_t offB = (vrow * APAD + (2 * np + 1) * 16 + v_coll) * 2;
                ldm_x4_trans(vha, aVh + offA);
                ldm_x4_trans(vhb, aVh + offB);
                ldm_x4_trans(vla, aVl + offA);
                ldm_x4_trans(vlb, aVl + offB);
                mma16816(o0, ph, &vha[0]);
                mma16816(o1, ph, &vha[2]);
                mma16816(o2, ph, &vhb[0]);
                mma16816(o3, ph, &vhb[2]);
                mma16816(o0, ph, &vla[0]);
                mma16816(o1, ph, &vla[2]);
                mma16816(o2, ph, &vlb[0]);
                mma16816(o3, ph, &vlb[2]);
                mma16816(o0, pl, &vha[0]);
                mma16816(o1, pl, &vha[2]);
                mma16816(o2, pl, &vhb[0]);
                mma16816(o3, pl, &vhb[2]);
            }
        }
        __syncthreads();
    }

    // ---- epilogue: normalize, split to bf16 hi/lo ----
    const float i0 = 1.0f / L0;
    const float i1 = 1.0f / L1;
    const int r = lane >> 2;
    const int c = (lane & 3) * 2;
    const int row = row0 + w * 16 + r;
    const size_t base0 = ((size_t)b * TT + row) * DIMD + h * DHD + c;
    const size_t base1 = base0 + 8 * DIMD;
#pragma unroll
    for (int nt = 0; nt < 8; nt++) {
        float a0 = accO[nt][0] * i0, a1 = accO[nt][1] * i0;
        float b0 = accO[nt][2] * i1, b1 = accO[nt][3] * i1;
        uint32_t h0 = pack_bf16x2(a0, a1);
        uint32_t h1 = pack_bf16x2(b0, b1);
        uint32_t l0 = pack_bf16x2(a0 - __uint_as_float(h0 << 16),
                                  a1 - __uint_as_float(h0 & 0xffff0000u));
        uint32_t l1 = pack_bf16x2(b0 - __uint_as_float(h1 << 16),
                                  b1 - __uint_as_float(h1 & 0xffff0000u));
        *(uint32_t*)(g_aoh + base0 + nt * 8) = h0;
        *(uint32_t*)(g_aol + base0 + nt * 8) = l0;
        *(uint32_t*)(g_aoh + base1 + nt * 8) = h1;
        *(uint32_t*)(g_aol + base1 + nt * 8) = l1;
    }
}

// ---------------------------------------------------------------------------
extern "C" void kernel_launch(void* const* d_in, const int* in_sizes, int n_in,
                              void* d_out, int out_size) {
    const float* x     = (const float*)d_in[0];
    const float* w_qkv = (const float*)d_in[1];
    const float* w_out = (const float*)d_in[2];
    const float* b_out = (const float*)d_in[3];
    float* y = (float*)d_out;

    void *p_xh, *p_xl, *p_wqh, *p_wql, *p_woh, *p_wol, *p_aoh, *p_aol;
    cudaGetSymbolAddress(&p_xh, g_xh);
    cudaGetSymbolAddress(&p_xl, g_xl);
    cudaGetSymbolAddress(&p_wqh, g_wqh);
    cudaGetSymbolAddress(&p_wql, g_wql);
    cudaGetSymbolAddress(&p_woh, g_woh);
    cudaGetSymbolAddress(&p_wol, g_wol);
    cudaGetSymbolAddress(&p_aoh, g_aoh);
    cudaGetSymbolAddress(&p_aol, g_aol);

    const int GEMM_SMEM = 2 * 4 * GAS * 2;   // 81,920 B
    const int ATTN_SMEM = 2 * 4 * ARR * 2;   // 73,728 B
    cudaFuncSetAttribute(mma_gemm<0>, cudaFuncAttributeMaxDynamicSharedMemorySize, GEMM_SMEM);
    cudaFuncSetAttribute(mma_gemm<1>, cudaFuncAttributeMaxDynamicSharedMemorySize, GEMM_SMEM);
    cudaFuncSetAttribute(attn_mma_kernel, cudaFuncAttributeMaxDynamicSharedMemorySize, ATTN_SMEM);

    {
        int n4 = (BB * TT * DIMD) / 4;
        split_kernel<<<(n4 + 255) / 256, 256>>>(x, (__nv_bfloat16*)p_xh, (__nv_bfloat16*)p_xl, n4);
    }
    {
        int n4 = (NQKV * DIMD) / 4;
        split_kernel<<<(n4 + 255) / 256, 256>>>(w_qkv, (__nv_bfloat16*)p_wqh, (__nv_bfloat16*)p_wql, n4);
    }
    {
        int n4 = (DIMD * DIMD) / 4;
        split_kernel<<<(n4 + 255) / 256, 256>>>(w_out, (__nv_bfloat16*)p_woh, (__nv_bfloat16*)p_wol, n4);
    }

    {
        dim3 g(NQKV / 128, (BB * TT) / 128);
        mma_gemm<0><<<g, 256, GEMM_SMEM>>>((__nv_bfloat16*)p_xh, (__nv_bfloat16*)p_xl,
                                           (__nv_bfloat16*)p_wqh, (__nv_bfloat16*)p_wql,
                                           nullptr, nullptr);
    }

    attn_mma_kernel<<<BB * HH * (TT / 128), 256, ATTN_SMEM>>>();

    {
        dim3 g(DIMD / 128, (BB * TT) / 128);
        mma_gemm<1><<<g, 256, GEMM_SMEM>>>((__nv_bfloat16*)p_aoh, (__nv_bfloat16*)p_aol,
                                           (__nv_bfloat16*)p_woh, (__nv_bfloat16*)p_wol,
                                           b_out, y);
    }
}

// round 9
// speedup vs baseline: 2.8043x; 1.0281x over previous
#include <cuda_runtime.h>
#include <cuda_bf16.h>
#include <math.h>
#include <stdint.h>

#define BB 4
#define TT 2048
#define DIMD 1024
#define HH 16
#define DHD 64
#define NQKV 3072
#define KDIM 1024
#define ROWPAD 40   /* gemm smem row pad (bf16) */
#define APAD 72     /* attention smem row pad (bf16) */
#define EXP_C 0.045084439f  /* (1/32) * log2(e) */

// ---------------------------------------------------------------------------
// Device-global scratch
// ---------------------------------------------------------------------------
__device__ __nv_bfloat16 g_qh[BB * HH * TT * DHD];
__device__ __nv_bfloat16 g_ql[BB * HH * TT * DHD];
__device__ __nv_bfloat16 g_kh[BB * HH * TT * DHD];
__device__ __nv_bfloat16 g_kl[BB * HH * TT * DHD];
__device__ __nv_bfloat16 g_vh[BB * HH * TT * DHD];
__device__ __nv_bfloat16 g_vl[BB * HH * TT * DHD];

__device__ __nv_bfloat16 g_xh[BB * TT * DIMD];
__device__ __nv_bfloat16 g_xl[BB * TT * DIMD];
__device__ __nv_bfloat16 g_wqh[NQKV * DIMD];
__device__ __nv_bfloat16 g_wql[NQKV * DIMD];
__device__ __nv_bfloat16 g_woh[DIMD * DIMD];
__device__ __nv_bfloat16 g_wol[DIMD * DIMD];
__device__ __nv_bfloat16 g_aoh[BB * TT * DIMD];
__device__ __nv_bfloat16 g_aol[BB * TT * DIMD];

// ---------------------------------------------------------------------------
// Standard-PTX helpers (compute_103-safe)
// ---------------------------------------------------------------------------
__device__ __forceinline__ uint32_t smem_u32(const void* p) {
    uint32_t a;
    asm("{ .reg .u64 t; cvta.to.shared.u64 t, %1; cvt.u32.u64 %0, t; }" : "=r"(a) : "l"(p));
    return a;
}
__device__ __forceinline__ void cp16(uint32_t dst, const void* src) {
    asm volatile("cp.async.cg.shared.global [%0], [%1], 16;" :: "r"(dst), "l"(src));
}
#define CP_COMMIT() asm volatile("cp.async.commit_group;" ::: "memory")
#define CP_WAIT0()  asm volatile("cp.async.wait_group 0;" ::: "memory")

__device__ __forceinline__ void ldm_x4(uint32_t* r, uint32_t addr) {
    asm volatile("ldmatrix.sync.aligned.m8n8.x4.shared.b16 {%0,%1,%2,%3}, [%4];"
                 : "=r"(r[0]), "=r"(r[1]), "=r"(r[2]), "=r"(r[3]) : "r"(addr));
}
__device__ __forceinline__ void ldm_x4_trans(uint32_t* r, uint32_t addr) {
    asm volatile("ldmatrix.sync.aligned.m8n8.x4.trans.shared.b16 {%0,%1,%2,%3}, [%4];"
                 : "=r"(r[0]), "=r"(r[1]), "=r"(r[2]), "=r"(r[3]) : "r"(addr));
}
__device__ __forceinline__ void mma16816(float* d, const uint32_t* a, const uint32_t* b) {
    asm volatile(
        "mma.sync.aligned.m16n8k16.row.col.f32.bf16.bf16.f32 "
        "{%0,%1,%2,%3}, {%4,%5,%6,%7}, {%8,%9}, {%0,%1,%2,%3};"
        : "+f"(d[0]), "+f"(d[1]), "+f"(d[2]), "+f"(d[3])
        : "r"(a[0]), "r"(a[1]), "r"(a[2]), "r"(a[3]), "r"(b[0]), "r"(b[1]));
}
__device__ __forceinline__ uint32_t pack_bf16x2(float lo, float hi) {
    uint32_t r;
    asm("cvt.rn.satfinite.bf16x2.f32 %0, %1, %2;" : "=r"(r) : "f"(hi), "f"(lo));
    return r;
}
__device__ __forceinline__ float fexp2(float x) {
    float r;
    asm("ex2.approx.ftz.f32 %0, %1;" : "=f"(r) : "f"(x));
    return r;
}

// ---------------------------------------------------------------------------
// fp32 -> (bf16 hi, bf16 lo) split pre-pass
// ---------------------------------------------------------------------------
__global__ __launch_bounds__(256) void split_kernel(const float* __restrict__ s,
                                                    __nv_bfloat16* __restrict__ h,
                                                    __nv_bfloat16* __restrict__ l,
                                                    int n4) {
    int i = blockIdx.x * blockDim.x + threadIdx.x;
    if (i >= n4) return;
    float4 v = ((const float4*)s)[i];
    uint2 hp, lp;
    hp.x = pack_bf16x2(v.x, v.y);
    hp.y = pack_bf16x2(v.z, v.w);
    lp.x = pack_bf16x2(v.x - __uint_as_float(hp.x << 16),
                       v.y - __uint_as_float(hp.x & 0xffff0000u));
    lp.y = pack_bf16x2(v.z - __uint_as_float(hp.y << 16),
                       v.w - __uint_as_float(hp.y & 0xffff0000u));
    ((uint2*)h)[i] = hp;
    ((uint2*)l)[i] = lp;
}

// ---------------------------------------------------------------------------
// HMMA bf16x3 GEMM, cp.async double-buffered, SINGLE barrier per chunk.
// ---------------------------------------------------------------------------
#define GAS (128 * ROWPAD)

template <int EPI>
__global__ __launch_bounds__(256, 2) void mma_gemm(const __nv_bfloat16* __restrict__ Ahp,
                                                   const __nv_bfloat16* __restrict__ Alp,
                                                   const __nv_bfloat16* __restrict__ Bhp,
                                                   const __nv_bfloat16* __restrict__ Blp,
                                                   const float* __restrict__ bias,
                                                   float* __restrict__ out) {
    extern __shared__ __nv_bfloat16 dsm[];
    const uint32_t aD = smem_u32(dsm);

    const int tid = threadIdx.x;
    const int wid = tid >> 5;
    const int lane = tid & 31;
    const int warp_m = wid & 1;
    const int warp_n = wid >> 1;
    const int m0 = blockIdx.y * 128;
    const int n0 = blockIdx.x * 128;

    const __nv_bfloat16* srcs[4] = {
        Ahp + (size_t)m0 * KDIM, Alp + (size_t)m0 * KDIM,
        Bhp + (size_t)n0 * KDIM, Blp + (size_t)n0 * KDIM};

    const int ld_row = tid >> 2;
    const int ld_seg = tid & 3;

    const int a_row_base = warp_m * 64 + (lane & 15);
    const int a_colsel = (lane >> 4) * 8;
    const int b_row_base = warp_n * 32 + ((lane >> 4) & 1) * 8 + (lane & 7);
    const int b_colsel = ((lane >> 3) & 1) * 8;

    float acc[4][4][4];
#pragma unroll
    for (int mi = 0; mi < 4; mi++)
#pragma unroll
        for (int ni = 0; ni < 4; ni++)
#pragma unroll
            for (int e = 0; e < 4; e++) acc[mi][ni][e] = 0.0f;

    auto issue = [&](int c, int s) {
        const int k0 = c * 32;
        const uint32_t sb = aD + (uint32_t)s * (4 * GAS * 2);
#pragma unroll
        for (int a = 0; a < 4; a++) {
#pragma unroll
            for (int i = 0; i < 2; i++) {
                int row = ld_row + i * 64;
                cp16(sb + (uint32_t)(a * GAS + row * ROWPAD + ld_seg * 8) * 2,
                     srcs[a] + (size_t)row * KDIM + k0 + ld_seg * 8);
            }
        }
        CP_COMMIT();
    };

    issue(0, 0);

    for (int c = 0; c < 32; c++) {
        CP_WAIT0();
        __syncthreads();
        if (c + 1 < 32) issue(c + 1, (c + 1) & 1);

        const uint32_t sb = aD + (uint32_t)(c & 1) * (4 * GAS * 2);
        const uint32_t aAh = sb;
        const uint32_t aAl = sb + GAS * 2;
        const uint32_t aBh = sb + 2 * GAS * 2;
        const uint32_t aBl = sb + 3 * GAS * 2;

#pragma unroll
        for (int kk = 0; kk < 2; kk++) {
            const int acol = kk * 16 + a_colsel;
            const int bcol = kk * 16 + b_colsel;

            uint32_t fa[4][4];
            uint32_t fbh[4][2];
            uint32_t fbl[4][2];

#pragma unroll
            for (int mi = 0; mi < 4; mi++)
                ldm_x4(fa[mi], aAh + ((a_row_base + mi * 16) * ROWPAD + acol) * 2);
#pragma unroll
            for (int ni2 = 0; ni2 < 2; ni2++) {
                const uint32_t boff = ((b_row_base + ni2 * 16) * ROWPAD + bcol) * 2;
                ldm_x4(&fbh[ni2 * 2][0], aBh + boff);
                ldm_x4(&fbl[ni2 * 2][0], aBl + boff);
            }

#pragma unroll
            for (int mi = 0; mi < 4; mi++)
#pragma unroll
                for (int ni = 0; ni < 4; ni++) mma16816(acc[mi][ni], fa[mi], fbh[ni]);
#pragma unroll
            for (int mi = 0; mi < 4; mi++)
#pragma unroll
                for (int ni = 0; ni < 4; ni++) mma16816(acc[mi][ni], fa[mi], fbl[ni]);
#pragma unroll
            for (int mi = 0; mi < 4; mi++)
                ldm_x4(fa[mi], aAl + ((a_row_base + mi * 16) * ROWPAD + acol) * 2);
#pragma unroll
            for (int mi = 0; mi < 4; mi++)
#pragma unroll
                for (int ni = 0; ni < 4; ni++) mma16816(acc[mi][ni], fa[mi], fbh[ni]);
        }
    }

    const int r0 = lane >> 2;
    const int c0 = (lane & 3) * 2;
#pragma unroll
    for (int mi = 0; mi < 4; mi++) {
#pragma unroll
        for (int half = 0; half < 2; half++) {
            const int m = m0 + warp_m * 64 + mi * 16 + r0 + half * 8;
            if (EPI == 0) {
                const int b = m >> 11;
                const int t = m & (TT - 1);
                const size_t mbase = ((size_t)b * HH) * TT;
#pragma unroll
                for (int ni = 0; ni < 4; ni++) {
#pragma unroll
                    for (int e = 0; e < 2; e++) {
                        int o = n0 + warp_n * 32 + ni * 8 + c0 + e;
                        float v = acc[mi][ni][half * 2 + e];
                        int d = o / 48;
                        int rem = o - d * 48;
                        int kq = rem >> 4;
                        int h = rem & 15;
                        __nv_bfloat16* dh = (kq == 0) ? g_qh : (kq == 1) ? g_kh : g_vh;
                        __nv_bfloat16* dl = (kq == 0) ? g_ql : (kq == 1) ? g_kl : g_vl;
                        size_t idx = ((mbase + (size_t)h * TT) + t) * DHD + d;
                        __nv_bfloat16 hi = __float2bfloat16(v);
                        dh[idx] = hi;
                        dl[idx] = __float2bfloat16(v - __bfloat162float(hi));
                    }
                }
            } else {
#pragma unroll
                for (int ni = 0; ni < 4; ni++) {
#pragma unroll
                    for (int e = 0; e < 2; e++) {
                        int o = n0 + warp_n * 32 + ni * 8 + c0 + e;
                        out[(size_t)m * DIMD + o] = acc[mi][ni][half * 2 + e] + bias[o];
                    }
                }
            }
        }
    }
}

// ---------------------------------------------------------------------------
// HMMA flash attention.
//  - Ql fragments sourced from a persistent smem region (kills reg spills)
//  - single __syncthreads per chunk
// smem layout (bf16 elems): stages 0,1: 4 arrays x ARR; then QL: 128 x APAD.
// ---------------------------------------------------------------------------
#define ARR (64 * APAD)
#define QLOFF (8 * ARR)
#define ATTN_ELEMS (8 * ARR + 128 * APAD)

__global__ __launch_bounds__(256, 2) void attn_mma_kernel() {
    extern __shared__ __nv_bfloat16 dsm[];
    const uint32_t aD = smem_u32(dsm);

    const int tid = threadIdx.x;
    const int w = tid >> 5;
    const int lane = tid & 31;
    const int bh = blockIdx.x >> 4;
    const int rb = blockIdx.x & 15;
    const int b = bh >> 4;
    const int h = bh & 15;
    const int row0 = rb * 128;

    const __nv_bfloat16* Qhp = g_qh + (size_t)bh * TT * DHD;
    const __nv_bfloat16* Qlp = g_ql + (size_t)bh * TT * DHD;
    const __nv_bfloat16* Khp = g_kh + (size_t)bh * TT * DHD;
    const __nv_bfloat16* Klp = g_kl + (size_t)bh * TT * DHD;
    const __nv_bfloat16* Vhp = g_vh + (size_t)bh * TT * DHD;
    const __nv_bfloat16* Vlp = g_vl + (size_t)bh * TT * DHD;

    // ---- stage: Qh -> stage0 scratch, Ql -> persistent QL region ----
#pragma unroll
    for (int i = 0; i < 4; i++) {
        int idx = tid + i * 256;
        int r = idx >> 3;
        int sg = idx & 7;
        *(uint4*)&dsm[r * APAD + sg * 8] =
            *(const uint4*)(Qhp + (size_t)(row0 + r) * DHD + sg * 8);
        *(uint4*)&dsm[QLOFF + r * APAD + sg * 8] =
            *(const uint4*)(Qlp + (size_t)(row0 + r) * DHD + sg * 8);
    }
    __syncthreads();

    const uint32_t qrow = w * 16 + (lane & 15);
    const uint32_t qcol = (lane >> 4) * 8;

    uint32_t qh[4][4];   // Qh fragments stay in registers
#pragma unroll
    for (int ks = 0; ks < 4; ks++)
        ldm_x4(qh[ks], aD + (qrow * APAD + ks * 16 + qcol) * 2);
    __syncthreads();   // all Qh reads done before cp.async overwrites stage0

    const int ld_row = tid >> 2;
    const int ld_seg = tid & 3;

    auto issue = [&](int kt, int s) {
        const size_t goff = (size_t)kt * 64 * DHD;
        const uint32_t sb = aD + (uint32_t)s * (4 * ARR * 2);
        const __nv_bfloat16* srcs[4] = {Khp + goff, Klp + goff, Vhp + goff, Vlp + goff};
#pragma unroll
        for (int a = 0; a < 4; a++) {
#pragma unroll
            for (int i = 0; i < 2; i++) {
                int sg = ld_seg + i * 4;
                cp16(sb + (uint32_t)(a * ARR + ld_row * APAD + sg * 8) * 2,
                     srcs[a] + (size_t)ld_row * DHD + sg * 8);
            }
        }
        CP_COMMIT();
    };

    float accO[8][4];
#pragma unroll
    for (int nt = 0; nt < 8; nt++)
#pragma unroll
        for (int e = 0; e < 4; e++) accO[nt][e] = 0.0f;

    float M0 = -1e30f, M1 = -1e30f;
    float L0 = 0.0f, L1 = 0.0f;

    issue(0, 0);

    const uint32_t k_rowl = ((lane >> 4) & 1) * 8 + (lane & 7);
    const uint32_t k_coll = ((lane >> 3) & 1) * 8;
    const uint32_t v_rowl = ((lane >> 3) & 1) * 8 + (lane & 7);
    const uint32_t v_coll = ((lane >> 4) & 1) * 8;

    for (int kt = 0; kt < TT / 64; kt++) {
        CP_WAIT0();
        __syncthreads();
        if (kt + 1 < TT / 64) issue(kt + 1, (kt + 1) & 1);

        const uint32_t sb = aD + (uint32_t)(kt & 1) * (4 * ARR * 2);
        const uint32_t aKh = sb;
        const uint32_t aKl = sb + ARR * 2;
        const uint32_t aVh = sb + 2 * ARR * 2;
        const uint32_t aVl = sb + 3 * ARR * 2;

        // ---- S = Q K^T: ks-outer, ql fragment reloaded from smem per ks ----
        float accS[8][4];
#pragma unroll
        for (int nt = 0; nt < 8; nt++)
#pragma unroll
            for (int e = 0; e < 4; e++) accS[nt][e] = 0.0f;

#pragma unroll
        for (int ks = 0; ks < 4; ks++) {
            uint32_t qlf[4];
            ldm_x4(qlf, aD + (QLOFF + qrow * APAD + ks * 16 + qcol) * 2);
#pragma unroll
            for (int np = 0; np < 2; np++) {
                float* a0 = accS[4 * np + 0];
                float* a1 = accS[4 * np + 1];
                float* a2 = accS[4 * np + 2];
                float* a3 = accS[4 * np + 3];
                const uint32_t krowA = (2 * np) * 16 + k_rowl;
                const uint32_t krowB = (2 * np + 1) * 16 + k_rowl;
                uint32_t kha[4], khb[4], kla[4], klb[4];
                const uint32_t offA = (krowA * APAD + ks * 16 + k_coll) * 2;
                const uint32_t offB = (krowB * APAD + ks * 16 + k_coll) * 2;
                ldm_x4(kha, aKh + offA);
                ldm_x4(khb, aKh + offB);
                ldm_x4(kla, aKl + offA);
                ldm_x4(klb, aKl + offB);
                mma16816(a0, qh[ks], &kha[0]);
                mma16816(a1, qh[ks], &kha[2]);
                mma16816(a2, qh[ks], &khb[0]);
                mma16816(a3, qh[ks], &khb[2]);
                mma16816(a0, qh[ks], &kla[0]);
                mma16816(a1, qh[ks], &kla[2]);
                mma16816(a2, qh[ks], &klb[0]);
                mma16816(a3, qh[ks], &klb[2]);
                mma16816(a0, qlf, &kha[0]);
                mma16816(a1, qlf, &kha[2]);
                mma16816(a2, qlf, &khb[0]);
                mma16816(a3, qlf, &khb[2]);
            }
        }

        // ---- online softmax ----
        float vm0 = accS[0][0], vm1 = accS[0][2];
#pragma unroll
        for (int nt = 0; nt < 8; nt++) {
            vm0 = fmaxf(vm0, fmaxf(accS[nt][0], accS[nt][1]));
            vm1 = fmaxf(vm1, fmaxf(accS[nt][2], accS[nt][3]));
        }
        vm0 = fmaxf(vm0, __shfl_xor_sync(0xffffffffu, vm0, 1));
        vm0 = fmaxf(vm0, __shfl_xor_sync(0xffffffffu, vm0, 2));
        vm1 = fmaxf(vm1, __shfl_xor_sync(0xffffffffu, vm1, 1));
        vm1 = fmaxf(vm1, __shfl_xor_sync(0xffffffffu, vm1, 2));

        const float Mn0 = fmaxf(M0, vm0);
        const float Mn1 = fmaxf(M1, vm1);
        const float corr0 = fexp2((M0 - Mn0) * EXP_C);
        const float corr1 = fexp2((M1 - Mn1) * EXP_C);
        M0 = Mn0; M1 = Mn1;
        const float mc0 = M0 * EXP_C;
        const float mc1 = M1 * EXP_C;

        float sp0 = 0.0f, sp1 = 0.0f;
#pragma unroll
        for (int nt = 0; nt < 8; nt++) {
            accS[nt][0] = fexp2(fmaf(accS[nt][0], EXP_C, -mc0));
            accS[nt][1] = fexp2(fmaf(accS[nt][1], EXP_C, -mc0));
            accS[nt][2] = fexp2(fmaf(accS[nt][2], EXP_C, -mc1));
            accS[nt][3] = fexp2(fmaf(accS[nt][3], EXP_C, -mc1));
            sp0 += accS[nt][0] + accS[nt][1];
            sp1 += accS[nt][2] + accS[nt][3];
        }
        sp0 += __shfl_xor_sync(0xffffffffu, sp0, 1);
        sp0 += __shfl_xor_sync(0xffffffffu, sp0, 2);
        sp1 += __shfl_xor_sync(0xffffffffu, sp1, 1);
        sp1 += __shfl_xor_sync(0xffffffffu, sp1, 2);
        L0 = L0 * corr0 + sp0;
        L1 = L1 * corr1 + sp1;

#pragma unroll
        for (int nt = 0; nt < 8; nt++) {
            accO[nt][0] *= corr0; accO[nt][1] *= corr0;
            accO[nt][2] *= corr1; accO[nt][3] *= corr1;
        }

        // ---- O += P V ----
#pragma unroll
        for (int kc = 0; kc < 4; kc++) {
            uint32_t ph[4], pl[4];
#pragma unroll
            for (int half = 0; half < 2; half++) {
                const int nt = 2 * kc + half;
                uint32_t h0 = pack_bf16x2(accS[nt][0], accS[nt][1]);
                uint32_t h1 = pack_bf16x2(accS[nt][2], accS[nt][3]);
                ph[half * 2 + 0] = h0;
                ph[half * 2 + 1] = h1;
                float f0 = __uint_as_float(h0 << 16);
                float f1 = __uint_as_float(h0 & 0xffff0000u);
                float f2 = __uint_as_float(h1 << 16);
                float f3 = __uint_as_float(h1 & 0xffff0000u);
                pl[half * 2 + 0] = pack_bf16x2(accS[nt][0] - f0, accS[nt][1] - f1);
                pl[half * 2 + 1] = pack_bf16x2(accS[nt][2] - f2, accS[nt][3] - f3);
            }
            const uint32_t vrow = kc * 16 + v_rowl;
#pragma unroll
            for (int np = 0; np < 2; np++) {
                float* o0 = accO[4 * np + 0];
                float* o1 = accO[4 * np + 1];
                float* o2 = accO[4 * np + 2];
                float* o3 = accO[4 * np + 3];
                uint32_t vha[4], vhb[4], vla[4], vlb[4];
                const uint32_t offA = (vrow * APAD + (2 * np) * 16 + v_coll) * 2;
                const uint32_t offB = (vrow * APAD + (2 * np + 1) * 16 + v_coll) * 2;
                ldm_x4_trans(vha, aVh + offA);
                ldm_x4_trans(vhb, aVh + offB);
                ldm_x4_trans(vla, aVl + offA);
                ldm_x4_trans(vlb, aVl + offB);
                mma16816(o0, ph, &vha[0]);
                mma16816(o1, ph, &vha[2]);
                mma16816(o2, ph, &vhb[0]);
                mma16816(o3, ph, &vhb[2]);
                mma16816(o0, ph, &vla[0]);
                mma16816(o1, ph, &vla[2]);
                mma16816(o2, ph, &vlb[0]);
                mma16816(o3, ph, &vlb[2]);
                mma16816(o0, pl, &vha[0]);
                mma16816(o1, pl, &vha[2]);
                mma16816(o2, pl, &vhb[0]);
                mma16816(o3, pl, &vhb[2]);
            }
        }
    }

    // ---- epilogue: normalize, split to bf16 hi/lo ----
    const float i0 = 1.0f / L0;
    const float i1 = 1.0f / L1;
    const int r = lane >> 2;
    const int c = (lane & 3) * 2;
    const int row = row0 + w * 16 + r;
    const size_t base0 = ((size_t)b * TT + row) * DIMD + h * DHD + c;
    const size_t base1 = base0 + 8 * DIMD;
#pragma unroll
    for (int nt = 0; nt < 8; nt++) {
        float a0 = accO[nt][0] * i0, a1 = accO[nt][1] * i0;
        float b0 = accO[nt][2] * i1, b1 = accO[nt][3] * i1;
        uint32_t h0 = pack_bf16x2(a0, a1);
        uint32_t h1 = pack_bf16x2(b0, b1);
        uint32_t l0 = pack_bf16x2(a0 - __uint_as_float(h0 << 16),
                                  a1 - __uint_as_float(h0 & 0xffff0000u));
        uint32_t l1 = pack_bf16x2(b0 - __uint_as_float(h1 << 16),
                                  b1 - __uint_as_float(h1 & 0xffff0000u));
        *(uint32_t*)(g_aoh + base0 + nt * 8) = h0;
        *(uint32_t*)(g_aol + base0 + nt * 8) = l0;
        *(uint32_t*)(g_aoh + base1 + nt * 8) = h1;
        *(uint32_t*)(g_aol + base1 + nt * 8) = l1;
    }
}

// ---------------------------------------------------------------------------
extern "C" void kernel_launch(void* const* d_in, const int* in_sizes, int n_in,
                              void* d_out, int out_size) {
    const float* x     = (const float*)d_in[0];
    const float* w_qkv = (const float*)d_in[1];
    const float* w_out = (const float*)d_in[2];
    const float* b_out = (const float*)d_in[3];
    float* y = (float*)d_out;

    void *p_xh, *p_xl, *p_wqh, *p_wql, *p_woh, *p_wol, *p_aoh, *p_aol;
    cudaGetSymbolAddress(&p_xh, g_xh);
    cudaGetSymbolAddress(&p_xl, g_xl);
    cudaGetSymbolAddress(&p_wqh, g_wqh);
    cudaGetSymbolAddress(&p_wql, g_wql);
    cudaGetSymbolAddress(&p_woh, g_woh);
    cudaGetSymbolAddress(&p_wol, g_wol);
    cudaGetSymbolAddress(&p_aoh, g_aoh);
    cudaGetSymbolAddress(&p_aol, g_aol);

    const int GEMM_SMEM = 2 * 4 * GAS * 2;     // 81,920 B
    const int ATTN_SMEM = ATTN_ELEMS * 2;      // 92,160 B
    cudaFuncSetAttribute(mma_gemm<0>, cudaFuncAttributeMaxDynamicSharedMemorySize, GEMM_SMEM);
    cudaFuncSetAttribute(mma_gemm<1>, cudaFuncAttributeMaxDynamicSharedMemorySize, GEMM_SMEM);
    cudaFuncSetAttribute(attn_mma_kernel, cudaFuncAttributeMaxDynamicSharedMemorySize, ATTN_SMEM);

    {
        int n4 = (BB * TT * DIMD) / 4;
        split_kernel<<<(n4 + 255) / 256, 256>>>(x, (__nv_bfloat16*)p_xh, (__nv_bfloat16*)p_xl, n4);
    }
    {
        int n4 = (NQKV * DIMD) / 4;
        split_kernel<<<(n4 + 255) / 256, 256>>>(w_qkv, (__nv_bfloat16*)p_wqh, (__nv_bfloat16*)p_wql, n4);
    }
    {
        int n4 = (DIMD * DIMD) / 4;
        split_kernel<<<(n4 + 255) / 256, 256>>>(w_out, (__nv_bfloat16*)p_woh, (__nv_bfloat16*)p_wol, n4);
    }

    {
        dim3 g(NQKV / 128, (BB * TT) / 128);
        mma_gemm<0><<<g, 256, GEMM_SMEM>>>((__nv_bfloat16*)p_xh, (__nv_bfloat16*)p_xl,
                                           (__nv_bfloat16*)p_wqh, (__nv_bfloat16*)p_wql,
                                           nullptr, nullptr);
    }

    attn_mma_kernel<<<BB * HH * (TT / 128), 256, ATTN_SMEM>>>();

    {
        dim3 g(DIMD / 128, (BB * TT) / 128);
        mma_gemm<1><<<g, 256, GEMM_SMEM>>>((__nv_bfloat16*)p_aoh, (__nv_bfloat16*)p_aol,
                                           (__nv_bfloat16*)p_woh, (__nv_bfloat16*)p_wol,
                                           b_out, y);
    }
}

// round 10
// speedup vs baseline: 4.2318x; 1.5090x over previous
#include <cuda_runtime.h>
#include <cuda_bf16.h>
#include <cuda_fp16.h>
#include <math.h>
#include <stdint.h>

#define BB 4
#define TT 2048
#define DIMD 1024
#define HH 16
#define DHD 64
#define NQKV 3072
#define KDIM 1024
#define ROWPAD 40   /* gemm smem row pad (bf16) */
#define APAD 72     /* attention smem row pad (fp16) */
#define EXP_C 0.045084439f  /* (1/32) * log2(e) */

// ---------------------------------------------------------------------------
// Device-global scratch
// ---------------------------------------------------------------------------
__device__ __half g_q16[BB * HH * TT * DHD];   // [b,h,t,d] fp16
__device__ __half g_k16[BB * HH * TT * DHD];
__device__ __half g_v16[BB * HH * TT * DHD];

__device__ __nv_bfloat16 g_xh[BB * TT * DIMD];
__device__ __nv_bfloat16 g_xl[BB * TT * DIMD];
__device__ __nv_bfloat16 g_wqh[NQKV * DIMD];
__device__ __nv_bfloat16 g_wql[NQKV * DIMD];
__device__ __nv_bfloat16 g_woh[DIMD * DIMD];
__device__ __nv_bfloat16 g_wol[DIMD * DIMD];
__device__ __nv_bfloat16 g_aoh[BB * TT * DIMD];
__device__ __nv_bfloat16 g_aol[BB * TT * DIMD];

// ---------------------------------------------------------------------------
// Standard-PTX helpers (compute_103-safe)
// ---------------------------------------------------------------------------
__device__ __forceinline__ uint32_t smem_u32(const void* p) {
    uint32_t a;
    asm("{ .reg .u64 t; cvta.to.shared.u64 t, %1; cvt.u32.u64 %0, t; }" : "=r"(a) : "l"(p));
    return a;
}
__device__ __forceinline__ void cp16(uint32_t dst, const void* src) {
    asm volatile("cp.async.cg.shared.global [%0], [%1], 16;" :: "r"(dst), "l"(src));
}
#define CP_COMMIT() asm volatile("cp.async.commit_group;" ::: "memory")
#define CP_WAIT0()  asm volatile("cp.async.wait_group 0;" ::: "memory")

__device__ __forceinline__ void ldm_x4(uint32_t* r, uint32_t addr) {
    asm volatile("ldmatrix.sync.aligned.m8n8.x4.shared.b16 {%0,%1,%2,%3}, [%4];"
                 : "=r"(r[0]), "=r"(r[1]), "=r"(r[2]), "=r"(r[3]) : "r"(addr));
}
__device__ __forceinline__ void ldm_x4_trans(uint32_t* r, uint32_t addr) {
    asm volatile("ldmatrix.sync.aligned.m8n8.x4.trans.shared.b16 {%0,%1,%2,%3}, [%4];"
                 : "=r"(r[0]), "=r"(r[1]), "=r"(r[2]), "=r"(r[3]) : "r"(addr));
}
// bf16 MMA (projections)
__device__ __forceinline__ void mma16816(float* d, const uint32_t* a, const uint32_t* b) {
    asm volatile(
        "mma.sync.aligned.m16n8k16.row.col.f32.bf16.bf16.f32 "
        "{%0,%1,%2,%3}, {%4,%5,%6,%7}, {%8,%9}, {%0,%1,%2,%3};"
        : "+f"(d[0]), "+f"(d[1]), "+f"(d[2]), "+f"(d[3])
        : "r"(a[0]), "r"(a[1]), "r"(a[2]), "r"(a[3]), "r"(b[0]), "r"(b[1]));
}
// fp16 MMA (attention)
__device__ __forceinline__ void mma16816h(float* d, const uint32_t* a, const uint32_t* b) {
    asm volatile(
        "mma.sync.aligned.m16n8k16.row.col.f32.f16.f16.f32 "
        "{%0,%1,%2,%3}, {%4,%5,%6,%7}, {%8,%9}, {%0,%1,%2,%3};"
        : "+f"(d[0]), "+f"(d[1]), "+f"(d[2]), "+f"(d[3])
        : "r"(a[0]), "r"(a[1]), "r"(a[2]), "r"(a[3]), "r"(b[0]), "r"(b[1]));
}
__device__ __forceinline__ uint32_t pack_bf16x2(float lo, float hi) {
    uint32_t r;
    asm("cvt.rn.satfinite.bf16x2.f32 %0, %1, %2;" : "=r"(r) : "f"(hi), "f"(lo));
    return r;
}
__device__ __forceinline__ uint32_t pack_f16x2(float lo, float hi) {
    uint32_t r;
    asm("cvt.rn.f16x2.f32 %0, %1, %2;" : "=r"(r) : "f"(hi), "f"(lo));
    return r;
}
__device__ __forceinline__ float fexp2(float x) {
    float r;
    asm("ex2.approx.ftz.f32 %0, %1;" : "=f"(r) : "f"(x));
    return r;
}

// ---------------------------------------------------------------------------
// fp32 -> (bf16 hi, bf16 lo) split pre-pass
// ---------------------------------------------------------------------------
__global__ __launch_bounds__(256) void split_kernel(const float* __restrict__ s,
                                                    __nv_bfloat16* __restrict__ h,
                                                    __nv_bfloat16* __restrict__ l,
                                                    int n4) {
    int i = blockIdx.x * blockDim.x + threadIdx.x;
    if (i >= n4) return;
    float4 v = ((const float4*)s)[i];
    uint2 hp, lp;
    hp.x = pack_bf16x2(v.x, v.y);
    hp.y = pack_bf16x2(v.z, v.w);
    lp.x = pack_bf16x2(v.x - __uint_as_float(hp.x << 16),
                       v.y - __uint_as_float(hp.x & 0xffff0000u));
    lp.y = pack_bf16x2(v.z - __uint_as_float(hp.y << 16),
                       v.w - __uint_as_float(hp.y & 0xffff0000u));
    ((uint2*)h)[i] = hp;
    ((uint2*)l)[i] = lp;
}

// ---------------------------------------------------------------------------
// HMMA bf16x3 GEMM (projections). EPI 0: -> fp16 q/k/v. EPI 1: +bias fp32 out.
// ---------------------------------------------------------------------------
#define GAS (128 * ROWPAD)

template <int EPI>
__global__ __launch_bounds__(256, 2) void mma_gemm(const __nv_bfloat16* __restrict__ Ahp,
                                                   const __nv_bfloat16* __restrict__ Alp,
                                                   const __nv_bfloat16* __restrict__ Bhp,
                                                   const __nv_bfloat16* __restrict__ Blp,
                                                   const float* __restrict__ bias,
                                                   float* __restrict__ out) {
    extern __shared__ __nv_bfloat16 dsm[];
    const uint32_t aD = smem_u32(dsm);

    const int tid = threadIdx.x;
    const int wid = tid >> 5;
    const int lane = tid & 31;
    const int warp_m = wid & 1;
    const int warp_n = wid >> 1;
    const int m0 = blockIdx.y * 128;
    const int n0 = blockIdx.x * 128;

    const __nv_bfloat16* srcs[4] = {
        Ahp + (size_t)m0 * KDIM, Alp + (size_t)m0 * KDIM,
        Bhp + (size_t)n0 * KDIM, Blp + (size_t)n0 * KDIM};

    const int ld_row = tid >> 2;
    const int ld_seg = tid & 3;

    const int a_row_base = warp_m * 64 + (lane & 15);
    const int a_colsel = (lane >> 4) * 8;
    const int b_row_base = warp_n * 32 + ((lane >> 4) & 1) * 8 + (lane & 7);
    const int b_colsel = ((lane >> 3) & 1) * 8;

    float acc[4][4][4];
#pragma unroll
    for (int mi = 0; mi < 4; mi++)
#pragma unroll
        for (int ni = 0; ni < 4; ni++)
#pragma unroll
            for (int e = 0; e < 4; e++) acc[mi][ni][e] = 0.0f;

    auto issue = [&](int c, int s) {
        const int k0 = c * 32;
        const uint32_t sb = aD + (uint32_t)s * (4 * GAS * 2);
#pragma unroll
        for (int a = 0; a < 4; a++) {
#pragma unroll
            for (int i = 0; i < 2; i++) {
                int row = ld_row + i * 64;
                cp16(sb + (uint32_t)(a * GAS + row * ROWPAD + ld_seg * 8) * 2,
                     srcs[a] + (size_t)row * KDIM + k0 + ld_seg * 8);
            }
        }
        CP_COMMIT();
    };

    issue(0, 0);

    for (int c = 0; c < 32; c++) {
        CP_WAIT0();
        __syncthreads();
        if (c + 1 < 32) issue(c + 1, (c + 1) & 1);

        const uint32_t sb = aD + (uint32_t)(c & 1) * (4 * GAS * 2);
        const uint32_t aAh = sb;
        const uint32_t aAl = sb + GAS * 2;
        const uint32_t aBh = sb + 2 * GAS * 2;
        const uint32_t aBl = sb + 3 * GAS * 2;

#pragma unroll
        for (int kk = 0; kk < 2; kk++) {
            const int acol = kk * 16 + a_colsel;
            const int bcol = kk * 16 + b_colsel;

            uint32_t fa[4][4];
            uint32_t fbh[4][2];
            uint32_t fbl[4][2];

#pragma unroll
            for (int mi = 0; mi < 4; mi++)
                ldm_x4(fa[mi], aAh + ((a_row_base + mi * 16) * ROWPAD + acol) * 2);
#pragma unroll
            for (int ni2 = 0; ni2 < 2; ni2++) {
                const uint32_t boff = ((b_row_base + ni2 * 16) * ROWPAD + bcol) * 2;
                ldm_x4(&fbh[ni2 * 2][0], aBh + boff);
                ldm_x4(&fbl[ni2 * 2][0], aBl + boff);
            }

#pragma unroll
            for (int mi = 0; mi < 4; mi++)
#pragma unroll
                for (int ni = 0; ni < 4; ni++) mma16816(acc[mi][ni], fa[mi], fbh[ni]);
#pragma unroll
            for (int mi = 0; mi < 4; mi++)
#pragma unroll
                for (int ni = 0; ni < 4; ni++) mma16816(acc[mi][ni], fa[mi], fbl[ni]);
#pragma unroll
            for (int mi = 0; mi < 4; mi++)
                ldm_x4(fa[mi], aAl + ((a_row_base + mi * 16) * ROWPAD + acol) * 2);
#pragma unroll
            for (int mi = 0; mi < 4; mi++)
#pragma unroll
                for (int ni = 0; ni < 4; ni++) mma16816(acc[mi][ni], fa[mi], fbh[ni]);
        }
    }

    const int r0 = lane >> 2;
    const int c0 = (lane & 3) * 2;
#pragma unroll
    for (int mi = 0; mi < 4; mi++) {
#pragma unroll
        for (int half = 0; half < 2; half++) {
            const int m = m0 + warp_m * 64 + mi * 16 + r0 + half * 8;
            if (EPI == 0) {
                const int b = m >> 11;
                const int t = m & (TT - 1);
                const size_t mbase = ((size_t)b * HH) * TT;
#pragma unroll
                for (int ni = 0; ni < 4; ni++) {
#pragma unroll
                    for (int e = 0; e < 2; e++) {
                        int o = n0 + warp_n * 32 + ni * 8 + c0 + e;
                        float v = acc[mi][ni][half * 2 + e];
                        int d = o / 48;
                        int rem = o - d * 48;
                        int kq = rem >> 4;
                        int h = rem & 15;
                        __half* dst = (kq == 0) ? g_q16 : (kq == 1) ? g_k16 : g_v16;
                        size_t idx = ((mbase + (size_t)h * TT) + t) * DHD + d;
                        dst[idx] = __float2half(v);
                    }
                }
            } else {
#pragma unroll
                for (int ni = 0; ni < 4; ni++) {
#pragma unroll
                    for (int e = 0; e < 2; e++) {
                        int o = n0 + warp_n * 32 + ni * 8 + c0 + e;
                        out[(size_t)m * DIMD + o] = acc[mi][ni][half * 2 + e] + bias[o];
                    }
                }
            }
        }
    }
}

// ---------------------------------------------------------------------------
// fp16 single-pass HMMA flash attention.
// smem: 2 stages x (K, V) x 64 x APAD fp16 = 36,864 B. Q staged in stage 0.
// ---------------------------------------------------------------------------
#define ARR (64 * APAD)
#define ATTN_ELEMS (4 * ARR)

__global__ __launch_bounds__(256, 2) void attn_mma_kernel() {
    extern __shared__ __half hsm[];
    const uint32_t aD = smem_u32(hsm);

    const int tid = threadIdx.x;
    const int w = tid >> 5;
    const int lane = tid & 31;
    const int bh = blockIdx.x >> 4;
    const int rb = blockIdx.x & 15;
    const int b = bh >> 4;
    const int h = bh & 15;
    const int row0 = rb * 128;

    const __half* Qp = g_q16 + (size_t)bh * TT * DHD;
    const __half* Kp = g_k16 + (size_t)bh * TT * DHD;
    const __half* Vp = g_v16 + (size_t)bh * TT * DHD;

    // ---- stage Q into stage-0 region (exactly 128*APAD elems), build frags ----
#pragma unroll
    for (int i = 0; i < 4; i++) {
        int idx = tid + i * 256;       // 1024: 128 rows x 8 segs
        int r = idx >> 3;
        int sg = idx & 7;
        *(uint4*)&hsm[r * APAD + sg * 8] =
            *(const uint4*)(Qp + (size_t)(row0 + r) * DHD + sg * 8);
    }
    __syncthreads();

    const uint32_t qrow = w * 16 + (lane & 15);
    const uint32_t qcol = (lane >> 4) * 8;
    uint32_t qf[4][4];
#pragma unroll
    for (int ks = 0; ks < 4; ks++)
        ldm_x4(qf[ks], aD + (qrow * APAD + ks * 16 + qcol) * 2);
    __syncthreads();   // Q reads done before cp.async overwrites stage 0

    const int ld_row = tid >> 2;
    const int ld_seg = tid & 3;

    auto issue = [&](int kt, int s) {
        const size_t goff = (size_t)kt * 64 * DHD;
        const uint32_t sb = aD + (uint32_t)s * (2 * ARR * 2);
        const __half* srcs[2] = {Kp + goff, Vp + goff};
#pragma unroll
        for (int a = 0; a < 2; a++) {
#pragma unroll
            for (int i = 0; i < 2; i++) {
                int sg = ld_seg + i * 4;
                cp16(sb + (uint32_t)(a * ARR + ld_row * APAD + sg * 8) * 2,
                     srcs[a] + (size_t)ld_row * DHD + sg * 8);
            }
        }
        CP_COMMIT();
    };

    float accO[8][4];
#pragma unroll
    for (int nt = 0; nt < 8; nt++)
#pragma unroll
        for (int e = 0; e < 4; e++) accO[nt][e] = 0.0f;

    float M0 = -1e30f, M1 = -1e30f;
    float L0 = 0.0f, L1 = 0.0f;

    issue(0, 0);

    const uint32_t k_rowl = ((lane >> 4) & 1) * 8 + (lane & 7);
    const uint32_t k_coll = ((lane >> 3) & 1) * 8;
    const uint32_t v_rowl = ((lane >> 3) & 1) * 8 + (lane & 7);
    const uint32_t v_coll = ((lane >> 4) & 1) * 8;

    for (int kt = 0; kt < TT / 64; kt++) {
        CP_WAIT0();
        __syncthreads();
        if (kt + 1 < TT / 64) issue(kt + 1, (kt + 1) & 1);

        const uint32_t sb = aD + (uint32_t)(kt & 1) * (2 * ARR * 2);
        const uint32_t aK = sb;
        const uint32_t aV = sb + ARR * 2;

        // ---- S = Q K^T (single fp16 pass) ----
        float accS[8][4];
#pragma unroll
        for (int nt = 0; nt < 8; nt++)
#pragma unroll
            for (int e = 0; e < 4; e++) accS[nt][e] = 0.0f;

#pragma unroll
        for (int ks = 0; ks < 4; ks++) {
#pragma unroll
            for (int np = 0; np < 2; np++) {
                uint32_t kfa[4], kfb[4];
                const uint32_t offA = (((2 * np) * 16 + k_rowl) * APAD + ks * 16 + k_coll) * 2;
                const uint32_t offB = (((2 * np + 1) * 16 + k_rowl) * APAD + ks * 16 + k_coll) * 2;
                ldm_x4(kfa, aK + offA);
                ldm_x4(kfb, aK + offB);
                mma16816h(accS[4 * np + 0], qf[ks], &kfa[0]);
                mma16816h(accS[4 * np + 1], qf[ks], &kfa[2]);
                mma16816h(accS[4 * np + 2], qf[ks], &kfb[0]);
                mma16816h(accS[4 * np + 3], qf[ks], &kfb[2]);
            }
        }

        // ---- online softmax ----
        float vm0 = accS[0][0], vm1 = accS[0][2];
#pragma unroll
        for (int nt = 0; nt < 8; nt++) {
            vm0 = fmaxf(vm0, fmaxf(accS[nt][0], accS[nt][1]));
            vm1 = fmaxf(vm1, fmaxf(accS[nt][2], accS[nt][3]));
        }
        vm0 = fmaxf(vm0, __shfl_xor_sync(0xffffffffu, vm0, 1));
        vm0 = fmaxf(vm0, __shfl_xor_sync(0xffffffffu, vm0, 2));
        vm1 = fmaxf(vm1, __shfl_xor_sync(0xffffffffu, vm1, 1));
        vm1 = fmaxf(vm1, __shfl_xor_sync(0xffffffffu, vm1, 2));

        const float Mn0 = fmaxf(M0, vm0);
        const float Mn1 = fmaxf(M1, vm1);
        const float corr0 = fexp2((M0 - Mn0) * EXP_C);
        const float corr1 = fexp2((M1 - Mn1) * EXP_C);
        M0 = Mn0; M1 = Mn1;
        const float mc0 = M0 * EXP_C;
        const float mc1 = M1 * EXP_C;

        float sp0 = 0.0f, sp1 = 0.0f;
#pragma unroll
        for (int nt = 0; nt < 8; nt++) {
            accS[nt][0] = fexp2(fmaf(accS[nt][0], EXP_C, -mc0));
            accS[nt][1] = fexp2(fmaf(accS[nt][1], EXP_C, -mc0));
            accS[nt][2] = fexp2(fmaf(accS[nt][2], EXP_C, -mc1));
            accS[nt][3] = fexp2(fmaf(accS[nt][3], EXP_C, -mc1));
            sp0 += accS[nt][0] + accS[nt][1];
            sp1 += accS[nt][2] + accS[nt][3];
        }
        sp0 += __shfl_xor_sync(0xffffffffu, sp0, 1);
        sp0 += __shfl_xor_sync(0xffffffffu, sp0, 2);
        sp1 += __shfl_xor_sync(0xffffffffu, sp1, 1);
        sp1 += __shfl_xor_sync(0xffffffffu, sp1, 2);
        L0 = L0 * corr0 + sp0;
        L1 = L1 * corr1 + sp1;

#pragma unroll
        for (int nt = 0; nt < 8; nt++) {
            accO[nt][0] *= corr0; accO[nt][1] *= corr0;
            accO[nt][2] *= corr1; accO[nt][3] *= corr1;
        }

        // ---- O += P V (single fp16 pass) ----
#pragma unroll
        for (int kc = 0; kc < 4; kc++) {
            uint32_t ph[4];
#pragma unroll
            for (int half = 0; half < 2; half++) {
                const int nt = 2 * kc + half;
                ph[half * 2 + 0] = pack_f16x2(accS[nt][0], accS[nt][1]);
                ph[half * 2 + 1] = pack_f16x2(accS[nt][2], accS[nt][3]);
            }
            const uint32_t vrow = kc * 16 + v_rowl;
#pragma unroll
            for (int np = 0; np < 2; np++) {
                uint32_t vfa[4], vfb[4];
                const uint32_t offA = (vrow * APAD + (2 * np) * 16 + v_coll) * 2;
                const uint32_t offB = (vrow * APAD + (2 * np + 1) * 16 + v_coll) * 2;
                ldm_x4_trans(vfa, aV + offA);
                ldm_x4_trans(vfb, aV + offB);
                mma16816h(accO[4 * np + 0], ph, &vfa[0]);
                mma16816h(accO[4 * np + 1], ph, &vfa[2]);
                mma16816h(accO[4 * np + 2], ph, &vfb[0]);
                mma16816h(accO[4 * np + 3], ph, &vfb[2]);
            }
        }
    }

    // ---- epilogue: normalize, split to bf16 hi/lo for out-projection ----
    const float i0 = 1.0f / L0;
    const float i1 = 1.0f / L1;
    const int r = lane >> 2;
    const int c = (lane & 3) * 2;
    const int row = row0 + w * 16 + r;
    const size_t base0 = ((size_t)b * TT + row) * DIMD + h * DHD + c;
    const size_t base1 = base0 + 8 * DIMD;
#pragma unroll
    for (int nt = 0; nt < 8; nt++) {
        float a0 = accO[nt][0] * i0, a1 = accO[nt][1] * i0;
        float b0 = accO[nt][2] * i1, b1 = accO[nt][3] * i1;
        uint32_t h0 = pack_bf16x2(a0, a1);
        uint32_t h1 = pack_bf16x2(b0, b1);
        uint32_t l0 = pack_bf16x2(a0 - __uint_as_float(h0 << 16),
                                  a1 - __uint_as_float(h0 & 0xffff0000u));
        uint32_t l1 = pack_bf16x2(b0 - __uint_as_float(h1 << 16),
                                  b1 - __uint_as_float(h1 & 0xffff0000u));
        *(uint32_t*)(g_aoh + base0 + nt * 8) = h0;
        *(uint32_t*)(g_aol + base0 + nt * 8) = l0;
        *(uint32_t*)(g_aoh + base1 + nt * 8) = h1;
        *(uint32_t*)(g_aol + base1 + nt * 8) = l1;
    }
}

// ---------------------------------------------------------------------------
extern "C" void kernel_launch(void* const* d_in, const int* in_sizes, int n_in,
                              void* d_out, int out_size) {
    const float* x     = (const float*)d_in[0];
    const float* w_qkv = (const float*)d_in[1];
    const float* w_out = (const float*)d_in[2];
    const float* b_out = (const float*)d_in[3];
    float* y = (float*)d_out;

    void *p_xh, *p_xl, *p_wqh, *p_wql, *p_woh, *p_wol, *p_aoh, *p_aol;
    cudaGetSymbolAddress(&p_xh, g_xh);
    cudaGetSymbolAddress(&p_xl, g_xl);
    cudaGetSymbolAddress(&p_wqh, g_wqh);
    cudaGetSymbolAddress(&p_wql, g_wql);
    cudaGetSymbolAddress(&p_woh, g_woh);
    cudaGetSymbolAddress(&p_wol, g_wol);
    cudaGetSymbolAddress(&p_aoh, g_aoh);
    cudaGetSymbolAddress(&p_aol, g_aol);

    const int GEMM_SMEM = 2 * 4 * GAS * 2;     // 81,920 B
    const int ATTN_SMEM = ATTN_ELEMS * 2;      // 36,864 B
    cudaFuncSetAttribute(mma_gemm<0>, cudaFuncAttributeMaxDynamicSharedMemorySize, GEMM_SMEM);
    cudaFuncSetAttribute(mma_gemm<1>, cudaFuncAttributeMaxDynamicSharedMemorySize, GEMM_SMEM);
    cudaFuncSetAttribute(attn_mma_kernel, cudaFuncAttributeMaxDynamicSharedMemorySize, ATTN_SMEM);

    {
        int n4 = (BB * TT * DIMD) / 4;
        split_kernel<<<(n4 + 255) / 256, 256>>>(x, (__nv_bfloat16*)p_xh, (__nv_bfloat16*)p_xl, n4);
    }
    {
        int n4 = (NQKV * DIMD) / 4;
        split_kernel<<<(n4 + 255) / 256, 256>>>(w_qkv, (__nv_bfloat16*)p_wqh, (__nv_bfloat16*)p_wql, n4);
    }
    {
        int n4 = (DIMD * DIMD) / 4;
        split_kernel<<<(n4 + 255) / 256, 256>>>(w_out, (__nv_bfloat16*)p_woh, (__nv_bfloat16*)p_wol, n4);
    }

    {
        dim3 g(NQKV / 128, (BB * TT) / 128);
        mma_gemm<0><<<g, 256, GEMM_SMEM>>>((__nv_bfloat16*)p_xh, (__nv_bfloat16*)p_xl,
                                           (__nv_bfloat16*)p_wqh, (__nv_bfloat16*)p_wql,
                                           nullptr, nullptr);
    }

    attn_mma_kernel<<<BB * HH * (TT / 128), 256, ATTN_SMEM>>>();

    {
        dim3 g(DIMD / 128, (BB * TT) / 128);
        mma_gemm<1><<<g, 256, GEMM_SMEM>>>((__nv_bfloat16*)p_aoh, (__nv_bfloat16*)p_aol,
                                           (__nv_bfloat16*)p_woh, (__nv_bfloat16*)p_wol,
                                           b_out, y);
    }
}

// round 11
// speedup vs baseline: 6.2532x; 1.4777x over previous
#include <cuda_runtime.h>
#include <cuda_bf16.h>
#include <cuda_fp16.h>
#include <math.h>
#include <stdint.h>

#define BB 4
#define TT 2048
#define DIMD 1024
#define HH 16
#define DHD 64
#define NQKV 3072
#define KDIM 1024
#define ROWPAD 40   /* gemm smem row pad (fp16) */
#define APAD 72     /* attention smem row pad (fp16) */
#define EXP_C 0.045084439f  /* (1/32) * log2(e) */

// ---------------------------------------------------------------------------
// Device-global scratch (all fp16 now)
// ---------------------------------------------------------------------------
__device__ __half g_q16[BB * HH * TT * DHD];   // [b,h,t,d]
__device__ __half g_k16[BB * HH * TT * DHD];
__device__ __half g_v16[BB * HH * TT * DHD];

__device__ __half g_x16[BB * TT * DIMD];
__device__ __half g_wq16[NQKV * DIMD];
__device__ __half g_wo16[DIMD * DIMD];
__device__ __half g_ao16[BB * TT * DIMD];      // attention out, [b,t,(h d)]

// ---------------------------------------------------------------------------
// Standard-PTX helpers (compute_103-safe)
// ---------------------------------------------------------------------------
__device__ __forceinline__ uint32_t smem_u32(const void* p) {
    uint32_t a;
    asm("{ .reg .u64 t; cvta.to.shared.u64 t, %1; cvt.u32.u64 %0, t; }" : "=r"(a) : "l"(p));
    return a;
}
__device__ __forceinline__ void cp16(uint32_t dst, const void* src) {
    asm volatile("cp.async.cg.shared.global [%0], [%1], 16;" :: "r"(dst), "l"(src));
}
#define CP_COMMIT() asm volatile("cp.async.commit_group;" ::: "memory")
#define CP_WAIT0()  asm volatile("cp.async.wait_group 0;" ::: "memory")

__device__ __forceinline__ void ldm_x4(uint32_t* r, uint32_t addr) {
    asm volatile("ldmatrix.sync.aligned.m8n8.x4.shared.b16 {%0,%1,%2,%3}, [%4];"
                 : "=r"(r[0]), "=r"(r[1]), "=r"(r[2]), "=r"(r[3]) : "r"(addr));
}
__device__ __forceinline__ void ldm_x4_trans(uint32_t* r, uint32_t addr) {
    asm volatile("ldmatrix.sync.aligned.m8n8.x4.trans.shared.b16 {%0,%1,%2,%3}, [%4];"
                 : "=r"(r[0]), "=r"(r[1]), "=r"(r[2]), "=r"(r[3]) : "r"(addr));
}
// fp16 MMA
__device__ __forceinline__ void mma16816h(float* d, const uint32_t* a, const uint32_t* b) {
    asm volatile(
        "mma.sync.aligned.m16n8k16.row.col.f32.f16.f16.f32 "
        "{%0,%1,%2,%3}, {%4,%5,%6,%7}, {%8,%9}, {%0,%1,%2,%3};"
        : "+f"(d[0]), "+f"(d[1]), "+f"(d[2]), "+f"(d[3])
        : "r"(a[0]), "r"(a[1]), "r"(a[2]), "r"(a[3]), "r"(b[0]), "r"(b[1]));
}
__device__ __forceinline__ uint32_t pack_f16x2(float lo, float hi) {
    uint32_t r;
    asm("cvt.rn.f16x2.f32 %0, %1, %2;" : "=r"(r) : "f"(hi), "f"(lo));
    return r;
}
__device__ __forceinline__ float fexp2(float x) {
    float r;
    asm("ex2.approx.ftz.f32 %0, %1;" : "=f"(r) : "f"(x));
    return r;
}

// ---------------------------------------------------------------------------
// fp32 -> fp16 convert pre-pass
// ---------------------------------------------------------------------------
__global__ __launch_bounds__(256) void cvt16_kernel(const float* __restrict__ s,
                                                    __half* __restrict__ d, int n4) {
    int i = blockIdx.x * blockDim.x + threadIdx.x;
    if (i >= n4) return;
    float4 v = ((const float4*)s)[i];
    uint2 p;
    p.x = pack_f16x2(v.x, v.y);
    p.y = pack_f16x2(v.z, v.w);
    ((uint2*)d)[i] = p;
}

// ---------------------------------------------------------------------------
// Single-pass fp16 HMMA GEMM: D[128x128] = A[128xK] * B[128xK]^T, fp32 accum.
// cp.async double-buffered, single barrier per chunk.
// EPI 0: scatter to fp16 q/k/v.  EPI 1: +bias -> fp32 out.
// ---------------------------------------------------------------------------
#define GAS (128 * ROWPAD)

template <int EPI>
__global__ __launch_bounds__(256, 2) void mma_gemm(const __half* __restrict__ Ap,
                                                   const __half* __restrict__ Bp,
                                                   const float* __restrict__ bias,
                                                   float* __restrict__ out) {
    extern __shared__ __half dsm[];
    const uint32_t aD = smem_u32(dsm);

    const int tid = threadIdx.x;
    const int wid = tid >> 5;
    const int lane = tid & 31;
    const int warp_m = wid & 1;
    const int warp_n = wid >> 1;
    const int m0 = blockIdx.y * 128;
    const int n0 = blockIdx.x * 128;

    const __half* srcA = Ap + (size_t)m0 * KDIM;
    const __half* srcB = Bp + (size_t)n0 * KDIM;

    const int ld_row = tid >> 2;
    const int ld_seg = tid & 3;

    const int a_row_base = warp_m * 64 + (lane & 15);
    const int a_colsel = (lane >> 4) * 8;
    const int b_row_base = warp_n * 32 + ((lane >> 4) & 1) * 8 + (lane & 7);
    const int b_colsel = ((lane >> 3) & 1) * 8;

    float acc[4][4][4];
#pragma unroll
    for (int mi = 0; mi < 4; mi++)
#pragma unroll
        for (int ni = 0; ni < 4; ni++)
#pragma unroll
            for (int e = 0; e < 4; e++) acc[mi][ni][e] = 0.0f;

    auto issue = [&](int c, int s) {
        const int k0 = c * 32;
        const uint32_t sb = aD + (uint32_t)s * (2 * GAS * 2);
#pragma unroll
        for (int i = 0; i < 2; i++) {
            int row = ld_row + i * 64;
            cp16(sb + (uint32_t)(row * ROWPAD + ld_seg * 8) * 2,
                 srcA + (size_t)row * KDIM + k0 + ld_seg * 8);
            cp16(sb + (uint32_t)(GAS + row * ROWPAD + ld_seg * 8) * 2,
                 srcB + (size_t)row * KDIM + k0 + ld_seg * 8);
        }
        CP_COMMIT();
    };

    issue(0, 0);

    for (int c = 0; c < 32; c++) {
        CP_WAIT0();
        __syncthreads();
        if (c + 1 < 32) issue(c + 1, (c + 1) & 1);

        const uint32_t sb = aD + (uint32_t)(c & 1) * (2 * GAS * 2);
        const uint32_t aA = sb;
        const uint32_t aB = sb + GAS * 2;

#pragma unroll
        for (int kk = 0; kk < 2; kk++) {
            const int acol = kk * 16 + a_colsel;
            const int bcol = kk * 16 + b_colsel;

            uint32_t fa[4][4];
            uint32_t fb[4][2];

#pragma unroll
            for (int mi = 0; mi < 4; mi++)
                ldm_x4(fa[mi], aA + ((a_row_base + mi * 16) * ROWPAD + acol) * 2);
#pragma unroll
            for (int ni2 = 0; ni2 < 2; ni2++)
                ldm_x4(&fb[ni2 * 2][0], aB + ((b_row_base + ni2 * 16) * ROWPAD + bcol) * 2);

#pragma unroll
            for (int mi = 0; mi < 4; mi++)
#pragma unroll
                for (int ni = 0; ni < 4; ni++) mma16816h(acc[mi][ni], fa[mi], fb[ni]);
        }
    }

    const int r0 = lane >> 2;
    const int c0 = (lane & 3) * 2;
#pragma unroll
    for (int mi = 0; mi < 4; mi++) {
#pragma unroll
        for (int half = 0; half < 2; half++) {
            const int m = m0 + warp_m * 64 + mi * 16 + r0 + half * 8;
            if (EPI == 0) {
                const int b = m >> 11;
                const int t = m & (TT - 1);
                const size_t mbase = ((size_t)b * HH) * TT;
#pragma unroll
                for (int ni = 0; ni < 4; ni++) {
#pragma unroll
                    for (int e = 0; e < 2; e++) {
                        int o = n0 + warp_n * 32 + ni * 8 + c0 + e;
                        float v = acc[mi][ni][half * 2 + e];
                        int d = o / 48;
                        int rem = o - d * 48;
                        int kq = rem >> 4;
                        int h = rem & 15;
                        __half* dst = (kq == 0) ? g_q16 : (kq == 1) ? g_k16 : g_v16;
                        size_t idx = ((mbase + (size_t)h * TT) + t) * DHD + d;
                        dst[idx] = __float2half(v);
                    }
                }
            } else {
#pragma unroll
                for (int ni = 0; ni < 4; ni++) {
#pragma unroll
                    for (int e = 0; e < 2; e++) {
                        int o = n0 + warp_n * 32 + ni * 8 + c0 + e;
                        out[(size_t)m * DIMD + o] = acc[mi][ni][half * 2 + e] + bias[o];
                    }
                }
            }
        }
    }
}

// ---------------------------------------------------------------------------
// fp16 single-pass HMMA flash attention (validated R9), fp16 output.
// ---------------------------------------------------------------------------
#define ARR (64 * APAD)
#define ATTN_ELEMS (4 * ARR)

__global__ __launch_bounds__(256, 2) void attn_mma_kernel() {
    extern __shared__ __half hsm[];
    const uint32_t aD = smem_u32(hsm);

    const int tid = threadIdx.x;
    const int w = tid >> 5;
    const int lane = tid & 31;
    const int bh = blockIdx.x >> 4;
    const int rb = blockIdx.x & 15;
    const int b = bh >> 4;
    const int h = bh & 15;
    const int row0 = rb * 128;

    const __half* Qp = g_q16 + (size_t)bh * TT * DHD;
    const __half* Kp = g_k16 + (size_t)bh * TT * DHD;
    const __half* Vp = g_v16 + (size_t)bh * TT * DHD;

    // ---- stage Q into stage-0 region, build fragments ----
#pragma unroll
    for (int i = 0; i < 4; i++) {
        int idx = tid + i * 256;
        int r = idx >> 3;
        int sg = idx & 7;
        *(uint4*)&hsm[r * APAD + sg * 8] =
            *(const uint4*)(Qp + (size_t)(row0 + r) * DHD + sg * 8);
    }
    __syncthreads();

    const uint32_t qrow = w * 16 + (lane & 15);
    const uint32_t qcol = (lane >> 4) * 8;
    uint32_t qf[4][4];
#pragma unroll
    for (int ks = 0; ks < 4; ks++)
        ldm_x4(qf[ks], aD + (qrow * APAD + ks * 16 + qcol) * 2);
    __syncthreads();

    const int ld_row = tid >> 2;
    const int ld_seg = tid & 3;

    auto issue = [&](int kt, int s) {
        const size_t goff = (size_t)kt * 64 * DHD;
        const uint32_t sb = aD + (uint32_t)s * (2 * ARR * 2);
        const __half* srcs[2] = {Kp + goff, Vp + goff};
#pragma unroll
        for (int a = 0; a < 2; a++) {
#pragma unroll
            for (int i = 0; i < 2; i++) {
                int sg = ld_seg + i * 4;
                cp16(sb + (uint32_t)(a * ARR + ld_row * APAD + sg * 8) * 2,
                     srcs[a] + (size_t)ld_row * DHD + sg * 8);
            }
        }
        CP_COMMIT();
    };

    float accO[8][4];
#pragma unroll
    for (int nt = 0; nt < 8; nt++)
#pragma unroll
        for (int e = 0; e < 4; e++) accO[nt][e] = 0.0f;

    float M0 = -1e30f, M1 = -1e30f;
    float L0 = 0.0f, L1 = 0.0f;

    issue(0, 0);

    const uint32_t k_rowl = ((lane >> 4) & 1) * 8 + (lane & 7);
    const uint32_t k_coll = ((lane >> 3) & 1) * 8;
    const uint32_t v_rowl = ((lane >> 3) & 1) * 8 + (lane & 7);
    const uint32_t v_coll = ((lane >> 4) & 1) * 8;

    for (int kt = 0; kt < TT / 64; kt++) {
        CP_WAIT0();
        __syncthreads();
        if (kt + 1 < TT / 64) issue(kt + 1, (kt + 1) & 1);

        const uint32_t sb = aD + (uint32_t)(kt & 1) * (2 * ARR * 2);
        const uint32_t aK = sb;
        const uint32_t aV = sb + ARR * 2;

        // ---- S = Q K^T ----
        float accS[8][4];
#pragma unroll
        for (int nt = 0; nt < 8; nt++)
#pragma unroll
            for (int e = 0; e < 4; e++) accS[nt][e] = 0.0f;

#pragma unroll
        for (int ks = 0; ks < 4; ks++) {
#pragma unroll
            for (int np = 0; np < 2; np++) {
                uint32_t kfa[4], kfb[4];
                const uint32_t offA = (((2 * np) * 16 + k_rowl) * APAD + ks * 16 + k_coll) * 2;
                const uint32_t offB = (((2 * np + 1) * 16 + k_rowl) * APAD + ks * 16 + k_coll) * 2;
                ldm_x4(kfa, aK + offA);
                ldm_x4(kfb, aK + offB);
                mma16816h(accS[4 * np + 0], qf[ks], &kfa[0]);
                mma16816h(accS[4 * np + 1], qf[ks], &kfa[2]);
                mma16816h(accS[4 * np + 2], qf[ks], &kfb[0]);
                mma16816h(accS[4 * np + 3], qf[ks], &kfb[2]);
            }
        }

        // ---- online softmax ----
        float vm0 = accS[0][0], vm1 = accS[0][2];
#pragma unroll
        for (int nt = 0; nt < 8; nt++) {
            vm0 = fmaxf(vm0, fmaxf(accS[nt][0], accS[nt][1]));
            vm1 = fmaxf(vm1, fmaxf(accS[nt][2], accS[nt][3]));
        }
        vm0 = fmaxf(vm0, __shfl_xor_sync(0xffffffffu, vm0, 1));
        vm0 = fmaxf(vm0, __shfl_xor_sync(0xffffffffu, vm0, 2));
        vm1 = fmaxf(vm1, __shfl_xor_sync(0xffffffffu, vm1, 1));
        vm1 = fmaxf(vm1, __shfl_xor_sync(0xffffffffu, vm1, 2));

        const float Mn0 = fmaxf(M0, vm0);
        const float Mn1 = fmaxf(M1, vm1);
        const float corr0 = fexp2((M0 - Mn0) * EXP_C);
        const float corr1 = fexp2((M1 - Mn1) * EXP_C);
        M0 = Mn0; M1 = Mn1;
        const float mc0 = M0 * EXP_C;
        const float mc1 = M1 * EXP_C;

        float sp0 = 0.0f, sp1 = 0.0f;
#pragma unroll
        for (int nt = 0; nt < 8; nt++) {
            accS[nt][0] = fexp2(fmaf(accS[nt][0], EXP_C, -mc0));
            accS[nt][1] = fexp2(fmaf(accS[nt][1], EXP_C, -mc0));
            accS[nt][2] = fexp2(fmaf(accS[nt][2], EXP_C, -mc1));
            accS[nt][3] = fexp2(fmaf(accS[nt][3], EXP_C, -mc1));
            sp0 += accS[nt][0] + accS[nt][1];
            sp1 += accS[nt][2] + accS[nt][3];
        }
        sp0 += __shfl_xor_sync(0xffffffffu, sp0, 1);
        sp0 += __shfl_xor_sync(0xffffffffu, sp0, 2);
        sp1 += __shfl_xor_sync(0xffffffffu, sp1, 1);
        sp1 += __shfl_xor_sync(0xffffffffu, sp1, 2);
        L0 = L0 * corr0 + sp0;
        L1 = L1 * corr1 + sp1;

#pragma unroll
        for (int nt = 0; nt < 8; nt++) {
            accO[nt][0] *= corr0; accO[nt][1] *= corr0;
            accO[nt][2] *= corr1; accO[nt][3] *= corr1;
        }

        // ---- O += P V ----
#pragma unroll
        for (int kc = 0; kc < 4; kc++) {
            uint32_t ph[4];
#pragma unroll
            for (int half = 0; half < 2; half++) {
                const int nt = 2 * kc + half;
                ph[half * 2 + 0] = pack_f16x2(accS[nt][0], accS[nt][1]);
                ph[half * 2 + 1] = pack_f16x2(accS[nt][2], accS[nt][3]);
            }
            const uint32_t vrow = kc * 16 + v_rowl;
#pragma unroll
            for (int np = 0; np < 2; np++) {
                uint32_t vfa[4], vfb[4];
                const uint32_t offA = (vrow * APAD + (2 * np) * 16 + v_coll) * 2;
                const uint32_t offB = (vrow * APAD + (2 * np + 1) * 16 + v_coll) * 2;
                ldm_x4_trans(vfa, aV + offA);
                ldm_x4_trans(vfb, aV + offB);
                mma16816h(accO[4 * np + 0], ph, &vfa[0]);
                mma16816h(accO[4 * np + 1], ph, &vfa[2]);
                mma16816h(accO[4 * np + 2], ph, &vfb[0]);
                mma16816h(accO[4 * np + 3], ph, &vfb[2]);
            }
        }
    }

    // ---- epilogue: normalize, write fp16 g_ao16 ----
    const float i0 = 1.0f / L0;
    const float i1 = 1.0f / L1;
    const int r = lane >> 2;
    const int c = (lane & 3) * 2;
    const int row = row0 + w * 16 + r;
    const size_t base0 = ((size_t)b * TT + row) * DIMD + h * DHD + c;
    const size_t base1 = base0 + 8 * DIMD;
#pragma unroll
    for (int nt = 0; nt < 8; nt++) {
        *(uint32_t*)(g_ao16 + base0 + nt * 8) =
            pack_f16x2(accO[nt][0] * i0, accO[nt][1] * i0);
        *(uint32_t*)(g_ao16 + base1 + nt * 8) =
            pack_f16x2(accO[nt][2] * i1, accO[nt][3] * i1);
    }
}

// ---------------------------------------------------------------------------
extern "C" void kernel_launch(void* const* d_in, const int* in_sizes, int n_in,
                              void* d_out, int out_size) {
    const float* x     = (const float*)d_in[0];
    const float* w_qkv = (const float*)d_in[1];
    const float* w_out = (const float*)d_in[2];
    const float* b_out = (const float*)d_in[3];
    float* y = (float*)d_out;

    void *p_x16, *p_wq16, *p_wo16, *p_ao16;
    cudaGetSymbolAddress(&p_x16, g_x16);
    cudaGetSymbolAddress(&p_wq16, g_wq16);
    cudaGetSymbolAddress(&p_wo16, g_wo16);
    cudaGetSymbolAddress(&p_ao16, g_ao16);

    const int GEMM_SMEM = 2 * 2 * GAS * 2;     // 40,960 B
    const int ATTN_SMEM = ATTN_ELEMS * 2;      // 36,864 B
    cudaFuncSetAttribute(mma_gemm<0>, cudaFuncAttributeMaxDynamicSharedMemorySize, GEMM_SMEM);
    cudaFuncSetAttribute(mma_gemm<1>, cudaFuncAttributeMaxDynamicSharedMemorySize, GEMM_SMEM);
    cudaFuncSetAttribute(attn_mma_kernel, cudaFuncAttributeMaxDynamicSharedMemorySize, ATTN_SMEM);

    {
        int n4 = (BB * TT * DIMD) / 4;
        cvt16_kernel<<<(n4 + 255) / 256, 256>>>(x, (__half*)p_x16, n4);
    }
    {
        int n4 = (NQKV * DIMD) / 4;
        cvt16_kernel<<<(n4 + 255) / 256, 256>>>(w_qkv, (__half*)p_wq16, n4);
    }
    {
        int n4 = (DIMD * DIMD) / 4;
        cvt16_kernel<<<(n4 + 255) / 256, 256>>>(w_out, (__half*)p_wo16, n4);
    }

    // QKV projection: M=8192, N=3072
    {
        dim3 g(NQKV / 128, (BB * TT) / 128);
        mma_gemm<0><<<g, 256, GEMM_SMEM>>>((const __half*)p_x16, (const __half*)p_wq16,
                                           nullptr, nullptr);
    }

    attn_mma_kernel<<<BB * HH * (TT / 128), 256, ATTN_SMEM>>>();

    // Output projection: M=8192, N=1024 (+bias)
    {
        dim3 g(DIMD / 128, (BB * TT) / 128);
        mma_gemm<1><<<g, 256, GEMM_SMEM>>>((const __half*)p_ao16, (const __half*)p_wo16,
                                           b_out, y);
    }
}

// round 14
// speedup vs baseline: 6.4522x; 1.0318x over previous
#include <cuda_runtime.h>
#include <cuda_bf16.h>
#include <cuda_fp16.h>
#include <math.h>
#include <stdint.h>

#define BB 4
#define TT 2048
#define DIMD 1024
#define HH 16
#define DHD 64
#define NQKV 3072
#define KDIM 1024
#define GPAD 72     /* gemm smem row pad (fp16): 64 data + 8 pad, 144B stride */
#define APAD 72     /* attention smem row pad (fp16) */
#define EXP_C 0.045084439f  /* (1/32) * log2(e) */

// ---------------------------------------------------------------------------
// Device-global scratch (all fp16)
// ---------------------------------------------------------------------------
__device__ __half g_q16[BB * HH * TT * DHD];   // [b,h,t,d]
__device__ __half g_k16[BB * HH * TT * DHD];
__device__ __half g_v16[BB * HH * TT * DHD];

__device__ __half g_x16[BB * TT * DIMD];
__device__ __half g_wq16[NQKV * DIMD];
__device__ __half g_wo16[DIMD * DIMD];
__device__ __half g_ao16[BB * TT * DIMD];      // attention out, [b,t,(h d)]

// ---------------------------------------------------------------------------
// Standard-PTX helpers (compute_103-safe)
// ---------------------------------------------------------------------------
__device__ __forceinline__ uint32_t smem_u32(const void* p) {
    uint32_t a;
    asm("{ .reg .u64 t; cvta.to.shared.u64 t, %1; cvt.u32.u64 %0, t; }" : "=r"(a) : "l"(p));
    return a;
}
__device__ __forceinline__ void cp16(uint32_t dst, const void* src) {
    asm volatile("cp.async.cg.shared.global [%0], [%1], 16;" :: "r"(dst), "l"(src));
}
#define CP_COMMIT() asm volatile("cp.async.commit_group;" ::: "memory")
#define CP_WAIT0()  asm volatile("cp.async.wait_group 0;" ::: "memory")

__device__ __forceinline__ void ldm_x4(uint32_t* r, uint32_t addr) {
    asm volatile("ldmatrix.sync.aligned.m8n8.x4.shared.b16 {%0,%1,%2,%3}, [%4];"
                 : "=r"(r[0]), "=r"(r[1]), "=r"(r[2]), "=r"(r[3]) : "r"(addr));
}
__device__ __forceinline__ void ldm_x4_trans(uint32_t* r, uint32_t addr) {
    asm volatile("ldmatrix.sync.aligned.m8n8.x4.trans.shared.b16 {%0,%1,%2,%3}, [%4];"
                 : "=r"(r[0]), "=r"(r[1]), "=r"(r[2]), "=r"(r[3]) : "r"(addr));
}
__device__ __forceinline__ void mma16816h(float* d, const uint32_t* a, const uint32_t* b) {
    asm volatile(
        "mma.sync.aligned.m16n8k16.row.col.f32.f16.f16.f32 "
        "{%0,%1,%2,%3}, {%4,%5,%6,%7}, {%8,%9}, {%0,%1,%2,%3};"
        : "+f"(d[0]), "+f"(d[1]), "+f"(d[2]), "+f"(d[3])
        : "r"(a[0]), "r"(a[1]), "r"(a[2]), "r"(a[3]), "r"(b[0]), "r"(b[1]));
}
__device__ __forceinline__ uint32_t pack_f16x2(float lo, float hi) {
    uint32_t r;
    asm("cvt.rn.f16x2.f32 %0, %1, %2;" : "=r"(r) : "f"(hi), "f"(lo));
    return r;
}
__device__ __forceinline__ float fexp2(float x) {
    float r;
    asm("ex2.approx.ftz.f32 %0, %1;" : "=f"(r) : "f"(x));
    return r;
}

// ---------------------------------------------------------------------------
// fp32 -> fp16 convert pre-pass
// ---------------------------------------------------------------------------
__global__ __launch_bounds__(256) void cvt16_kernel(const float* __restrict__ s,
                                                    __half* __restrict__ d, int n4) {
    int i = blockIdx.x * blockDim.x + threadIdx.x;
    if (i >= n4) return;
    float4 v = ((const float4*)s)[i];
    uint2 p;
    p.x = pack_f16x2(v.x, v.y);
    p.y = pack_f16x2(v.z, v.w);
    ((uint2*)d)[i] = p;
}

// ---------------------------------------------------------------------------
// Single-pass fp16 HMMA GEMM, K-stage = 64, double-buffered, 1 barrier/stage.
// D[128x128] = A[128xK] * B[128xK]^T, fp32 accum.
// EPI 0: scatter to fp16 q/k/v.  EPI 1: +bias -> fp32 out.
// smem: 2 stages x 2 arrays x 128 x GPAD fp16 = 73,728 B.
// ---------------------------------------------------------------------------
#define GAS (128 * GPAD)

template <int EPI>
__global__ __launch_bounds__(256, 2) void mma_gemm(const __half* __restrict__ Ap,
                                                   const __half* __restrict__ Bp,
                                                   const float* __restrict__ bias,
                                                   float* __restrict__ out) {
    extern __shared__ __half dsm[];
    const uint32_t aD = smem_u32(dsm);

    const int tid = threadIdx.x;
    const int wid = tid >> 5;
    const int lane = tid & 31;
    const int warp_m = wid & 1;
    const int warp_n = wid >> 1;
    const int m0 = blockIdx.y * 128;
    const int n0 = blockIdx.x * 128;

    const __half* srcA = Ap + (size_t)m0 * KDIM;
    const __half* srcB = Bp + (size_t)n0 * KDIM;

    const int a_row_base = warp_m * 64 + (lane & 15);
    const int a_colsel = (lane >> 4) * 8;
    const int b_row_base = warp_n * 32 + ((lane >> 4) & 1) * 8 + (lane & 7);
    const int b_colsel = ((lane >> 3) & 1) * 8;

    float acc[4][4][4];
#pragma unroll
    for (int mi = 0; mi < 4; mi++)
#pragma unroll
        for (int ni = 0; ni < 4; ni++)
#pragma unroll
            for (int e = 0; e < 4; e++) acc[mi][ni][e] = 0.0f;

    // Stage load: 128 rows x 64 fp16 per array = 8 x 16B segs/row.
    // 1024 segs per array; 4 per thread per array.
    auto issue = [&](int s, int buf) {
        const int k0 = s * 64;
        const uint32_t sb = aD + (uint32_t)buf * (2 * GAS * 2);
#pragma unroll
        for (int i = 0; i < 4; i++) {
            int idx = tid + i * 256;       // 0..1023
            int r = idx >> 3;
            int sg = idx & 7;
            cp16(sb + (uint32_t)(r * GPAD + sg * 8) * 2,
                 srcA + (size_t)r * KDIM + k0 + sg * 8);
            cp16(sb + (uint32_t)(GAS + r * GPAD + sg * 8) * 2,
                 srcB + (size_t)r * KDIM + k0 + sg * 8);
        }
        CP_COMMIT();
    };

    issue(0, 0);

    for (int s = 0; s < 16; s++) {
        CP_WAIT0();
        __syncthreads();
        if (s + 1 < 16) issue(s + 1, (s + 1) & 1);

        const uint32_t sb = aD + (uint32_t)(s & 1) * (2 * GAS * 2);
        const uint32_t aA = sb;
        const uint32_t aB = sb + GAS * 2;

#pragma unroll
        for (int kk = 0; kk < 4; kk++) {
            const int acol = kk * 16 + a_colsel;
            const int bcol = kk * 16 + b_colsel;

            uint32_t fa[4][4];
            uint32_t fb[4][2];

#pragma unroll
            for (int mi = 0; mi < 4; mi++)
                ldm_x4(fa[mi], aA + ((a_row_base + mi * 16) * GPAD + acol) * 2);
#pragma unroll
            for (int ni2 = 0; ni2 < 2; ni2++)
                ldm_x4(&fb[ni2 * 2][0], aB + ((b_row_base + ni2 * 16) * GPAD + bcol) * 2);

#pragma unroll
            for (int mi = 0; mi < 4; mi++)
#pragma unroll
                for (int ni = 0; ni < 4; ni++) mma16816h(acc[mi][ni], fa[mi], fb[ni]);
        }
    }

    const int r0 = lane >> 2;
    const int c0 = (lane & 3) * 2;
#pragma unroll
    for (int mi = 0; mi < 4; mi++) {
#pragma unroll
        for (int half = 0; half < 2; half++) {
            const int m = m0 + warp_m * 64 + mi * 16 + r0 + half * 8;
            if (EPI == 0) {
                const int b = m >> 11;
                const int t = m & (TT - 1);
                const size_t mbase = ((size_t)b * HH) * TT;
#pragma unroll
                for (int ni = 0; ni < 4; ni++) {
#pragma unroll
                    for (int e = 0; e < 2; e++) {
                        int o = n0 + warp_n * 32 + ni * 8 + c0 + e;
                        float v = acc[mi][ni][half * 2 + e];
                        int d = o / 48;
                        int rem = o - d * 48;
                        int kq = rem >> 4;
                        int h = rem & 15;
                        __half* dst = (kq == 0) ? g_q16 : (kq == 1) ? g_k16 : g_v16;
                        size_t idx = ((mbase + (size_t)h * TT) + t) * DHD + d;
                        dst[idx] = __float2half(v);
                    }
                }
            } else {
#pragma unroll
                for (int ni = 0; ni < 4; ni++) {
#pragma unroll
                    for (int e = 0; e < 2; e++) {
                        int o = n0 + warp_n * 32 + ni * 8 + c0 + e;
                        out[(size_t)m * DIMD + o] = acc[mi][ni][half * 2 + e] + bias[o];
                    }
                }
            }
        }
    }
}

// ---------------------------------------------------------------------------
// fp16 single-pass HMMA flash attention (at MMA ceiling — unchanged from R10)
// ---------------------------------------------------------------------------
#define ARR (64 * APAD)
#define ATTN_ELEMS (4 * ARR)

__global__ __launch_bounds__(256, 2) void attn_mma_kernel() {
    extern __shared__ __half hsm[];
    const uint32_t aD = smem_u32(hsm);

    const int tid = threadIdx.x;
    const int w = tid >> 5;
    const int lane = tid & 31;
    const int bh = blockIdx.x >> 4;
    const int rb = blockIdx.x & 15;
    const int b = bh >> 4;
    const int h = bh & 15;
    const int row0 = rb * 128;

    const __half* Qp = g_q16 + (size_t)bh * TT * DHD;
    const __half* Kp = g_k16 + (size_t)bh * TT * DHD;
    const __half* Vp = g_v16 + (size_t)bh * TT * DHD;

#pragma unroll
    for (int i = 0; i < 4; i++) {
        int idx = tid + i * 256;
        int r = idx >> 3;
        int sg = idx & 7;
        *(uint4*)&hsm[r * APAD + sg * 8] =
            *(const uint4*)(Qp + (size_t)(row0 + r) * DHD + sg * 8);
    }
    __syncthreads();

    const uint32_t qrow = w * 16 + (lane & 15);
    const uint32_t qcol = (lane >> 4) * 8;
    uint32_t qf[4][4];
#pragma unroll
    for (int ks = 0; ks < 4; ks++)
        ldm_x4(qf[ks], aD + (qrow * APAD + ks * 16 + qcol) * 2);
    __syncthreads();

    const int ld_row = tid >> 2;
    const int ld_seg = tid & 3;

    auto issue = [&](int kt, int s) {
        const size_t goff = (size_t)kt * 64 * DHD;
        const uint32_t sb = aD + (uint32_t)s * (2 * ARR * 2);
        const __half* srcs[2] = {Kp + goff, Vp + goff};
#pragma unroll
        for (int a = 0; a < 2; a++) {
#pragma unroll
            for (int i = 0; i < 2; i++) {
                int sg = ld_seg + i * 4;
                cp16(sb + (uint32_t)(a * ARR + ld_row * APAD + sg * 8) * 2,
                     srcs[a] + (size_t)ld_row * DHD + sg * 8);
            }
        }
        CP_COMMIT();
    };

    float accO[8][4];
#pragma unroll
    for (int nt = 0; nt < 8; nt++)
#pragma unroll
        for (int e = 0; e < 4; e++) accO[nt][e] = 0.0f;

    float M0 = -1e30f, M1 = -1e30f;
    float L0 = 0.0f, L1 = 0.0f;

    issue(0, 0);

    const uint32_t k_rowl = ((lane >> 4) & 1) * 8 + (lane & 7);
    const uint32_t k_coll = ((lane >> 3) & 1) * 8;
    const uint32_t v_rowl = ((lane >> 3) & 1) * 8 + (lane & 7);
    const uint32_t v_coll = ((lane >> 4) & 1) * 8;

    for (int kt = 0; kt < TT / 64; kt++) {
        CP_WAIT0();
        __syncthreads();
        if (kt + 1 < TT / 64) issue(kt + 1, (kt + 1) & 1);

        const uint32_t sb = aD + (uint32_t)(kt & 1) * (2 * ARR * 2);
        const uint32_t aK = sb;
        const uint32_t aV = sb + ARR * 2;

        float accS[8][4];
#pragma unroll
        for (int nt = 0; nt < 8; nt++)
#pragma unroll
            for (int e = 0; e < 4; e++) accS[nt][e] = 0.0f;

#pragma unroll
        for (int ks = 0; ks < 4; ks++) {
#pragma unroll
            for (int np = 0; np < 2; np++) {
                uint32_t kfa[4], kfb[4];
                const uint32_t offA = (((2 * np) * 16 + k_rowl) * APAD + ks * 16 + k_coll) * 2;
                const uint32_t offB = (((2 * np + 1) * 16 + k_rowl) * APAD + ks * 16 + k_coll) * 2;
                ldm_x4(kfa, aK + offA);
                ldm_x4(kfb, aK + offB);
                mma16816h(accS[4 * np + 0], qf[ks], &kfa[0]);
                mma16816h(accS[4 * np + 1], qf[ks], &kfa[2]);
                mma16816h(accS[4 * np + 2], qf[ks], &kfb[0]);
                mma16816h(accS[4 * np + 3], qf[ks], &kfb[2]);
            }
        }

        float vm0 = accS[0][0], vm1 = accS[0][2];
#pragma unroll
        for (int nt = 0; nt < 8; nt++) {
            vm0 = fmaxf(vm0, fmaxf(accS[nt][0], accS[nt][1]));
            vm1 = fmaxf(vm1, fmaxf(accS[nt][2], accS[nt][3]));
        }
        vm0 = fmaxf(vm0, __shfl_xor_sync(0xffffffffu, vm0, 1));
        vm0 = fmaxf(vm0, __shfl_xor_sync(0xffffffffu, vm0, 2));
        vm1 = fmaxf(vm1, __shfl_xor_sync(0xffffffffu, vm1, 1));
        vm1 = fmaxf(vm1, __shfl_xor_sync(0xffffffffu, vm1, 2));

        const float Mn0 = fmaxf(M0, vm0);
        const float Mn1 = fmaxf(M1, vm1);
        const float corr0 = fexp2((M0 - Mn0) * EXP_C);
        const float corr1 = fexp2((M1 - Mn1) * EXP_C);
        M0 = Mn0; M1 = Mn1;
        const float mc0 = M0 * EXP_C;
        const float mc1 = M1 * EXP_C;

        float sp0 = 0.0f, sp1 = 0.0f;
#pragma unroll
        for (int nt = 0; nt < 8; nt++) {
            accS[nt][0] = fexp2(fmaf(accS[nt][0], EXP_C, -mc0));
            accS[nt][1] = fexp2(fmaf(accS[nt][1], EXP_C, -mc0));
            accS[nt][2] = fexp2(fmaf(accS[nt][2], EXP_C, -mc1));
            accS[nt][3] = fexp2(fmaf(accS[nt][3], EXP_C, -mc1));
            sp0 += accS[nt][0] + accS[nt][1];
            sp1 += accS[nt][2] + accS[nt][3];
        }
        sp0 += __shfl_xor_sync(0xffffffffu, sp0, 1);
        sp0 += __shfl_xor_sync(0xffffffffu, sp0, 2);
        sp1 += __shfl_xor_sync(0xffffffffu, sp1, 1);
        sp1 += __shfl_xor_sync(0xffffffffu, sp1, 2);
        L0 = L0 * corr0 + sp0;
        L1 = L1 * corr1 + sp1;

#pragma unroll
        for (int nt = 0; nt < 8; nt++) {
            accO[nt][0] *= corr0; accO[nt][1] *= corr0;
            accO[nt][2] *= corr1; accO[nt][3] *= corr1;
        }

#pragma unroll
        for (int kc = 0; kc < 4; kc++) {
            uint32_t ph[4];
#pragma unroll
            for (int half = 0; half < 2; half++) {
                const int nt = 2 * kc + half;
                ph[half * 2 + 0] = pack_f16x2(accS[nt][0], accS[nt][1]);
                ph[half * 2 + 1] = pack_f16x2(accS[nt][2], accS[nt][3]);
            }
            const uint32_t vrow = kc * 16 + v_rowl;
#pragma unroll
            for (int np = 0; np < 2; np++) {
                uint32_t vfa[4], vfb[4];
                const uint32_t offA = (vrow * APAD + (2 * np) * 16 + v_coll) * 2;
                const uint32_t offB = (vrow * APAD + (2 * np + 1) * 16 + v_coll) * 2;
                ldm_x4_trans(vfa, aV + offA);
                ldm_x4_trans(vfb, aV + offB);
                mma16816h(accO[4 * np + 0], ph, &vfa[0]);
                mma16816h(accO[4 * np + 1], ph, &vfa[2]);
                mma16816h(accO[4 * np + 2], ph, &vfb[0]);
                mma16816h(accO[4 * np + 3], ph, &vfb[2]);
            }
        }
    }

    const float i0 = 1.0f / L0;
    const float i1 = 1.0f / L1;
    const int r = lane >> 2;
    const int c = (lane & 3) * 2;
    const int row = row0 + w * 16 + r;
    const size_t base0 = ((size_t)b * TT + row) * DIMD + h * DHD + c;
    const size_t base1 = base0 + 8 * DIMD;
#pragma unroll
    for (int nt = 0; nt < 8; nt++) {
        *(uint32_t*)(g_ao16 + base0 + nt * 8) =
            pack_f16x2(accO[nt][0] * i0, accO[nt][1] * i0);
        *(uint32_t*)(g_ao16 + base1 + nt * 8) =
            pack_f16x2(accO[nt][2] * i1, accO[nt][3] * i1);
    }
}

// ---------------------------------------------------------------------------
extern "C" void kernel_launch(void* const* d_in, const int* in_sizes, int n_in,
                              void* d_out, int out_size) {
    const float* x     = (const float*)d_in[0];
    const float* w_qkv = (const float*)d_in[1];
    const float* w_out = (const float*)d_in[2];
    const float* b_out = (const float*)d_in[3];
    float* y = (float*)d_out;

    void *p_x16, *p_wq16, *p_wo16, *p_ao16;
    cudaGetSymbolAddress(&p_x16, g_x16);
    cudaGetSymbolAddress(&p_wq16, g_wq16);
    cudaGetSymbolAddress(&p_wo16, g_wo16);
    cudaGetSymbolAddress(&p_ao16, g_ao16);

    const int GEMM_SMEM = 2 * 2 * GAS * 2;     // 73,728 B
    const int ATTN_SMEM = ATTN_ELEMS * 2;      // 36,864 B
    cudaFuncSetAttribute(mma_gemm<0>, cudaFuncAttributeMaxDynamicSharedMemorySize, GEMM_SMEM);
    cudaFuncSetAttribute(mma_gemm<1>, cudaFuncAttributeMaxDynamicSharedMemorySize, GEMM_SMEM);
    cudaFuncSetAttribute(attn_mma_kernel, cudaFuncAttributeMaxDynamicSharedMemorySize, ATTN_SMEM);

    {
        int n4 = (BB * TT * DIMD) / 4;
        cvt16_kernel<<<(n4 + 255) / 256, 256>>>(x, (__half*)p_x16, n4);
    }
    {
        int n4 = (NQKV * DIMD) / 4;
        cvt16_kernel<<<(n4 + 255) / 256, 256>>>(w_qkv, (__half*)p_wq16, n4);
    }
    {
        int n4 = (DIMD * DIMD) / 4;
        cvt16_kernel<<<(n4 + 255) / 256, 256>>>(w_out, (__half*)p_wo16, n4);
    }

    // QKV projection: M=8192, N=3072
    {
        dim3 g(NQKV / 128, (BB * TT) / 128);
        mma_gemm<0><<<g, 256, GEMM_SMEM>>>((const __half*)p_x16, (const __half*)p_wq16,
                                           nullptr, nullptr);
    }

    attn_mma_kernel<<<BB * HH * (TT / 128), 256, ATTN_SMEM>>>();

    // Output projection: M=8192, N=1024 (+bias)
    {
        dim3 g(DIMD / 128, (BB * TT) / 128);
        mma_gemm<1><<<g, 256, GEMM_SMEM>>>((const __half*)p_ao16, (const __half*)p_wo16,
                                           b_out, y);
    }
}